// round 1
// baseline (speedup 1.0000x reference)
#include <cuda_runtime.h>
#include <math.h>

// Problem constants
constexpr int B_   = 4;
constexpr int T_   = 2048;
constexpr int E_   = 2048;
constexpr int NH_  = 16;
constexpr int NKV_ = 4;
constexpr int HD_  = 128;
constexpr int KVD_ = NKV_ * HD_;   // 512
constexpr float SCALE_ = 11.313708498984761f;  // sqrt(128)

// Scratch (device globals: allowed; no runtime allocation)
__device__ float g_q[(size_t)B_ * T_ * E_];     // (B, NH, T, HD) view == (B,T,E) flat
__device__ float g_k[(size_t)B_ * T_ * KVD_];   // (B, NKV, T, HD) view
__device__ float g_v[(size_t)B_ * T_ * KVD_];
__device__ float g_att[(size_t)B_ * T_ * E_];   // attention output, (b,t,h,d)

// ---------------------------------------------------------------------------
// FP32 SGEMM: C[M,N] = A[M,K] @ W[K,N] + bias[N]
// 128x128 block tile, BK=16, 256 threads, 8x8 per-thread tile, reg prefetch.
// ---------------------------------------------------------------------------
__global__ void __launch_bounds__(256, 2)
sgemm_bias(const float* __restrict__ A, const float* __restrict__ W,
           const float* __restrict__ bias, float* __restrict__ C,
           int M, int N, int K)
{
    __shared__ float As[16][128];   // transposed A tile: As[k][m]
    __shared__ float Bs[16][128];   // natural W tile:    Bs[k][n]

    const int tid = threadIdx.x;
    const int tx = tid & 15, ty = tid >> 4;
    const int bm = blockIdx.y << 7, bn = blockIdx.x << 7;

    // loader indices
    const int am  = tid >> 2;           // 0..63 (and +64)
    const int ak  = (tid & 3) << 2;     // 0,4,8,12
    const int bk  = tid >> 5;           // 0..7 (and +8)
    const int bn4 = (tid & 31) << 2;    // 0..124

    const float* Aptr0 = A + (size_t)(bm + am) * K + ak;
    const float* Aptr1 = A + (size_t)(bm + am + 64) * K + ak;
    const float* Wptr0 = W + (size_t)bk * N + bn + bn4;
    const float* Wptr1 = W + (size_t)(bk + 8) * N + bn + bn4;

    float4 a0 = *(const float4*)Aptr0;
    float4 a1 = *(const float4*)Aptr1;
    float4 b0 = *(const float4*)Wptr0;
    float4 b1 = *(const float4*)Wptr1;

    float acc[8][8];
    #pragma unroll
    for (int i = 0; i < 8; i++)
        #pragma unroll
        for (int j = 0; j < 8; j++) acc[i][j] = 0.f;

    for (int kt = 0; kt < K; kt += 16) {
        As[ak + 0][am] = a0.x; As[ak + 1][am] = a0.y;
        As[ak + 2][am] = a0.z; As[ak + 3][am] = a0.w;
        As[ak + 0][am + 64] = a1.x; As[ak + 1][am + 64] = a1.y;
        As[ak + 2][am + 64] = a1.z; As[ak + 3][am + 64] = a1.w;
        *(float4*)&Bs[bk][bn4]     = b0;
        *(float4*)&Bs[bk + 8][bn4] = b1;
        __syncthreads();

        if (kt + 16 < K) {  // prefetch next tile into registers
            a0 = *(const float4*)(Aptr0 + kt + 16);
            a1 = *(const float4*)(Aptr1 + kt + 16);
            b0 = *(const float4*)(Wptr0 + (size_t)(kt + 16) * N);
            b1 = *(const float4*)(Wptr1 + (size_t)(kt + 16) * N);
        }

        #pragma unroll
        for (int k = 0; k < 16; k++) {
            float af[8], bf[8];
            *(float4*)&af[0] = *(float4*)&As[k][ty * 8];
            *(float4*)&af[4] = *(float4*)&As[k][ty * 8 + 4];
            *(float4*)&bf[0] = *(float4*)&Bs[k][tx * 8];
            *(float4*)&bf[4] = *(float4*)&Bs[k][tx * 8 + 4];
            #pragma unroll
            for (int i = 0; i < 8; i++)
                #pragma unroll
                for (int j = 0; j < 8; j++)
                    acc[i][j] += af[i] * bf[j];
        }
        __syncthreads();
    }

    float bv[8];
    *(float4*)&bv[0] = *(const float4*)(bias + bn + tx * 8);
    *(float4*)&bv[4] = *(const float4*)(bias + bn + tx * 8 + 4);
    #pragma unroll
    for (int i = 0; i < 8; i++) {
        float* cp = C + (size_t)(bm + ty * 8 + i) * N + bn + tx * 8;
        float4 o0, o1;
        o0.x = acc[i][0] + bv[0]; o0.y = acc[i][1] + bv[1];
        o0.z = acc[i][2] + bv[2]; o0.w = acc[i][3] + bv[3];
        o1.x = acc[i][4] + bv[4]; o1.y = acc[i][5] + bv[5];
        o1.z = acc[i][6] + bv[6]; o1.w = acc[i][7] + bv[7];
        *(float4*)cp       = o0;
        *(float4*)(cp + 4) = o1;
    }
}

// ---------------------------------------------------------------------------
// RoPE in place on k and v, interpreted as (B*NKV*T) rows of HD.
// Position = row % T (the reshaped-view t axis, matching the reference).
// angle quantized to fp32 like the reference; sin/cos in double for accuracy.
// ---------------------------------------------------------------------------
__global__ void rope_kernel(float* __restrict__ k, float* __restrict__ v)
{
    int p  = blockIdx.x * 256 + threadIdx.x;     // pair index
    int d2 = p & 63;
    int rr = p >> 6;
    int t  = rr & (T_ - 1);

    double th = pow(10000.0, -(double)(2 * d2) / 128.0);
    float angf = (float)t * (float)th;           // fp32 quantization (matches ref)
    double ang = (double)angf;
    float c = (float)cos(ang);
    float s = (float)sin(ang);

    size_t base = (size_t)rr * HD_ + 2 * d2;
    float2 kk = *(float2*)(k + base);
    float2 vv = *(float2*)(v + base);
    float2 ko, vo;
    ko.x = kk.x * c - kk.y * s;  ko.y = kk.x * s + kk.y * c;
    vo.x = vv.x * c - vv.y * s;  vo.y = vv.x * s + vv.y * c;
    *(float2*)(k + base) = ko;
    *(float2*)(v + base) = vo;
}

// ---------------------------------------------------------------------------
// FP32 flash attention. 64 queries x 64 keys per tile, HD=128.
// 256 threads as 16x16; each thread: 4 S-rows x 4 S-cols, 4 O-rows x 8 O-cols.
// Masked scores -> exactly 1e-9 (participates in the row max), scale=sqrt(HD).
// ---------------------------------------------------------------------------
constexpr int HP_ = 132;  // padded HD row stride in smem (16B aligned)

__global__ void __launch_bounds__(256)
flash_attn(const float* __restrict__ Q, const float* __restrict__ Kb,
           const float* __restrict__ Vb, const int* __restrict__ mask,
           float* __restrict__ O)
{
    extern __shared__ float sm[];
    float* Qs = sm;                  // [64][HP_]
    float* Ks = Qs + 64 * HP_;       // [64][HP_]
    float* Vs = Ks + 64 * HP_;       // [64][HD_]
    float* Ps = Vs + 64 * HD_;       // [64][64]

    const int tid = threadIdx.x;
    const int tx = tid & 15, ty = tid >> 4;
    const int q0 = blockIdx.x << 6;
    const int h  = blockIdx.y;
    const int b  = blockIdx.z;
    const int kh = h & (NKV_ - 1);   // jnp.tile => h % NKV

    const float* qb = Q  + ((size_t)b * NH_  + h ) * ((size_t)T_ * HD_);
    const float* kb = Kb + ((size_t)b * NKV_ + kh) * ((size_t)T_ * HD_);
    const float* vb = Vb + ((size_t)b * NKV_ + kh) * ((size_t)T_ * HD_);
    const int*   mb = mask + (size_t)b * T_ * T_;

    // Load Q tile (rows contiguous in gmem thanks to the reshape view)
    #pragma unroll
    for (int i = 0; i < 8; i++) {
        int f = i * 256 + tid;
        int r = f >> 5, dv = (f & 31) << 2;
        *(float4*)&Qs[r * HP_ + dv] = *(const float4*)(qb + (size_t)(q0 + r) * HD_ + dv);
    }

    float m_[4], l_[4], acc[4][8];
    #pragma unroll
    for (int i = 0; i < 4; i++) {
        m_[i] = -INFINITY; l_[i] = 0.f;
        #pragma unroll
        for (int c = 0; c < 8; c++) acc[i][c] = 0.f;
    }

    for (int k0 = 0; k0 < T_; k0 += 64) {
        __syncthreads();   // protect K/V/P reuse (and publish Qs on first iter)
        #pragma unroll
        for (int i = 0; i < 8; i++) {
            int f = i * 256 + tid;
            int r = f >> 5, dv = (f & 31) << 2;
            *(float4*)&Ks[r * HP_ + dv] = *(const float4*)(kb + (size_t)(k0 + r) * HD_ + dv);
            *(float4*)&Vs[r * HD_ + dv] = *(const float4*)(vb + (size_t)(k0 + r) * HD_ + dv);
        }
        __syncthreads();

        // S = Q K^T (64x64 distributed as 4x4 per thread)
        float s[4][4];
        #pragma unroll
        for (int i = 0; i < 4; i++)
            #pragma unroll
            for (int j = 0; j < 4; j++) s[i][j] = 0.f;

        #pragma unroll 4
        for (int d = 0; d < HD_; d += 4) {
            float4 qf[4], kf[4];
            #pragma unroll
            for (int i = 0; i < 4; i++) qf[i] = *(float4*)&Qs[(ty * 4 + i) * HP_ + d];
            #pragma unroll
            for (int j = 0; j < 4; j++) kf[j] = *(float4*)&Ks[(tx * 4 + j) * HP_ + d];
            #pragma unroll
            for (int i = 0; i < 4; i++)
                #pragma unroll
                for (int j = 0; j < 4; j++)
                    s[i][j] += qf[i].x * kf[j].x + qf[i].y * kf[j].y
                             + qf[i].z * kf[j].z + qf[i].w * kf[j].w;
        }

        // mask + scale + online softmax update
        #pragma unroll
        for (int i = 0; i < 4; i++) {
            const int row = q0 + ty * 4 + i;
            int4 mv = *(const int4*)(mb + (size_t)row * T_ + k0 + tx * 4);
            s[i][0] = mv.x ? s[i][0] * SCALE_ : 1e-9f;
            s[i][1] = mv.y ? s[i][1] * SCALE_ : 1e-9f;
            s[i][2] = mv.z ? s[i][2] * SCALE_ : 1e-9f;
            s[i][3] = mv.w ? s[i][3] * SCALE_ : 1e-9f;

            float rowm = fmaxf(fmaxf(s[i][0], s[i][1]), fmaxf(s[i][2], s[i][3]));
            rowm = fmaxf(rowm, __shfl_xor_sync(0xffffffffu, rowm, 1));
            rowm = fmaxf(rowm, __shfl_xor_sync(0xffffffffu, rowm, 2));
            rowm = fmaxf(rowm, __shfl_xor_sync(0xffffffffu, rowm, 4));
            rowm = fmaxf(rowm, __shfl_xor_sync(0xffffffffu, rowm, 8));

            float mnew  = fmaxf(m_[i], rowm);
            float alpha = expf(m_[i] - mnew);
            float rs = 0.f;
            #pragma unroll
            for (int j = 0; j < 4; j++) { s[i][j] = expf(s[i][j] - mnew); rs += s[i][j]; }
            rs += __shfl_xor_sync(0xffffffffu, rs, 1);
            rs += __shfl_xor_sync(0xffffffffu, rs, 2);
            rs += __shfl_xor_sync(0xffffffffu, rs, 4);
            rs += __shfl_xor_sync(0xffffffffu, rs, 8);

            l_[i] = l_[i] * alpha + rs;
            m_[i] = mnew;
            #pragma unroll
            for (int c = 0; c < 8; c++) acc[i][c] *= alpha;

            *(float4*)&Ps[(ty * 4 + i) * 64 + tx * 4] =
                make_float4(s[i][0], s[i][1], s[i][2], s[i][3]);
        }
        __syncthreads();

        // O += P V   (4 rows x 8 cols per thread)
        #pragma unroll 4
        for (int j0 = 0; j0 < 64; j0 += 4) {
            float4 pf[4];
            #pragma unroll
            for (int i = 0; i < 4; i++) pf[i] = *(float4*)&Ps[(ty * 4 + i) * 64 + j0];
            #pragma unroll
            for (int jj = 0; jj < 4; jj++) {
                float4 v0 = *(float4*)&Vs[(j0 + jj) * HD_ + tx * 8];
                float4 v1 = *(float4*)&Vs[(j0 + jj) * HD_ + tx * 8 + 4];
                #pragma unroll
                for (int i = 0; i < 4; i++) {
                    float pv = (jj == 0) ? pf[i].x : (jj == 1) ? pf[i].y
                             : (jj == 2) ? pf[i].z : pf[i].w;
                    acc[i][0] += pv * v0.x; acc[i][1] += pv * v0.y;
                    acc[i][2] += pv * v0.z; acc[i][3] += pv * v0.w;
                    acc[i][4] += pv * v1.x; acc[i][5] += pv * v1.y;
                    acc[i][6] += pv * v1.z; acc[i][7] += pv * v1.w;
                }
            }
        }
    }

    // Normalize and write out in (b, t, h, d) layout (the post-transpose layout)
    #pragma unroll
    for (int i = 0; i < 4; i++) {
        float inv = 1.f / l_[i];
        float* op = O + ((size_t)b * T_ + q0 + ty * 4 + i) * E_ + h * HD_ + tx * 8;
        float4 o0 = make_float4(acc[i][0] * inv, acc[i][1] * inv,
                                acc[i][2] * inv, acc[i][3] * inv);
        float4 o1 = make_float4(acc[i][4] * inv, acc[i][5] * inv,
                                acc[i][6] * inv, acc[i][7] * inv);
        *(float4*)op       = o0;
        *(float4*)(op + 4) = o1;
    }
}

// ---------------------------------------------------------------------------
extern "C" void kernel_launch(void* const* d_in, const int* in_sizes, int n_in,
                              void* d_out, int out_size)
{
    const float* x  = (const float*)d_in[0];
    const int*   am = (const int*)  d_in[1];
    const float* Wq = (const float*)d_in[2];
    const float* bq = (const float*)d_in[3];
    const float* Wk = (const float*)d_in[4];
    const float* bk = (const float*)d_in[5];
    const float* Wv = (const float*)d_in[6];
    const float* bv = (const float*)d_in[7];
    const float* Wo = (const float*)d_in[8];
    const float* bo = (const float*)d_in[9];
    float* out = (float*)d_out;

    float *q, *k, *v, *att;
    cudaGetSymbolAddress((void**)&q,   g_q);
    cudaGetSymbolAddress((void**)&k,   g_k);
    cudaGetSymbolAddress((void**)&v,   g_v);
    cudaGetSymbolAddress((void**)&att, g_att);

    const int M = B_ * T_;  // 8192

    // Projections
    sgemm_bias<<<dim3(E_ / 128,   M / 128), 256>>>(x, Wq, bq, q, M, E_,   E_);
    sgemm_bias<<<dim3(KVD_ / 128, M / 128), 256>>>(x, Wk, bk, k, M, KVD_, E_);
    sgemm_bias<<<dim3(KVD_ / 128, M / 128), 256>>>(x, Wv, bv, v, M, KVD_, E_);

    // RoPE on k and v (positions are the reshaped-view t axis)
    rope_kernel<<<(B_ * NKV_ * T_ * 64) / 256, 256>>>(k, v);

    // Attention
    const int asmem = 116736;  // (2*64*132 + 64*128 + 64*64) * 4 bytes
    cudaFuncSetAttribute(flash_attn, cudaFuncAttributeMaxDynamicSharedMemorySize, asmem);
    flash_attn<<<dim3(T_ / 64, NH_, B_), 256, asmem>>>(q, k, v, am, att);

    // Output projection
    sgemm_bias<<<dim3(E_ / 128, M / 128), 256>>>(att, Wo, bo, out, M, E_, E_);
}

// round 2
// speedup vs baseline: 1.1974x; 1.1974x over previous
#include <cuda_runtime.h>
#include <math.h>
#include <stdint.h>

// Problem constants
constexpr int B_   = 4;
constexpr int T_   = 2048;
constexpr int E_   = 2048;
constexpr int NH_  = 16;
constexpr int NKV_ = 4;
constexpr int HD_  = 128;
constexpr int KVD_ = NKV_ * HD_;   // 512
constexpr float SCALE_ = 11.313708498984761f;  // sqrt(128)

// Scratch (device globals: allowed; no runtime allocation)
__device__ float g_q[(size_t)B_ * T_ * E_];     // (B, NH, T, HD) view == (B,T,E) flat
__device__ float g_k[(size_t)B_ * T_ * KVD_];   // (B, NKV, T, HD) view
__device__ float g_v[(size_t)B_ * T_ * KVD_];
__device__ float g_att[(size_t)B_ * T_ * E_];   // attention output, (b,t,h,d)

// ---------------------------------------------------------------------------
// TF32 helpers
// ---------------------------------------------------------------------------
__device__ __forceinline__ uint32_t f2tf(float f) {
    uint32_t u;
    asm("cvt.rna.tf32.f32 %0, %1;" : "=r"(u) : "f"(f));
    return u;
}
__device__ __forceinline__ void split_tf(float f, uint32_t& hi, uint32_t& lo) {
    hi = f2tf(f);
    float r = f - __uint_as_float(hi);
    lo = f2tf(r);
}
__device__ __forceinline__ void mma_16n8k8(float c[4], const uint32_t a[4],
                                           const uint32_t b[2]) {
    asm volatile(
        "mma.sync.aligned.m16n8k8.row.col.f32.tf32.tf32.f32 "
        "{%0,%1,%2,%3}, {%4,%5,%6,%7}, {%8,%9}, {%0,%1,%2,%3};"
        : "+f"(c[0]), "+f"(c[1]), "+f"(c[2]), "+f"(c[3])
        : "r"(a[0]), "r"(a[1]), "r"(a[2]), "r"(a[3]), "r"(b[0]), "r"(b[1]));
}

// ---------------------------------------------------------------------------
// Tensor-core GEMM: C[M,N] = A[M,K] @ W[K,N] + bias[N]
// 128x128 tile, BK=32, 8 warps (2x4), warp tile 64x32, m16n8k8 tf32.
// SPLIT=true -> 3xTF32 (near-fp32 accuracy) for the Q/K score path.
// ---------------------------------------------------------------------------
template<bool SPLIT>
__global__ void __launch_bounds__(256, 1)
gemm_tf32(const float* __restrict__ A, const float* __restrict__ W,
          const float* __restrict__ bias, float* __restrict__ C,
          int M, int N, int K)
{
    constexpr int ASd = 36;    // As row stride (floats): banks 4*gid+tig distinct
    constexpr int BSd = 136;   // Bs row stride: banks 8*tig+gid distinct
    __shared__ float As[128 * ASd];
    __shared__ float Bs[32 * BSd];

    const int tid  = threadIdx.x;
    const int lane = tid & 31;
    const int warp = tid >> 5;
    const int wm = (warp >> 2) * 64;   // 0 / 64
    const int wn = (warp & 3) * 32;    // 0..96
    const int gid = lane >> 2, tig = lane & 3;
    const int bm = blockIdx.y * 128, bn = blockIdx.x * 128;

    // gmem loaders
    const int la_m = tid >> 1;            // 0..127
    const int la_k = (tid & 1) * 16;      // 0 / 16
    const int lb_k = warp;                // 0..7
    const int lb_n = lane * 4;            // 0..124

    const float* Ap = A + (size_t)(bm + la_m) * K + la_k;
    const float* Bp = W + (size_t)lb_k * N + (bn + lb_n);

    float4 ar[4], br[4];
    #pragma unroll
    for (int j = 0; j < 4; j++) ar[j] = *(const float4*)(Ap + 4 * j);
    #pragma unroll
    for (int j = 0; j < 4; j++) br[j] = *(const float4*)(Bp + (size_t)(8 * j) * N);

    float acc[4][4][4];
    #pragma unroll
    for (int i = 0; i < 4; i++)
        #pragma unroll
        for (int j = 0; j < 4; j++)
            #pragma unroll
            for (int c = 0; c < 4; c++) acc[i][j][c] = 0.f;

    for (int kt = 0; kt < K; kt += 32) {
        #pragma unroll
        for (int j = 0; j < 4; j++)
            *(float4*)&As[la_m * ASd + la_k + 4 * j] = ar[j];
        #pragma unroll
        for (int j = 0; j < 4; j++)
            *(float4*)&Bs[(lb_k + 8 * j) * BSd + lb_n] = br[j];
        __syncthreads();

        if (kt + 32 < K) {  // register prefetch of next k-tile
            #pragma unroll
            for (int j = 0; j < 4; j++)
                ar[j] = *(const float4*)(Ap + kt + 32 + 4 * j);
            #pragma unroll
            for (int j = 0; j < 4; j++)
                br[j] = *(const float4*)(Bp + (size_t)(kt + 32 + 8 * j) * N);
        }

        #pragma unroll
        for (int s = 0; s < 4; s++) {
            const int ks = s * 8;
            uint32_t ah[4][4], al[4][4];
            #pragma unroll
            for (int i = 0; i < 4; i++) {
                const int rb = wm + i * 16;
                float f0 = As[(rb + gid)     * ASd + ks + tig];
                float f1 = As[(rb + gid + 8) * ASd + ks + tig];
                float f2 = As[(rb + gid)     * ASd + ks + tig + 4];
                float f3 = As[(rb + gid + 8) * ASd + ks + tig + 4];
                if (SPLIT) {
                    split_tf(f0, ah[i][0], al[i][0]);
                    split_tf(f1, ah[i][1], al[i][1]);
                    split_tf(f2, ah[i][2], al[i][2]);
                    split_tf(f3, ah[i][3], al[i][3]);
                } else {
                    ah[i][0] = f2tf(f0); ah[i][1] = f2tf(f1);
                    ah[i][2] = f2tf(f2); ah[i][3] = f2tf(f3);
                }
            }
            #pragma unroll
            for (int j = 0; j < 4; j++) {
                const int cb = wn + j * 8;
                float g0 = Bs[(ks + tig)     * BSd + cb + gid];
                float g1 = Bs[(ks + tig + 4) * BSd + cb + gid];
                uint32_t bh[2], bl[2];
                if (SPLIT) {
                    split_tf(g0, bh[0], bl[0]);
                    split_tf(g1, bh[1], bl[1]);
                } else {
                    bh[0] = f2tf(g0); bh[1] = f2tf(g1);
                }
                #pragma unroll
                for (int i = 0; i < 4; i++) {
                    mma_16n8k8(acc[i][j], ah[i], bh);
                    if (SPLIT) {
                        mma_16n8k8(acc[i][j], ah[i], bl);
                        mma_16n8k8(acc[i][j], al[i], bh);
                    }
                }
            }
        }
        __syncthreads();
    }

    // Epilogue: bias + store
    #pragma unroll
    for (int j = 0; j < 4; j++) {
        const int col = bn + wn + j * 8 + tig * 2;
        const float b0 = bias[col], b1 = bias[col + 1];
        #pragma unroll
        for (int i = 0; i < 4; i++) {
            const int row = bm + wm + i * 16 + gid;
            float2 v0 = make_float2(acc[i][j][0] + b0, acc[i][j][1] + b1);
            float2 v1 = make_float2(acc[i][j][2] + b0, acc[i][j][3] + b1);
            *(float2*)&C[(size_t)row * N + col]       = v0;
            *(float2*)&C[(size_t)(row + 8) * N + col] = v1;
        }
    }
}

// ---------------------------------------------------------------------------
// RoPE in place on k and v (B*NKV*T rows of HD). Position = row % T.
// theta in double (exp2), angle quantized to fp32 (matches ref), sincosf.
// ---------------------------------------------------------------------------
__global__ void rope_kernel(float* __restrict__ k, float* __restrict__ v)
{
    int p  = blockIdx.x * 256 + threadIdx.x;     // pair index
    int d2 = p & 63;
    int rr = p >> 6;
    int t  = rr & (T_ - 1);

    // 10000^(-2*d2/128) = 2^(-d2 * log2(10000)/64)
    double th = exp2((double)d2 * -0.20762050593046014);
    float angf = (float)t * (float)th;           // fp32 quantization (matches ref)
    float s, c;
    sincosf(angf, &s, &c);

    size_t base = (size_t)rr * HD_ + 2 * d2;
    float2 kk = *(float2*)(k + base);
    float2 vv = *(float2*)(v + base);
    float2 ko, vo;
    ko.x = kk.x * c - kk.y * s;  ko.y = kk.x * s + kk.y * c;
    vo.x = vv.x * c - vv.y * s;  vo.y = vv.x * s + vv.y * c;
    *(float2*)(k + base) = ko;
    *(float2*)(v + base) = vo;
}

// ---------------------------------------------------------------------------
// FP32 flash attention (unchanged from round 1 — verified correct).
// 64x64 tiles, HD=128, 256 threads as 16x16.
// ---------------------------------------------------------------------------
constexpr int HP_ = 132;

__global__ void __launch_bounds__(256)
flash_attn(const float* __restrict__ Q, const float* __restrict__ Kb,
           const float* __restrict__ Vb, const int* __restrict__ mask,
           float* __restrict__ O)
{
    extern __shared__ float sm[];
    float* Qs = sm;                  // [64][HP_]
    float* Ks = Qs + 64 * HP_;       // [64][HP_]
    float* Vs = Ks + 64 * HP_;       // [64][HD_]
    float* Ps = Vs + 64 * HD_;       // [64][64]

    const int tid = threadIdx.x;
    const int tx = tid & 15, ty = tid >> 4;
    const int q0 = blockIdx.x << 6;
    const int h  = blockIdx.y;
    const int b  = blockIdx.z;
    const int kh = h & (NKV_ - 1);   // jnp.tile => h % NKV

    const float* qb = Q  + ((size_t)b * NH_  + h ) * ((size_t)T_ * HD_);
    const float* kb = Kb + ((size_t)b * NKV_ + kh) * ((size_t)T_ * HD_);
    const float* vb = Vb + ((size_t)b * NKV_ + kh) * ((size_t)T_ * HD_);
    const int*   mb = mask + (size_t)b * T_ * T_;

    #pragma unroll
    for (int i = 0; i < 8; i++) {
        int f = i * 256 + tid;
        int r = f >> 5, dv = (f & 31) << 2;
        *(float4*)&Qs[r * HP_ + dv] = *(const float4*)(qb + (size_t)(q0 + r) * HD_ + dv);
    }

    float m_[4], l_[4], acc[4][8];
    #pragma unroll
    for (int i = 0; i < 4; i++) {
        m_[i] = -INFINITY; l_[i] = 0.f;
        #pragma unroll
        for (int c = 0; c < 8; c++) acc[i][c] = 0.f;
    }

    for (int k0 = 0; k0 < T_; k0 += 64) {
        __syncthreads();
        #pragma unroll
        for (int i = 0; i < 8; i++) {
            int f = i * 256 + tid;
            int r = f >> 5, dv = (f & 31) << 2;
            *(float4*)&Ks[r * HP_ + dv] = *(const float4*)(kb + (size_t)(k0 + r) * HD_ + dv);
            *(float4*)&Vs[r * HD_ + dv] = *(const float4*)(vb + (size_t)(k0 + r) * HD_ + dv);
        }
        __syncthreads();

        float s[4][4];
        #pragma unroll
        for (int i = 0; i < 4; i++)
            #pragma unroll
            for (int j = 0; j < 4; j++) s[i][j] = 0.f;

        #pragma unroll 4
        for (int d = 0; d < HD_; d += 4) {
            float4 qf[4], kf[4];
            #pragma unroll
            for (int i = 0; i < 4; i++) qf[i] = *(float4*)&Qs[(ty * 4 + i) * HP_ + d];
            #pragma unroll
            for (int j = 0; j < 4; j++) kf[j] = *(float4*)&Ks[(tx * 4 + j) * HP_ + d];
            #pragma unroll
            for (int i = 0; i < 4; i++)
                #pragma unroll
                for (int j = 0; j < 4; j++)
                    s[i][j] += qf[i].x * kf[j].x + qf[i].y * kf[j].y
                             + qf[i].z * kf[j].z + qf[i].w * kf[j].w;
        }

        #pragma unroll
        for (int i = 0; i < 4; i++) {
            const int row = q0 + ty * 4 + i;
            int4 mv = *(const int4*)(mb + (size_t)row * T_ + k0 + tx * 4);
            s[i][0] = mv.x ? s[i][0] * SCALE_ : 1e-9f;
            s[i][1] = mv.y ? s[i][1] * SCALE_ : 1e-9f;
            s[i][2] = mv.z ? s[i][2] * SCALE_ : 1e-9f;
            s[i][3] = mv.w ? s[i][3] * SCALE_ : 1e-9f;

            float rowm = fmaxf(fmaxf(s[i][0], s[i][1]), fmaxf(s[i][2], s[i][3]));
            rowm = fmaxf(rowm, __shfl_xor_sync(0xffffffffu, rowm, 1));
            rowm = fmaxf(rowm, __shfl_xor_sync(0xffffffffu, rowm, 2));
            rowm = fmaxf(rowm, __shfl_xor_sync(0xffffffffu, rowm, 4));
            rowm = fmaxf(rowm, __shfl_xor_sync(0xffffffffu, rowm, 8));

            float mnew  = fmaxf(m_[i], rowm);
            float alpha = expf(m_[i] - mnew);
            float rs = 0.f;
            #pragma unroll
            for (int j = 0; j < 4; j++) { s[i][j] = expf(s[i][j] - mnew); rs += s[i][j]; }
            rs += __shfl_xor_sync(0xffffffffu, rs, 1);
            rs += __shfl_xor_sync(0xffffffffu, rs, 2);
            rs += __shfl_xor_sync(0xffffffffu, rs, 4);
            rs += __shfl_xor_sync(0xffffffffu, rs, 8);

            l_[i] = l_[i] * alpha + rs;
            m_[i] = mnew;
            #pragma unroll
            for (int c = 0; c < 8; c++) acc[i][c] *= alpha;

            *(float4*)&Ps[(ty * 4 + i) * 64 + tx * 4] =
                make_float4(s[i][0], s[i][1], s[i][2], s[i][3]);
        }
        __syncthreads();

        #pragma unroll 4
        for (int j0 = 0; j0 < 64; j0 += 4) {
            float4 pf[4];
            #pragma unroll
            for (int i = 0; i < 4; i++) pf[i] = *(float4*)&Ps[(ty * 4 + i) * 64 + j0];
            #pragma unroll
            for (int jj = 0; jj < 4; jj++) {
                float4 v0 = *(float4*)&Vs[(j0 + jj) * HD_ + tx * 8];
                float4 v1 = *(float4*)&Vs[(j0 + jj) * HD_ + tx * 8 + 4];
                #pragma unroll
                for (int i = 0; i < 4; i++) {
                    float pv = (jj == 0) ? pf[i].x : (jj == 1) ? pf[i].y
                             : (jj == 2) ? pf[i].z : pf[i].w;
                    acc[i][0] += pv * v0.x; acc[i][1] += pv * v0.y;
                    acc[i][2] += pv * v0.z; acc[i][3] += pv * v0.w;
                    acc[i][4] += pv * v1.x; acc[i][5] += pv * v1.y;
                    acc[i][6] += pv * v1.z; acc[i][7] += pv * v1.w;
                }
            }
        }
    }

    #pragma unroll
    for (int i = 0; i < 4; i++) {
        float inv = 1.f / l_[i];
        float* op = O + ((size_t)b * T_ + q0 + ty * 4 + i) * E_ + h * HD_ + tx * 8;
        float4 o0 = make_float4(acc[i][0] * inv, acc[i][1] * inv,
                                acc[i][2] * inv, acc[i][3] * inv);
        float4 o1 = make_float4(acc[i][4] * inv, acc[i][5] * inv,
                                acc[i][6] * inv, acc[i][7] * inv);
        *(float4*)op       = o0;
        *(float4*)(op + 4) = o1;
    }
}

// ---------------------------------------------------------------------------
extern "C" void kernel_launch(void* const* d_in, const int* in_sizes, int n_in,
                              void* d_out, int out_size)
{
    const float* x  = (const float*)d_in[0];
    const int*   am = (const int*)  d_in[1];
    const float* Wq = (const float*)d_in[2];
    const float* bq = (const float*)d_in[3];
    const float* Wk = (const float*)d_in[4];
    const float* bk = (const float*)d_in[5];
    const float* Wv = (const float*)d_in[6];
    const float* bv = (const float*)d_in[7];
    const float* Wo = (const float*)d_in[8];
    const float* bo = (const float*)d_in[9];
    float* out = (float*)d_out;

    float *q, *k, *v, *att;
    cudaGetSymbolAddress((void**)&q,   g_q);
    cudaGetSymbolAddress((void**)&k,   g_k);
    cudaGetSymbolAddress((void**)&v,   g_v);
    cudaGetSymbolAddress((void**)&att, g_att);

    const int M = B_ * T_;  // 8192

    // Projections: Q/K on the score path -> 3xTF32; V/O -> 1xTF32
    gemm_tf32<true ><<<dim3(E_ / 128,   M / 128), 256>>>(x, Wq, bq, q, M, E_,   E_);
    gemm_tf32<true ><<<dim3(KVD_ / 128, M / 128), 256>>>(x, Wk, bk, k, M, KVD_, E_);
    gemm_tf32<false><<<dim3(KVD_ / 128, M / 128), 256>>>(x, Wv, bv, v, M, KVD_, E_);

    // RoPE on k and v
    rope_kernel<<<(B_ * NKV_ * T_ * 64) / 256, 256>>>(k, v);

    // Attention (fp32, exact-precision path)
    const int asmem = 116736;
    cudaFuncSetAttribute(flash_attn, cudaFuncAttributeMaxDynamicSharedMemorySize, asmem);
    flash_attn<<<dim3(T_ / 64, NH_, B_), 256, asmem>>>(q, k, v, am, att);

    // Output projection: 1xTF32
    gemm_tf32<false><<<dim3(E_ / 128, M / 128), 256>>>(att, Wo, bo, out, M, E_, E_);
}

// round 6
// speedup vs baseline: 2.8351x; 2.3678x over previous
#include <cuda_runtime.h>
#include <cuda_bf16.h>
#include <math.h>
#include <stdint.h>

constexpr int B_   = 4;
constexpr int T_   = 2048;
constexpr int E_   = 2048;
constexpr int NH_  = 16;
constexpr int NKV_ = 4;
constexpr int HD_  = 128;
constexpr int KVD_ = NKV_ * HD_;
constexpr float SCL2_ = 16.32232319089277f;   // sqrt(128) * log2(e)
constexpr float MSK2_ = 1.4426950408889634e-9f; // 1e-9 * log2(e)

__device__ float g_q[(size_t)B_ * T_ * E_];
__device__ float g_k[(size_t)B_ * T_ * KVD_];
__device__ float g_v[(size_t)B_ * T_ * KVD_];
__device__ float g_att[(size_t)B_ * T_ * E_];

// ---------------- helpers ----------------
__device__ __forceinline__ uint32_t f2tf(float f) {
    uint32_t u; asm("cvt.rna.tf32.f32 %0, %1;" : "=r"(u) : "f"(f)); return u;
}
__device__ __forceinline__ void split_tf(float f, uint32_t& hi, uint32_t& lo) {
    hi = f2tf(f); lo = f2tf(f - __uint_as_float(hi));
}
__device__ __forceinline__ float bfhi(float f) {
    return __bfloat162float(__float2bfloat16(f));
}
__device__ __forceinline__ uint32_t packbf(float f0, float f1) {
    __nv_bfloat162 h = __floats2bfloat162_rn(f0, f1);
    return *(uint32_t*)&h;
}
__device__ __forceinline__ float ex2f(float x) {
    float r; asm("ex2.approx.f32 %0, %1;" : "=f"(r) : "f"(x)); return r;
}
__device__ __forceinline__ void mma_tf32(float c[4], const uint32_t a[4], const uint32_t b[2]) {
    asm volatile("mma.sync.aligned.m16n8k8.row.col.f32.tf32.tf32.f32 "
        "{%0,%1,%2,%3}, {%4,%5,%6,%7}, {%8,%9}, {%0,%1,%2,%3};"
        : "+f"(c[0]), "+f"(c[1]), "+f"(c[2]), "+f"(c[3])
        : "r"(a[0]), "r"(a[1]), "r"(a[2]), "r"(a[3]), "r"(b[0]), "r"(b[1]));
}
__device__ __forceinline__ void mma_bf16(float c[4], const uint32_t a[4], const uint32_t b[2]) {
    asm volatile("mma.sync.aligned.m16n8k16.row.col.f32.bf16.bf16.f32 "
        "{%0,%1,%2,%3}, {%4,%5,%6,%7}, {%8,%9}, {%0,%1,%2,%3};"
        : "+f"(c[0]), "+f"(c[1]), "+f"(c[2]), "+f"(c[3])
        : "r"(a[0]), "r"(a[1]), "r"(a[2]), "r"(a[3]), "r"(b[0]), "r"(b[1]));
}

// ---------------- GEMM (proven round-2 kernel) ----------------
template<bool SPLIT>
__global__ void __launch_bounds__(256, 1)
gemm_tf32(const float* __restrict__ A, const float* __restrict__ W,
          const float* __restrict__ bias, float* __restrict__ C,
          int M, int N, int K)
{
    constexpr int ASd = 36, BSd = 136;
    __shared__ float As[128 * ASd];
    __shared__ float Bs[32 * BSd];

    const int tid = threadIdx.x, lane = tid & 31, warp = tid >> 5;
    const int wm = (warp >> 2) * 64, wn = (warp & 3) * 32;
    const int gid = lane >> 2, tig = lane & 3;
    const int bm = blockIdx.y * 128, bn = blockIdx.x * 128;
    const int la_m = tid >> 1, la_k = (tid & 1) * 16;
    const float* Ap = A + (size_t)(bm + la_m) * K + la_k;
    const float* Bp = W + (size_t)warp * N + bn + lane * 4;

    float4 ar[4], br[4];
    #pragma unroll
    for (int j = 0; j < 4; j++) ar[j] = *(const float4*)(Ap + 4 * j);
    #pragma unroll
    for (int j = 0; j < 4; j++) br[j] = *(const float4*)(Bp + (size_t)(8 * j) * N);

    float acc[4][4][4];
    #pragma unroll
    for (int i = 0; i < 4; i++)
        #pragma unroll
        for (int j = 0; j < 4; j++)
            #pragma unroll
            for (int c = 0; c < 4; c++) acc[i][j][c] = 0.f;

    for (int kt = 0; kt < K; kt += 32) {
        #pragma unroll
        for (int j = 0; j < 4; j++)
            *(float4*)&As[la_m * ASd + la_k + 4 * j] = ar[j];
        #pragma unroll
        for (int j = 0; j < 4; j++)
            *(float4*)&Bs[(warp + 8 * j) * BSd + lane * 4] = br[j];
        __syncthreads();

        if (kt + 32 < K) {
            #pragma unroll
            for (int j = 0; j < 4; j++) ar[j] = *(const float4*)(Ap + kt + 32 + 4 * j);
            #pragma unroll
            for (int j = 0; j < 4; j++) br[j] = *(const float4*)(Bp + (size_t)(kt + 32 + 8 * j) * N);
        }

        #pragma unroll
        for (int s = 0; s < 4; s++) {
            const int ks = s * 8;
            uint32_t ah[4][4], al[4][4];
            #pragma unroll
            for (int i = 0; i < 4; i++) {
                const int rb = wm + i * 16;
                float f0 = As[(rb + gid)     * ASd + ks + tig];
                float f1 = As[(rb + gid + 8) * ASd + ks + tig];
                float f2 = As[(rb + gid)     * ASd + ks + tig + 4];
                float f3 = As[(rb + gid + 8) * ASd + ks + tig + 4];
                if (SPLIT) {
                    split_tf(f0, ah[i][0], al[i][0]); split_tf(f1, ah[i][1], al[i][1]);
                    split_tf(f2, ah[i][2], al[i][2]); split_tf(f3, ah[i][3], al[i][3]);
                } else {
                    ah[i][0] = f2tf(f0); ah[i][1] = f2tf(f1);
                    ah[i][2] = f2tf(f2); ah[i][3] = f2tf(f3);
                }
            }
            #pragma unroll
            for (int j = 0; j < 4; j++) {
                const int cb = wn + j * 8;
                float g0 = Bs[(ks + tig)     * BSd + cb + gid];
                float g1 = Bs[(ks + tig + 4) * BSd + cb + gid];
                uint32_t bh[2], bl[2];
                if (SPLIT) { split_tf(g0, bh[0], bl[0]); split_tf(g1, bh[1], bl[1]); }
                else       { bh[0] = f2tf(g0); bh[1] = f2tf(g1); }
                #pragma unroll
                for (int i = 0; i < 4; i++) {
                    mma_tf32(acc[i][j], ah[i], bh);
                    if (SPLIT) { mma_tf32(acc[i][j], ah[i], bl); mma_tf32(acc[i][j], al[i], bh); }
                }
            }
        }
        __syncthreads();
    }

    #pragma unroll
    for (int j = 0; j < 4; j++) {
        const int col = bn + wn + j * 8 + tig * 2;
        const float b0 = bias[col], b1 = bias[col + 1];
        #pragma unroll
        for (int i = 0; i < 4; i++) {
            const int row = bm + wm + i * 16 + gid;
            *(float2*)&C[(size_t)row * N + col]       = make_float2(acc[i][j][0] + b0, acc[i][j][1] + b1);
            *(float2*)&C[(size_t)(row + 8) * N + col] = make_float2(acc[i][j][2] + b0, acc[i][j][3] + b1);
        }
    }
}

// ---------------- RoPE ----------------
__global__ void rope_kernel(float* __restrict__ k, float* __restrict__ v)
{
    int p = blockIdx.x * 256 + threadIdx.x;
    int d2 = p & 63, rr = p >> 6, t = rr & (T_ - 1);
    double th = exp2((double)d2 * -0.20762050593046014);
    float angf = (float)t * (float)th;
    float s, c;
    sincosf(angf, &s, &c);
    size_t base = (size_t)rr * HD_ + 2 * d2;
    float2 kk = *(float2*)(k + base), vv = *(float2*)(v + base);
    *(float2*)(k + base) = make_float2(kk.x * c - kk.y * s, kk.x * s + kk.y * c);
    *(float2*)(v + base) = make_float2(vv.x * c - vv.y * s, vv.x * s + vv.y * c);
}

// ---------------- Tensor-core flash attention ----------------
// 64q x 64k tiles. 8 warps: rg = warp&3 (16 q-rows), cg = warp>>2 (32 k-cols / 64 d-cols).
// S: bf16 3-term m16n8k16. Softmax in exp2 domain. PV: 1xTF32 m16n8k8.
// P (tf32 bits) aliases the K-lo plane: phases are disjoint.
constexpr int BST = 68;   // u32 stride, 64 bf16-pairs + pad (68 % 32 == 4)
constexpr int VST = 132;  // u32 stride for V tf32 (132 % 32 == 4)

__global__ void __launch_bounds__(256)
flash_mma(const float* __restrict__ Q, const float* __restrict__ Kb,
          const float* __restrict__ Vb, const int* __restrict__ mask,
          float* __restrict__ O)
{
    extern __shared__ uint32_t s4[];
    uint32_t* Qh = s4;                 // 64*68
    uint32_t* Ql = Qh + 64 * BST;
    uint32_t* Kh = Ql + 64 * BST;
    uint32_t* Kl = Kh + 64 * BST;      // aliased by Ps after S phase
    uint32_t* Ps = Kl;
    uint32_t* Vs = Kl + 64 * BST;      // 64*132
    float*   pmx = (float*)(Vs + 64 * VST);   // [2][64]

    const int tid = threadIdx.x, lane = tid & 31, warp = tid >> 5;
    const int rg = warp & 3, cg = warp >> 2;
    const int gid = lane >> 2, tig = lane & 3;
    const int q0 = blockIdx.x * 64, h = blockIdx.y, b = blockIdx.z;
    const int kh = h & (NKV_ - 1);
    const int lr = rg * 16 + gid;            // local q row (thread's first row)

    const float* qb = Q  + ((size_t)b * NH_  + h ) * ((size_t)T_ * HD_);
    const float* kb = Kb + ((size_t)b * NKV_ + kh) * ((size_t)T_ * HD_);
    const float* vb = Vb + ((size_t)b * NKV_ + kh) * ((size_t)T_ * HD_);
    const int*   mb = mask + (size_t)b * T_ * T_;

    // Q tile -> bf16 hi/lo planes (once)
    #pragma unroll
    for (int i = 0; i < 8; i++) {
        int f = i * 256 + tid, r = f >> 5, c4 = (f & 31) * 4;
        float4 x = *(const float4*)(qb + (size_t)(q0 + r) * HD_ + c4);
        int p0 = r * BST + (c4 >> 1);
        float hx = bfhi(x.x), hy = bfhi(x.y), hz = bfhi(x.z), hw = bfhi(x.w);
        Qh[p0]     = packbf(hx, hy);        Qh[p0 + 1] = packbf(hz, hw);
        Ql[p0]     = packbf(x.x - hx, x.y - hy);
        Ql[p0 + 1] = packbf(x.z - hz, x.w - hw);
    }

    float m0 = -1e30f, m1 = -1e30f, l0 = 0.f, l1 = 0.f;
    float oacc[8][4];
    #pragma unroll
    for (int j = 0; j < 8; j++)
        #pragma unroll
        for (int c = 0; c < 4; c++) oacc[j][c] = 0.f;

    for (int k0 = 0; k0 < T_; k0 += 64) {
        __syncthreads();   // prior PV reads done; Qh ready on first iter
        // load K (split) and V (tf32)
        #pragma unroll
        for (int i = 0; i < 8; i++) {
            int f = i * 256 + tid, r = f >> 5, c4 = (f & 31) * 4;
            float4 x = *(const float4*)(kb + (size_t)(k0 + r) * HD_ + c4);
            int p0 = r * BST + (c4 >> 1);
            float hx = bfhi(x.x), hy = bfhi(x.y), hz = bfhi(x.z), hw = bfhi(x.w);
            Kh[p0]     = packbf(hx, hy);        Kh[p0 + 1] = packbf(hz, hw);
            Kl[p0]     = packbf(x.x - hx, x.y - hy);
            Kl[p0 + 1] = packbf(x.z - hz, x.w - hw);
            float4 y = *(const float4*)(vb + (size_t)(k0 + r) * HD_ + c4);
            int v0 = r * VST + c4;
            Vs[v0] = f2tf(y.x); Vs[v0 + 1] = f2tf(y.y);
            Vs[v0 + 2] = f2tf(y.z); Vs[v0 + 3] = f2tf(y.w);
        }
        __syncthreads();

        // S = Q K^T  (bf16 3-term)
        float sacc[4][4];
        #pragma unroll
        for (int j = 0; j < 4; j++)
            #pragma unroll
            for (int c = 0; c < 4; c++) sacc[j][c] = 0.f;

        #pragma unroll
        for (int s = 0; s < 8; s++) {
            const int qa = lr * BST + 8 * s;
            uint32_t ah[4] = {Qh[qa + tig], Qh[qa + 8 * BST + tig],
                              Qh[qa + tig + 4], Qh[qa + 8 * BST + tig + 4]};
            uint32_t al[4] = {Ql[qa + tig], Ql[qa + 8 * BST + tig],
                              Ql[qa + tig + 4], Ql[qa + 8 * BST + tig + 4]};
            #pragma unroll
            for (int j = 0; j < 4; j++) {
                const int kbase = (cg * 32 + j * 8 + gid) * BST + 8 * s;
                uint32_t bh[2] = {Kh[kbase + tig], Kh[kbase + tig + 4]};
                uint32_t bl[2] = {Kl[kbase + tig], Kl[kbase + tig + 4]};
                mma_bf16(sacc[j], ah, bh);
                mma_bf16(sacc[j], ah, bl);
                mma_bf16(sacc[j], al, bh);
            }
        }

        // mask + scale (exp2 domain) + tile max
        float mx0 = -1e30f, mx1 = -1e30f;
        #pragma unroll
        for (int j = 0; j < 4; j++) {
            const int col = k0 + cg * 32 + j * 8 + 2 * tig;
            int2 mv0 = *(const int2*)(mb + (size_t)(q0 + lr)     * T_ + col);
            int2 mv1 = *(const int2*)(mb + (size_t)(q0 + lr + 8) * T_ + col);
            sacc[j][0] = mv0.x ? sacc[j][0] * SCL2_ : MSK2_;
            sacc[j][1] = mv0.y ? sacc[j][1] * SCL2_ : MSK2_;
            sacc[j][2] = mv1.x ? sacc[j][2] * SCL2_ : MSK2_;
            sacc[j][3] = mv1.y ? sacc[j][3] * SCL2_ : MSK2_;
            mx0 = fmaxf(mx0, fmaxf(sacc[j][0], sacc[j][1]));
            mx1 = fmaxf(mx1, fmaxf(sacc[j][2], sacc[j][3]));
        }
        mx0 = fmaxf(mx0, __shfl_xor_sync(0xffffffffu, mx0, 1));
        mx0 = fmaxf(mx0, __shfl_xor_sync(0xffffffffu, mx0, 2));
        mx1 = fmaxf(mx1, __shfl_xor_sync(0xffffffffu, mx1, 1));
        mx1 = fmaxf(mx1, __shfl_xor_sync(0xffffffffu, mx1, 2));
        if (tig == 0) { pmx[cg * 64 + lr] = mx0; pmx[cg * 64 + lr + 8] = mx1; }
        __syncthreads();   // also: all S-mma reads of Kl are done -> Ps may overwrite

        float mn0 = fmaxf(m0, fmaxf(pmx[lr],     pmx[64 + lr]));
        float mn1 = fmaxf(m1, fmaxf(pmx[lr + 8], pmx[64 + lr + 8]));
        float a0 = ex2f(m0 - mn0), a1 = ex2f(m1 - mn1);
        m0 = mn0; m1 = mn1;

        float sum0 = 0.f, sum1 = 0.f;
        #pragma unroll
        for (int j = 0; j < 4; j++) {
            float p0 = ex2f(sacc[j][0] - mn0), p1 = ex2f(sacc[j][1] - mn0);
            float p2 = ex2f(sacc[j][2] - mn1), p3 = ex2f(sacc[j][3] - mn1);
            sum0 += p0 + p1; sum1 += p2 + p3;
            const int pc = cg * 32 + j * 8 + 2 * tig;
            Ps[lr * BST + pc]           = f2tf(p0);
            Ps[lr * BST + pc + 1]       = f2tf(p1);
            Ps[(lr + 8) * BST + pc]     = f2tf(p2);
            Ps[(lr + 8) * BST + pc + 1] = f2tf(p3);
        }
        sum0 += __shfl_xor_sync(0xffffffffu, sum0, 1);
        sum0 += __shfl_xor_sync(0xffffffffu, sum0, 2);
        sum1 += __shfl_xor_sync(0xffffffffu, sum1, 1);
        sum1 += __shfl_xor_sync(0xffffffffu, sum1, 2);
        l0 = l0 * a0 + sum0;   // per-cg partial; combined at the end
        l1 = l1 * a1 + sum1;
        #pragma unroll
        for (int j = 0; j < 8; j++) {
            oacc[j][0] *= a0; oacc[j][1] *= a0;
            oacc[j][2] *= a1; oacc[j][3] *= a1;
        }
        __syncthreads();   // Ps visible to all warps

        // O += P V  (1xTF32)
        #pragma unroll
        for (int s = 0; s < 8; s++) {
            const int pa0 = lr * BST + 8 * s, pa1 = (lr + 8) * BST + 8 * s;
            uint32_t pa[4] = {Ps[pa0 + tig], Ps[pa1 + tig],
                              Ps[pa0 + tig + 4], Ps[pa1 + tig + 4]};
            #pragma unroll
            for (int j = 0; j < 8; j++) {
                const int vn = cg * 64 + j * 8 + gid;
                uint32_t vbf[2] = {Vs[(8 * s + tig) * VST + vn],
                                   Vs[(8 * s + tig + 4) * VST + vn]};
                mma_tf32(oacc[j], pa, vbf);
            }
        }
    }

    // combine l across the two cg warps, normalize, store (b,t,h,d)
    __syncthreads();
    if (tig == 0) { pmx[cg * 64 + lr] = l0; pmx[cg * 64 + lr + 8] = l1; }
    __syncthreads();
    const float inv0 = 1.f / (pmx[lr] + pmx[64 + lr]);
    const float inv1 = 1.f / (pmx[lr + 8] + pmx[64 + lr + 8]);
    float* ob = O + ((size_t)b * T_ + q0 + lr) * E_ + h * HD_ + cg * 64 + 2 * tig;
    #pragma unroll
    for (int j = 0; j < 8; j++) {
        *(float2*)(ob + j * 8)            = make_float2(oacc[j][0] * inv0, oacc[j][1] * inv0);
        *(float2*)(ob + 8 * (size_t)E_ + j * 8) = make_float2(oacc[j][2] * inv1, oacc[j][3] * inv1);
    }
}

// ---------------- launcher ----------------
extern "C" void kernel_launch(void* const* d_in, const int* in_sizes, int n_in,
                              void* d_out, int out_size)
{
    const float* x  = (const float*)d_in[0];
    const int*   am = (const int*)  d_in[1];
    const float* Wq = (const float*)d_in[2];
    const float* bq = (const float*)d_in[3];
    const float* Wk = (const float*)d_in[4];
    const float* bk = (const float*)d_in[5];
    const float* Wv = (const float*)d_in[6];
    const float* bv = (const float*)d_in[7];
    const float* Wo = (const float*)d_in[8];
    const float* bo = (const float*)d_in[9];
    float* out = (float*)d_out;

    float *q, *k, *v, *att;
    cudaGetSymbolAddress((void**)&q,   g_q);
    cudaGetSymbolAddress((void**)&k,   g_k);
    cudaGetSymbolAddress((void**)&v,   g_v);
    cudaGetSymbolAddress((void**)&att, g_att);

    const int M = B_ * T_;

    gemm_tf32<true ><<<dim3(E_ / 128,   M / 128), 256>>>(x, Wq, bq, q, M, E_,   E_);
    gemm_tf32<true ><<<dim3(KVD_ / 128, M / 128), 256>>>(x, Wk, bk, k, M, KVD_, E_);
    gemm_tf32<false><<<dim3(KVD_ / 128, M / 128), 256>>>(x, Wv, bv, v, M, KVD_, E_);

    rope_kernel<<<(B_ * NKV_ * T_ * 64) / 256, 256>>>(k, v);

    const int fsmem = (4 * 64 * BST + 64 * VST + 128) * 4;  // 103936 B
    cudaFuncSetAttribute(flash_mma, cudaFuncAttributeMaxDynamicSharedMemorySize, fsmem);
    flash_mma<<<dim3(T_ / 64, NH_, B_), 256, fsmem>>>(q, k, v, am, att);

    gemm_tf32<false><<<dim3(E_ / 128, M / 128), 256>>>(att, Wo, bo, out, M, E_, E_);
}

// round 7
// speedup vs baseline: 3.2142x; 1.1337x over previous
#include <cuda_runtime.h>
#include <cuda_bf16.h>
#include <math.h>
#include <stdint.h>

constexpr int B_   = 4;
constexpr int T_   = 2048;
constexpr int E_   = 2048;
constexpr int NH_  = 16;
constexpr int NKV_ = 4;
constexpr int HD_  = 128;
constexpr int KVD_ = NKV_ * HD_;
constexpr float SCL2_ = 16.32232319089277f;     // sqrt(128) * log2(e)
constexpr float MSK2_ = 1.4426950408889634e-9f; // 1e-9 * log2(e)

__device__ float g_q[(size_t)B_ * T_ * E_];
__device__ float g_k[(size_t)B_ * T_ * KVD_];
__device__ float g_v[(size_t)B_ * T_ * KVD_];
__device__ float g_att[(size_t)B_ * T_ * E_];

// ---------------- helpers ----------------
__device__ __forceinline__ uint32_t f2tf(float f) {
    uint32_t u; asm("cvt.rna.tf32.f32 %0, %1;" : "=r"(u) : "f"(f)); return u;
}
__device__ __forceinline__ float bfhi(float f) {
    return __bfloat162float(__float2bfloat16(f));
}
__device__ __forceinline__ uint32_t packbf(float f0, float f1) {
    __nv_bfloat162 h = __floats2bfloat162_rn(f0, f1);
    return *(uint32_t*)&h;
}
__device__ __forceinline__ float ex2f(float x) {
    float r; asm("ex2.approx.f32 %0, %1;" : "=f"(r) : "f"(x)); return r;
}
__device__ __forceinline__ void mma_tf32(float c[4], const uint32_t a[4], const uint32_t b[2]) {
    asm volatile("mma.sync.aligned.m16n8k8.row.col.f32.tf32.tf32.f32 "
        "{%0,%1,%2,%3}, {%4,%5,%6,%7}, {%8,%9}, {%0,%1,%2,%3};"
        : "+f"(c[0]), "+f"(c[1]), "+f"(c[2]), "+f"(c[3])
        : "r"(a[0]), "r"(a[1]), "r"(a[2]), "r"(a[3]), "r"(b[0]), "r"(b[1]));
}
__device__ __forceinline__ void mma_bf16(float c[4], const uint32_t a[4], const uint32_t b[2]) {
    asm volatile("mma.sync.aligned.m16n8k16.row.col.f32.bf16.bf16.f32 "
        "{%0,%1,%2,%3}, {%4,%5,%6,%7}, {%8,%9}, {%0,%1,%2,%3};"
        : "+f"(c[0]), "+f"(c[1]), "+f"(c[2]), "+f"(c[3])
        : "r"(a[0]), "r"(a[1]), "r"(a[2]), "r"(a[3]), "r"(b[0]), "r"(b[1]));
}

// ---------------------------------------------------------------------------
// bf16 2-plane / 3-term GEMM for the Q/K projections.
// 128x128 tile, BK=32, 8 warps (2x4), m16n8k16. Split once at STS time.
// A smem [row][kpair] stride 20 u32; B smem [kpair][n] stride 132 u32.
// ---------------------------------------------------------------------------
__global__ void __launch_bounds__(256, 1)
gemm_bf16(const float* __restrict__ A, const float* __restrict__ W,
          const float* __restrict__ bias, float* __restrict__ C,
          int M, int N, int K)
{
    constexpr int AS = 20;    // u32 row stride (16 pairs + pad)
    constexpr int BS = 132;   // u32 kpair-row stride (128 n + pad)
    __shared__ uint32_t Ah[128 * AS], Al[128 * AS];
    __shared__ uint32_t Bh[16 * BS],  Bl[16 * BS];

    const int tid = threadIdx.x, lane = tid & 31, warp = tid >> 5;
    const int wm = (warp >> 2) * 64, wn = (warp & 3) * 32;
    const int gid = lane >> 2, tig = lane & 3;
    const int bm = blockIdx.y * 128, bn = blockIdx.x * 128;

    const int la_m = tid >> 1, la_k = (tid & 1) * 16;
    const float* Ap = A + (size_t)(bm + la_m) * K + la_k;
    const float* Bp = W + bn + lane * 4;
    const int kr0 = 2 * warp, kr1 = 2 * warp + 1;
    const int kr2 = 2 * warp + 16, kr3 = 2 * warp + 17;

    float4 ar[4], br[4];
    #pragma unroll
    for (int j = 0; j < 4; j++) ar[j] = *(const float4*)(Ap + 4 * j);
    br[0] = *(const float4*)(Bp + (size_t)kr0 * N);
    br[1] = *(const float4*)(Bp + (size_t)kr1 * N);
    br[2] = *(const float4*)(Bp + (size_t)kr2 * N);
    br[3] = *(const float4*)(Bp + (size_t)kr3 * N);

    float acc[4][4][4];
    #pragma unroll
    for (int i = 0; i < 4; i++)
        #pragma unroll
        for (int j = 0; j < 4; j++)
            #pragma unroll
            for (int c = 0; c < 4; c++) acc[i][j][c] = 0.f;

    for (int kt = 0; kt < K; kt += 32) {
        // A split + STS
        #pragma unroll
        for (int j = 0; j < 4; j++) {
            float4 x = ar[j];
            float hx = bfhi(x.x), hy = bfhi(x.y), hz = bfhi(x.z), hw = bfhi(x.w);
            uint2 hh = make_uint2(packbf(hx, hy), packbf(hz, hw));
            uint2 ll = make_uint2(packbf(x.x - hx, x.y - hy), packbf(x.z - hz, x.w - hw));
            int off = la_m * AS + (la_k >> 1) + 2 * j;
            *(uint2*)&Ah[off] = hh;
            *(uint2*)&Al[off] = ll;
        }
        // B split + STS (pairs along k: rows (kr0,kr1) -> kpair warp; (kr2,kr3) -> warp+8)
        {
            uint4 h0, l0, h1, l1;
            #pragma unroll
            for (int e = 0; e < 4; e++) {
                float a0 = ((const float*)&br[0])[e], a1 = ((const float*)&br[1])[e];
                float b0 = ((const float*)&br[2])[e], b1 = ((const float*)&br[3])[e];
                float ha0 = bfhi(a0), ha1 = bfhi(a1), hb0 = bfhi(b0), hb1 = bfhi(b1);
                ((uint32_t*)&h0)[e] = packbf(ha0, ha1);
                ((uint32_t*)&l0)[e] = packbf(a0 - ha0, a1 - ha1);
                ((uint32_t*)&h1)[e] = packbf(hb0, hb1);
                ((uint32_t*)&l1)[e] = packbf(b0 - hb0, b1 - hb1);
            }
            *(uint4*)&Bh[warp * BS + 4 * lane]       = h0;
            *(uint4*)&Bl[warp * BS + 4 * lane]       = l0;
            *(uint4*)&Bh[(warp + 8) * BS + 4 * lane] = h1;
            *(uint4*)&Bl[(warp + 8) * BS + 4 * lane] = l1;
        }
        __syncthreads();

        if (kt + 32 < K) {   // register prefetch
            #pragma unroll
            for (int j = 0; j < 4; j++) ar[j] = *(const float4*)(Ap + kt + 32 + 4 * j);
            br[0] = *(const float4*)(Bp + (size_t)(kt + 32 + kr0) * N);
            br[1] = *(const float4*)(Bp + (size_t)(kt + 32 + kr1) * N);
            br[2] = *(const float4*)(Bp + (size_t)(kt + 32 + kr2) * N);
            br[3] = *(const float4*)(Bp + (size_t)(kt + 32 + kr3) * N);
        }

        #pragma unroll
        for (int s = 0; s < 2; s++) {
            const int s8 = s * 8;
            uint32_t ah[4][4], al[4][4];
            #pragma unroll
            for (int i = 0; i < 4; i++) {
                const int r0 = (wm + i * 16 + gid) * AS + s8;
                const int r1 = r0 + 8 * AS;
                ah[i][0] = Ah[r0 + tig];     ah[i][1] = Ah[r1 + tig];
                ah[i][2] = Ah[r0 + tig + 4]; ah[i][3] = Ah[r1 + tig + 4];
                al[i][0] = Al[r0 + tig];     al[i][1] = Al[r1 + tig];
                al[i][2] = Al[r0 + tig + 4]; al[i][3] = Al[r1 + tig + 4];
            }
            #pragma unroll
            for (int j = 0; j < 4; j++) {
                const int cb = wn + j * 8 + gid;
                uint32_t bh[2] = {Bh[(s8 + tig) * BS + cb], Bh[(s8 + tig + 4) * BS + cb]};
                uint32_t bl[2] = {Bl[(s8 + tig) * BS + cb], Bl[(s8 + tig + 4) * BS + cb]};
                #pragma unroll
                for (int i = 0; i < 4; i++) {
                    mma_bf16(acc[i][j], ah[i], bh);
                    mma_bf16(acc[i][j], ah[i], bl);
                    mma_bf16(acc[i][j], al[i], bh);
                }
            }
        }
        __syncthreads();
    }

    #pragma unroll
    for (int j = 0; j < 4; j++) {
        const int col = bn + wn + j * 8 + tig * 2;
        const float b0 = bias[col], b1 = bias[col + 1];
        #pragma unroll
        for (int i = 0; i < 4; i++) {
            const int row = bm + wm + i * 16 + gid;
            *(float2*)&C[(size_t)row * N + col]       = make_float2(acc[i][j][0] + b0, acc[i][j][1] + b1);
            *(float2*)&C[(size_t)(row + 8) * N + col] = make_float2(acc[i][j][2] + b0, acc[i][j][3] + b1);
        }
    }
}

// ---------------- 1xTF32 GEMM (V/O projections, proven) ----------------
__global__ void __launch_bounds__(256, 1)
gemm_tf32(const float* __restrict__ A, const float* __restrict__ W,
          const float* __restrict__ bias, float* __restrict__ C,
          int M, int N, int K)
{
    constexpr int ASd = 36, BSd = 136;
    __shared__ float As[128 * ASd];
    __shared__ float Bs[32 * BSd];

    const int tid = threadIdx.x, lane = tid & 31, warp = tid >> 5;
    const int wm = (warp >> 2) * 64, wn = (warp & 3) * 32;
    const int gid = lane >> 2, tig = lane & 3;
    const int bm = blockIdx.y * 128, bn = blockIdx.x * 128;
    const int la_m = tid >> 1, la_k = (tid & 1) * 16;
    const float* Ap = A + (size_t)(bm + la_m) * K + la_k;
    const float* Bp = W + (size_t)warp * N + bn + lane * 4;

    float4 ar[4], br[4];
    #pragma unroll
    for (int j = 0; j < 4; j++) ar[j] = *(const float4*)(Ap + 4 * j);
    #pragma unroll
    for (int j = 0; j < 4; j++) br[j] = *(const float4*)(Bp + (size_t)(8 * j) * N);

    float acc[4][4][4];
    #pragma unroll
    for (int i = 0; i < 4; i++)
        #pragma unroll
        for (int j = 0; j < 4; j++)
            #pragma unroll
            for (int c = 0; c < 4; c++) acc[i][j][c] = 0.f;

    for (int kt = 0; kt < K; kt += 32) {
        #pragma unroll
        for (int j = 0; j < 4; j++)
            *(float4*)&As[la_m * ASd + la_k + 4 * j] = ar[j];
        #pragma unroll
        for (int j = 0; j < 4; j++)
            *(float4*)&Bs[(warp + 8 * j) * BSd + lane * 4] = br[j];
        __syncthreads();

        if (kt + 32 < K) {
            #pragma unroll
            for (int j = 0; j < 4; j++) ar[j] = *(const float4*)(Ap + kt + 32 + 4 * j);
            #pragma unroll
            for (int j = 0; j < 4; j++) br[j] = *(const float4*)(Bp + (size_t)(kt + 32 + 8 * j) * N);
        }

        #pragma unroll
        for (int s = 0; s < 4; s++) {
            const int ks = s * 8;
            uint32_t ah[4][4];
            #pragma unroll
            for (int i = 0; i < 4; i++) {
                const int rb = wm + i * 16;
                ah[i][0] = f2tf(As[(rb + gid)     * ASd + ks + tig]);
                ah[i][1] = f2tf(As[(rb + gid + 8) * ASd + ks + tig]);
                ah[i][2] = f2tf(As[(rb + gid)     * ASd + ks + tig + 4]);
                ah[i][3] = f2tf(As[(rb + gid + 8) * ASd + ks + tig + 4]);
            }
            #pragma unroll
            for (int j = 0; j < 4; j++) {
                const int cb = wn + j * 8;
                uint32_t bh[2];
                bh[0] = f2tf(Bs[(ks + tig)     * BSd + cb + gid]);
                bh[1] = f2tf(Bs[(ks + tig + 4) * BSd + cb + gid]);
                #pragma unroll
                for (int i = 0; i < 4; i++) mma_tf32(acc[i][j], ah[i], bh);
            }
        }
        __syncthreads();
    }

    #pragma unroll
    for (int j = 0; j < 4; j++) {
        const int col = bn + wn + j * 8 + tig * 2;
        const float b0 = bias[col], b1 = bias[col + 1];
        #pragma unroll
        for (int i = 0; i < 4; i++) {
            const int row = bm + wm + i * 16 + gid;
            *(float2*)&C[(size_t)row * N + col]       = make_float2(acc[i][j][0] + b0, acc[i][j][1] + b1);
            *(float2*)&C[(size_t)(row + 8) * N + col] = make_float2(acc[i][j][2] + b0, acc[i][j][3] + b1);
        }
    }
}

// ---------------- RoPE ----------------
__global__ void rope_kernel(float* __restrict__ k, float* __restrict__ v)
{
    int p = blockIdx.x * 256 + threadIdx.x;
    int d2 = p & 63, rr = p >> 6, t = rr & (T_ - 1);
    double th = exp2((double)d2 * -0.20762050593046014);
    float angf = (float)t * (float)th;
    float s, c;
    sincosf(angf, &s, &c);
    size_t base = (size_t)rr * HD_ + 2 * d2;
    float2 kk = *(float2*)(k + base), vv = *(float2*)(v + base);
    *(float2*)(k + base) = make_float2(kk.x * c - kk.y * s, kk.x * s + kk.y * c);
    *(float2*)(v + base) = make_float2(vv.x * c - vv.y * s, vv.x * s + vv.y * c);
}

// ---------------- Tensor-core flash attention ----------------
constexpr int BST = 68;
constexpr int VST = 132;

__global__ void __launch_bounds__(256, 2)
flash_mma(const float* __restrict__ Q, const float* __restrict__ Kb,
          const float* __restrict__ Vb, const int* __restrict__ mask,
          float* __restrict__ O)
{
    extern __shared__ uint32_t s4[];
    uint32_t* Qh = s4;
    uint32_t* Ql = Qh + 64 * BST;
    uint32_t* Kh = Ql + 64 * BST;
    uint32_t* Kl = Kh + 64 * BST;   // aliased by Ps after the S phase
    uint32_t* Ps = Kl;
    uint32_t* Vs = Kl + 64 * BST;
    float*   pmx = (float*)(Vs + 64 * VST);  // [2][64]

    const int tid = threadIdx.x, lane = tid & 31, warp = tid >> 5;
    const int rg = warp & 3, cg = warp >> 2;
    const int gid = lane >> 2, tig = lane & 3;
    const int q0 = blockIdx.x * 64, h = blockIdx.y, b = blockIdx.z;
    const int kh = h & (NKV_ - 1);
    const int lr = rg * 16 + gid;

    const float* qb = Q  + ((size_t)b * NH_  + h ) * ((size_t)T_ * HD_);
    const float* kb = Kb + ((size_t)b * NKV_ + kh) * ((size_t)T_ * HD_);
    const float* vb = Vb + ((size_t)b * NKV_ + kh) * ((size_t)T_ * HD_);
    const int*   mb = mask + (size_t)b * T_ * T_;

    #pragma unroll
    for (int i = 0; i < 8; i++) {
        int f = i * 256 + tid, r = f >> 5, c4 = (f & 31) * 4;
        float4 x = *(const float4*)(qb + (size_t)(q0 + r) * HD_ + c4);
        int p0 = r * BST + (c4 >> 1);
        float hx = bfhi(x.x), hy = bfhi(x.y), hz = bfhi(x.z), hw = bfhi(x.w);
        Qh[p0]     = packbf(hx, hy);        Qh[p0 + 1] = packbf(hz, hw);
        Ql[p0]     = packbf(x.x - hx, x.y - hy);
        Ql[p0 + 1] = packbf(x.z - hz, x.w - hw);
    }

    float m0 = -1e30f, m1 = -1e30f, l0 = 0.f, l1 = 0.f;
    float oacc[8][4];
    #pragma unroll
    for (int j = 0; j < 8; j++)
        #pragma unroll
        for (int c = 0; c < 4; c++) oacc[j][c] = 0.f;

    for (int k0 = 0; k0 < T_; k0 += 64) {
        // mask prefetch (no smem dependence — latency covered by barrier + loads + S-mma)
        int2 mq0[4], mq1[4];
        #pragma unroll
        for (int j = 0; j < 4; j++) {
            const int col = k0 + cg * 32 + j * 8 + 2 * tig;
            mq0[j] = *(const int2*)(mb + (size_t)(q0 + lr)     * T_ + col);
            mq1[j] = *(const int2*)(mb + (size_t)(q0 + lr + 8) * T_ + col);
        }
        __syncthreads();   // prior PV reads of Ps/Vs done
        // K/V tiles, batched loads (MLP 4)
        #pragma unroll
        for (int i = 0; i < 8; i += 2) {
            int f0 = i * 256 + tid, f1 = (i + 1) * 256 + tid;
            int r0 = f0 >> 5, c40 = (f0 & 31) * 4;
            int r1 = f1 >> 5, c41 = (f1 & 31) * 4;
            float4 x0 = *(const float4*)(kb + (size_t)(k0 + r0) * HD_ + c40);
            float4 x1 = *(const float4*)(kb + (size_t)(k0 + r1) * HD_ + c41);
            float4 y0 = *(const float4*)(vb + (size_t)(k0 + r0) * HD_ + c40);
            float4 y1 = *(const float4*)(vb + (size_t)(k0 + r1) * HD_ + c41);
            int p0 = r0 * BST + (c40 >> 1), p1 = r1 * BST + (c41 >> 1);
            float hx, hy, hz, hw;
            hx = bfhi(x0.x); hy = bfhi(x0.y); hz = bfhi(x0.z); hw = bfhi(x0.w);
            Kh[p0] = packbf(hx, hy); Kh[p0 + 1] = packbf(hz, hw);
            Kl[p0] = packbf(x0.x - hx, x0.y - hy); Kl[p0 + 1] = packbf(x0.z - hz, x0.w - hw);
            hx = bfhi(x1.x); hy = bfhi(x1.y); hz = bfhi(x1.z); hw = bfhi(x1.w);
            Kh[p1] = packbf(hx, hy); Kh[p1 + 1] = packbf(hz, hw);
            Kl[p1] = packbf(x1.x - hx, x1.y - hy); Kl[p1 + 1] = packbf(x1.z - hz, x1.w - hw);
            int v0 = r0 * VST + c40, v1 = r1 * VST + c41;
            Vs[v0] = f2tf(y0.x); Vs[v0 + 1] = f2tf(y0.y); Vs[v0 + 2] = f2tf(y0.z); Vs[v0 + 3] = f2tf(y0.w);
            Vs[v1] = f2tf(y1.x); Vs[v1 + 1] = f2tf(y1.y); Vs[v1 + 2] = f2tf(y1.z); Vs[v1 + 3] = f2tf(y1.w);
        }
        __syncthreads();

        // S = Q K^T (bf16 3-term)
        float sacc[4][4];
        #pragma unroll
        for (int j = 0; j < 4; j++)
            #pragma unroll
            for (int c = 0; c < 4; c++) sacc[j][c] = 0.f;

        #pragma unroll
        for (int s = 0; s < 8; s++) {
            const int qa = lr * BST + 8 * s;
            uint32_t ah[4] = {Qh[qa + tig], Qh[qa + 8 * BST + tig],
                              Qh[qa + tig + 4], Qh[qa + 8 * BST + tig + 4]};
            uint32_t al[4] = {Ql[qa + tig], Ql[qa + 8 * BST + tig],
                              Ql[qa + tig + 4], Ql[qa + 8 * BST + tig + 4]};
            #pragma unroll
            for (int j = 0; j < 4; j++) {
                const int kbase = (cg * 32 + j * 8 + gid) * BST + 8 * s;
                uint32_t bh[2] = {Kh[kbase + tig], Kh[kbase + tig + 4]};
                uint32_t bl[2] = {Kl[kbase + tig], Kl[kbase + tig + 4]};
                mma_bf16(sacc[j], ah, bh);
                mma_bf16(sacc[j], ah, bl);
                mma_bf16(sacc[j], al, bh);
            }
        }

        // mask (prefetched) + scale + tile max
        float mx0 = -1e30f, mx1 = -1e30f;
        #pragma unroll
        for (int j = 0; j < 4; j++) {
            sacc[j][0] = mq0[j].x ? sacc[j][0] * SCL2_ : MSK2_;
            sacc[j][1] = mq0[j].y ? sacc[j][1] * SCL2_ : MSK2_;
            sacc[j][2] = mq1[j].x ? sacc[j][2] * SCL2_ : MSK2_;
            sacc[j][3] = mq1[j].y ? sacc[j][3] * SCL2_ : MSK2_;
            mx0 = fmaxf(mx0, fmaxf(sacc[j][0], sacc[j][1]));
            mx1 = fmaxf(mx1, fmaxf(sacc[j][2], sacc[j][3]));
        }
        mx0 = fmaxf(mx0, __shfl_xor_sync(0xffffffffu, mx0, 1));
        mx0 = fmaxf(mx0, __shfl_xor_sync(0xffffffffu, mx0, 2));
        mx1 = fmaxf(mx1, __shfl_xor_sync(0xffffffffu, mx1, 1));
        mx1 = fmaxf(mx1, __shfl_xor_sync(0xffffffffu, mx1, 2));
        if (tig == 0) { pmx[cg * 64 + lr] = mx0; pmx[cg * 64 + lr + 8] = mx1; }
        __syncthreads();   // full: pmx exchange AND Kl->Ps alias guard

        float mn0 = fmaxf(m0, fmaxf(pmx[lr],     pmx[64 + lr]));
        float mn1 = fmaxf(m1, fmaxf(pmx[lr + 8], pmx[64 + lr + 8]));
        float a0 = ex2f(m0 - mn0), a1 = ex2f(m1 - mn1);
        m0 = mn0; m1 = mn1;

        float sum0 = 0.f, sum1 = 0.f;
        #pragma unroll
        for (int j = 0; j < 4; j++) {
            float p0 = ex2f(sacc[j][0] - mn0), p1 = ex2f(sacc[j][1] - mn0);
            float p2 = ex2f(sacc[j][2] - mn1), p3 = ex2f(sacc[j][3] - mn1);
            sum0 += p0 + p1; sum1 += p2 + p3;
            const int pc = cg * 32 + j * 8 + 2 * tig;
            Ps[lr * BST + pc]           = f2tf(p0);
            Ps[lr * BST + pc + 1]       = f2tf(p1);
            Ps[(lr + 8) * BST + pc]     = f2tf(p2);
            Ps[(lr + 8) * BST + pc + 1] = f2tf(p3);
        }
        sum0 += __shfl_xor_sync(0xffffffffu, sum0, 1);
        sum0 += __shfl_xor_sync(0xffffffffu, sum0, 2);
        sum1 += __shfl_xor_sync(0xffffffffu, sum1, 1);
        sum1 += __shfl_xor_sync(0xffffffffu, sum1, 2);
        l0 = l0 * a0 + sum0;
        l1 = l1 * a1 + sum1;
        #pragma unroll
        for (int j = 0; j < 8; j++) {
            oacc[j][0] *= a0; oacc[j][1] *= a0;
            oacc[j][2] *= a1; oacc[j][3] *= a1;
        }
        // Ps write -> PV read is pair-local (warps rg and rg+4 share rows lr..lr+15)
        asm volatile("bar.sync %0, 64;" :: "r"(rg + 1) : "memory");

        // O += P V (1xTF32)
        #pragma unroll
        for (int s = 0; s < 8; s++) {
            const int pa0 = lr * BST + 8 * s, pa1 = (lr + 8) * BST + 8 * s;
            uint32_t pa[4] = {Ps[pa0 + tig], Ps[pa1 + tig],
                              Ps[pa0 + tig + 4], Ps[pa1 + tig + 4]};
            #pragma unroll
            for (int j = 0; j < 8; j++) {
                const int vn = cg * 64 + j * 8 + gid;
                uint32_t vbf[2] = {Vs[(8 * s + tig) * VST + vn],
                                   Vs[(8 * s + tig + 4) * VST + vn]};
                mma_tf32(oacc[j], pa, vbf);
            }
        }
    }

    // pair-local l exchange (pmx slots are disjoint per rg)
    asm volatile("bar.sync %0, 64;" :: "r"(rg + 1) : "memory");
    if (tig == 0) { pmx[cg * 64 + lr] = l0; pmx[cg * 64 + lr + 8] = l1; }
    asm volatile("bar.sync %0, 64;" :: "r"(rg + 1) : "memory");
    const float inv0 = 1.f / (pmx[lr] + pmx[64 + lr]);
    const float inv1 = 1.f / (pmx[lr + 8] + pmx[64 + lr + 8]);
    float* ob = O + ((size_t)b * T_ + q0 + lr) * E_ + h * HD_ + cg * 64 + 2 * tig;
    #pragma unroll
    for (int j = 0; j < 8; j++) {
        *(float2*)(ob + j * 8)                  = make_float2(oacc[j][0] * inv0, oacc[j][1] * inv0);
        *(float2*)(ob + 8 * (size_t)E_ + j * 8) = make_float2(oacc[j][2] * inv1, oacc[j][3] * inv1);
    }
}

// ---------------- launcher ----------------
extern "C" void kernel_launch(void* const* d_in, const int* in_sizes, int n_in,
                              void* d_out, int out_size)
{
    const float* x  = (const float*)d_in[0];
    const int*   am = (const int*)  d_in[1];
    const float* Wq = (const float*)d_in[2];
    const float* bq = (const float*)d_in[3];
    const float* Wk = (const float*)d_in[4];
    const float* bk = (const float*)d_in[5];
    const float* Wv = (const float*)d_in[6];
    const float* bv = (const float*)d_in[7];
    const float* Wo = (const float*)d_in[8];
    const float* bo = (const float*)d_in[9];
    float* out = (float*)d_out;

    float *q, *k, *v, *att;
    cudaGetSymbolAddress((void**)&q,   g_q);
    cudaGetSymbolAddress((void**)&k,   g_k);
    cudaGetSymbolAddress((void**)&v,   g_v);
    cudaGetSymbolAddress((void**)&att, g_att);

    const int M = B_ * T_;

    gemm_bf16<<<dim3(E_ / 128,   M / 128), 256>>>(x, Wq, bq, q, M, E_,   E_);
    gemm_bf16<<<dim3(KVD_ / 128, M / 128), 256>>>(x, Wk, bk, k, M, KVD_, E_);
    gemm_tf32<<<dim3(KVD_ / 128, M / 128), 256>>>(x, Wv, bv, v, M, KVD_, E_);

    rope_kernel<<<(B_ * NKV_ * T_ * 64) / 256, 256>>>(k, v);

    const int fsmem = (4 * 64 * BST + 64 * VST + 128) * 4;  // 103936 B
    cudaFuncSetAttribute(flash_mma, cudaFuncAttributeMaxDynamicSharedMemorySize, fsmem);
    flash_mma<<<dim3(T_ / 64, NH_, B_), 256, fsmem>>>(q, k, v, am, att);

    gemm_tf32<<<dim3(E_ / 128, M / 128), 256>>>(att, Wo, bo, out, M, E_, E_);
}

// round 12
// speedup vs baseline: 3.2150x; 1.0002x over previous
#include <cuda_runtime.h>
#include <cuda_bf16.h>
#include <math.h>
#include <stdint.h>

constexpr int B_   = 4;
constexpr int T_   = 2048;
constexpr int E_   = 2048;
constexpr int NH_  = 16;
constexpr int NKV_ = 4;
constexpr int HD_  = 128;
constexpr int KVD_ = NKV_ * HD_;
constexpr float SCL2_ = 16.32232319089277f;     // sqrt(128) * log2(e)
constexpr float MSK2_ = 1.4426950408889634e-9f; // 1e-9 * log2(e)

__device__ float g_q[(size_t)B_ * T_ * E_];            // placeholder (POUT path writes planes)
__device__ float g_k[(size_t)B_ * T_ * KVD_];          // f32 K (rope input)
__device__ float g_v[(size_t)B_ * T_ * KVD_];          // f32 V (rope input)
__device__ float g_att[(size_t)B_ * T_ * E_];
__device__ uint32_t g_qh[(size_t)B_ * NH_  * T_ * 64]; // Q bf16-pair hi plane (view layout)
__device__ uint32_t g_ql[(size_t)B_ * NH_  * T_ * 64]; // Q lo plane
__device__ uint32_t g_kh[(size_t)B_ * NKV_ * T_ * 64]; // K hi plane (post-rope)
__device__ uint32_t g_kl[(size_t)B_ * NKV_ * T_ * 64]; // K lo plane
__device__ uint32_t g_vt[(size_t)B_ * NKV_ * T_ * 128];// V tf32 bits (post-rope)

// ---------------- helpers ----------------
__device__ __forceinline__ uint32_t f2tf(float f) {
    uint32_t u; asm("cvt.rna.tf32.f32 %0, %1;" : "=r"(u) : "f"(f)); return u;
}
__device__ __forceinline__ float bfhi(float f) {
    return __bfloat162float(__float2bfloat16(f));
}
__device__ __forceinline__ uint32_t packbf(float f0, float f1) {
    __nv_bfloat162 h = __floats2bfloat162_rn(f0, f1);
    return *(uint32_t*)&h;
}
__device__ __forceinline__ float ex2f(float x) {
    float r; asm("ex2.approx.f32 %0, %1;" : "=f"(r) : "f"(x)); return r;
}
__device__ __forceinline__ void mma_tf32(float c[4], const uint32_t a[4], const uint32_t b[2]) {
    asm volatile("mma.sync.aligned.m16n8k8.row.col.f32.tf32.tf32.f32 "
        "{%0,%1,%2,%3}, {%4,%5,%6,%7}, {%8,%9}, {%0,%1,%2,%3};"
        : "+f"(c[0]), "+f"(c[1]), "+f"(c[2]), "+f"(c[3])
        : "r"(a[0]), "r"(a[1]), "r"(a[2]), "r"(a[3]), "r"(b[0]), "r"(b[1]));
}
__device__ __forceinline__ void mma_bf16(float c[4], const uint32_t a[4], const uint32_t b[2]) {
    asm volatile("mma.sync.aligned.m16n8k16.row.col.f32.bf16.bf16.f32 "
        "{%0,%1,%2,%3}, {%4,%5,%6,%7}, {%8,%9}, {%0,%1,%2,%3};"
        : "+f"(c[0]), "+f"(c[1]), "+f"(c[2]), "+f"(c[3])
        : "r"(a[0]), "r"(a[1]), "r"(a[2]), "r"(a[3]), "r"(b[0]), "r"(b[1]));
}

// ---------------------------------------------------------------------------
// bf16 2-plane / 3-term GEMM. POUT=true: write bf16 hi/lo planes into the
// RESHAPE-VIEW layout (b, h, t, dpair):
//   rr = row % T;  h = rr>>7;  t = ((rr&127)<<4) | (col>>7);  d = col&127
// POUT=false: plain f32 C (K path).
// ---------------------------------------------------------------------------
template<bool POUT>
__global__ void __launch_bounds__(256, 1)
gemm_bf16(const float* __restrict__ A, const float* __restrict__ W,
          const float* __restrict__ bias, float* __restrict__ C,
          uint32_t* __restrict__ Ph, uint32_t* __restrict__ Pl,
          int M, int N, int K)
{
    constexpr int AS = 20;
    constexpr int BS = 132;
    __shared__ uint32_t Ah[128 * AS], Al[128 * AS];
    __shared__ uint32_t Bh[16 * BS],  Bl[16 * BS];

    const int tid = threadIdx.x, lane = tid & 31, warp = tid >> 5;
    const int wm = (warp >> 2) * 64, wn = (warp & 3) * 32;
    const int gid = lane >> 2, tig = lane & 3;
    const int bm = blockIdx.y * 128, bn = blockIdx.x * 128;

    const int la_m = tid >> 1, la_k = (tid & 1) * 16;
    const float* Ap = A + (size_t)(bm + la_m) * K + la_k;
    const float* Bp = W + bn + lane * 4;
    const int kr0 = 2 * warp, kr1 = 2 * warp + 1;
    const int kr2 = 2 * warp + 16, kr3 = 2 * warp + 17;

    float4 ar[4], br[4];
    #pragma unroll
    for (int j = 0; j < 4; j++) ar[j] = *(const float4*)(Ap + 4 * j);
    br[0] = *(const float4*)(Bp + (size_t)kr0 * N);
    br[1] = *(const float4*)(Bp + (size_t)kr1 * N);
    br[2] = *(const float4*)(Bp + (size_t)kr2 * N);
    br[3] = *(const float4*)(Bp + (size_t)kr3 * N);

    float acc[4][4][4];
    #pragma unroll
    for (int i = 0; i < 4; i++)
        #pragma unroll
        for (int j = 0; j < 4; j++)
            #pragma unroll
            for (int c = 0; c < 4; c++) acc[i][j][c] = 0.f;

    for (int kt = 0; kt < K; kt += 32) {
        #pragma unroll
        for (int j = 0; j < 4; j++) {
            float4 x = ar[j];
            float hx = bfhi(x.x), hy = bfhi(x.y), hz = bfhi(x.z), hw = bfhi(x.w);
            uint2 hh = make_uint2(packbf(hx, hy), packbf(hz, hw));
            uint2 ll = make_uint2(packbf(x.x - hx, x.y - hy), packbf(x.z - hz, x.w - hw));
            int off = la_m * AS + (la_k >> 1) + 2 * j;
            *(uint2*)&Ah[off] = hh;
            *(uint2*)&Al[off] = ll;
        }
        {
            uint4 h0, l0, h1, l1;
            #pragma unroll
            for (int e = 0; e < 4; e++) {
                float a0 = ((const float*)&br[0])[e], a1 = ((const float*)&br[1])[e];
                float b0 = ((const float*)&br[2])[e], b1 = ((const float*)&br[3])[e];
                float ha0 = bfhi(a0), ha1 = bfhi(a1), hb0 = bfhi(b0), hb1 = bfhi(b1);
                ((uint32_t*)&h0)[e] = packbf(ha0, ha1);
                ((uint32_t*)&l0)[e] = packbf(a0 - ha0, a1 - ha1);
                ((uint32_t*)&h1)[e] = packbf(hb0, hb1);
                ((uint32_t*)&l1)[e] = packbf(b0 - hb0, b1 - hb1);
            }
            *(uint4*)&Bh[warp * BS + 4 * lane]       = h0;
            *(uint4*)&Bl[warp * BS + 4 * lane]       = l0;
            *(uint4*)&Bh[(warp + 8) * BS + 4 * lane] = h1;
            *(uint4*)&Bl[(warp + 8) * BS + 4 * lane] = l1;
        }
        __syncthreads();

        if (kt + 32 < K) {
            #pragma unroll
            for (int j = 0; j < 4; j++) ar[j] = *(const float4*)(Ap + kt + 32 + 4 * j);
            br[0] = *(const float4*)(Bp + (size_t)(kt + 32 + kr0) * N);
            br[1] = *(const float4*)(Bp + (size_t)(kt + 32 + kr1) * N);
            br[2] = *(const float4*)(Bp + (size_t)(kt + 32 + kr2) * N);
            br[3] = *(const float4*)(Bp + (size_t)(kt + 32 + kr3) * N);
        }

        #pragma unroll
        for (int s = 0; s < 2; s++) {
            const int s8 = s * 8;
            uint32_t ah[4][4], al[4][4];
            #pragma unroll
            for (int i = 0; i < 4; i++) {
                const int r0 = (wm + i * 16 + gid) * AS + s8;
                const int r1 = r0 + 8 * AS;
                ah[i][0] = Ah[r0 + tig];     ah[i][1] = Ah[r1 + tig];
                ah[i][2] = Ah[r0 + tig + 4]; ah[i][3] = Ah[r1 + tig + 4];
                al[i][0] = Al[r0 + tig];     al[i][1] = Al[r1 + tig];
                al[i][2] = Al[r0 + tig + 4]; al[i][3] = Al[r1 + tig + 4];
            }
            #pragma unroll
            for (int j = 0; j < 4; j++) {
                const int cb = wn + j * 8 + gid;
                uint32_t bh[2] = {Bh[(s8 + tig) * BS + cb], Bh[(s8 + tig + 4) * BS + cb]};
                uint32_t bl[2] = {Bl[(s8 + tig) * BS + cb], Bl[(s8 + tig + 4) * BS + cb]};
                #pragma unroll
                for (int i = 0; i < 4; i++) {
                    mma_bf16(acc[i][j], ah[i], bh);
                    mma_bf16(acc[i][j], ah[i], bl);
                    mma_bf16(acc[i][j], al[i], bh);
                }
            }
        }
        __syncthreads();
    }

    #pragma unroll
    for (int j = 0; j < 4; j++) {
        const int col = bn + wn + j * 8 + tig * 2;
        const float b0 = bias[col], b1 = bias[col + 1];
        #pragma unroll
        for (int i = 0; i < 4; i++) {
            const int row0 = bm + wm + i * 16 + gid;
            if (POUT) {
                // Reshape-view mapping: flat = rr*E + col within batch,
                // h = rr>>7, t = ((rr&127)<<4)|(col>>7), dpair = (col&127)>>1.
                const int dp = (col & 127) >> 1;
                #pragma unroll
                for (int half = 0; half < 2; half++) {
                    const int row = row0 + 8 * half;
                    const float v0 = acc[i][j][2 * half]     + b0;
                    const float v1 = acc[i][j][2 * half + 1] + b1;
                    const float h0 = bfhi(v0), h1 = bfhi(v1);
                    const int bb = row >> 11;
                    const int rr = row & (T_ - 1);
                    const int hh = rr >> 7;
                    const int t  = ((rr & 127) << 4) | (col >> 7);
                    const size_t o = ((size_t)(bb * NH_ + hh) * T_ + t) * 64 + dp;
                    Ph[o] = packbf(h0, h1);
                    Pl[o] = packbf(v0 - h0, v1 - h1);
                }
            } else {
                *(float2*)&C[(size_t)row0 * N + col]       = make_float2(acc[i][j][0] + b0, acc[i][j][1] + b1);
                *(float2*)&C[(size_t)(row0 + 8) * N + col] = make_float2(acc[i][j][2] + b0, acc[i][j][3] + b1);
            }
        }
    }
}

// ---------------- 1xTF32 GEMM (V/O projections, proven) ----------------
__global__ void __launch_bounds__(256, 1)
gemm_tf32(const float* __restrict__ A, const float* __restrict__ W,
          const float* __restrict__ bias, float* __restrict__ C,
          int M, int N, int K)
{
    constexpr int ASd = 36, BSd = 136;
    __shared__ float As[128 * ASd];
    __shared__ float Bs[32 * BSd];

    const int tid = threadIdx.x, lane = tid & 31, warp = tid >> 5;
    const int wm = (warp >> 2) * 64, wn = (warp & 3) * 32;
    const int gid = lane >> 2, tig = lane & 3;
    const int bm = blockIdx.y * 128, bn = blockIdx.x * 128;
    const int la_m = tid >> 1, la_k = (tid & 1) * 16;
    const float* Ap = A + (size_t)(bm + la_m) * K + la_k;
    const float* Bp = W + (size_t)warp * N + bn + lane * 4;

    float4 ar[4], br[4];
    #pragma unroll
    for (int j = 0; j < 4; j++) ar[j] = *(const float4*)(Ap + 4 * j);
    #pragma unroll
    for (int j = 0; j < 4; j++) br[j] = *(const float4*)(Bp + (size_t)(8 * j) * N);

    float acc[4][4][4];
    #pragma unroll
    for (int i = 0; i < 4; i++)
        #pragma unroll
        for (int j = 0; j < 4; j++)
            #pragma unroll
            for (int c = 0; c < 4; c++) acc[i][j][c] = 0.f;

    for (int kt = 0; kt < K; kt += 32) {
        #pragma unroll
        for (int j = 0; j < 4; j++)
            *(float4*)&As[la_m * ASd + la_k + 4 * j] = ar[j];
        #pragma unroll
        for (int j = 0; j < 4; j++)
            *(float4*)&Bs[(warp + 8 * j) * BSd + lane * 4] = br[j];
        __syncthreads();

        if (kt + 32 < K) {
            #pragma unroll
            for (int j = 0; j < 4; j++) ar[j] = *(const float4*)(Ap + kt + 32 + 4 * j);
            #pragma unroll
            for (int j = 0; j < 4; j++) br[j] = *(const float4*)(Bp + (size_t)(kt + 32 + 8 * j) * N);
        }

        #pragma unroll
        for (int s = 0; s < 4; s++) {
            const int ks = s * 8;
            uint32_t ah[4][4];
            #pragma unroll
            for (int i = 0; i < 4; i++) {
                const int rb = wm + i * 16;
                ah[i][0] = f2tf(As[(rb + gid)     * ASd + ks + tig]);
                ah[i][1] = f2tf(As[(rb + gid + 8) * ASd + ks + tig]);
                ah[i][2] = f2tf(As[(rb + gid)     * ASd + ks + tig + 4]);
                ah[i][3] = f2tf(As[(rb + gid + 8) * ASd + ks + tig + 4]);
            }
            #pragma unroll
            for (int j = 0; j < 4; j++) {
                const int cb = wn + j * 8;
                uint32_t bh[2];
                bh[0] = f2tf(Bs[(ks + tig)     * BSd + cb + gid]);
                bh[1] = f2tf(Bs[(ks + tig + 4) * BSd + cb + gid]);
                #pragma unroll
                for (int i = 0; i < 4; i++) mma_tf32(acc[i][j], ah[i], bh);
            }
        }
        __syncthreads();
    }

    #pragma unroll
    for (int j = 0; j < 4; j++) {
        const int col = bn + wn + j * 8 + tig * 2;
        const float b0 = bias[col], b1 = bias[col + 1];
        #pragma unroll
        for (int i = 0; i < 4; i++) {
            const int row = bm + wm + i * 16 + gid;
            *(float2*)&C[(size_t)row * N + col]       = make_float2(acc[i][j][0] + b0, acc[i][j][1] + b1);
            *(float2*)&C[(size_t)(row + 8) * N + col] = make_float2(acc[i][j][2] + b0, acc[i][j][3] + b1);
        }
    }
}

// ---------------- RoPE + operand prep: K -> bf16 planes, V -> tf32 bits ----
__global__ void rope_split(const float* __restrict__ k, const float* __restrict__ v,
                           uint32_t* __restrict__ kh, uint32_t* __restrict__ kl,
                           uint32_t* __restrict__ vt)
{
    int p = blockIdx.x * 256 + threadIdx.x;
    int d2 = p & 63, rr = p >> 6, t = rr & (T_ - 1);
    double th = exp2((double)d2 * -0.20762050593046014);
    float angf = (float)t * (float)th;
    float s, c;
    sincosf(angf, &s, &c);
    size_t base = (size_t)rr * HD_ + 2 * d2;
    float2 kk = *(const float2*)(k + base), vv = *(const float2*)(v + base);
    float kx = kk.x * c - kk.y * s, ky = kk.x * s + kk.y * c;
    float vx = vv.x * c - vv.y * s, vy = vv.x * s + vv.y * c;
    float hx = bfhi(kx), hy = bfhi(ky);
    kh[(size_t)rr * 64 + d2] = packbf(hx, hy);
    kl[(size_t)rr * 64 + d2] = packbf(kx - hx, ky - hy);
    *(uint2*)(vt + (size_t)rr * 128 + 2 * d2) = make_uint2(f2tf(vx), f2tf(vy));
}

// ---------------- Tensor-core flash attention (pre-split operands) --------
constexpr int BST = 68;
constexpr int VST = 132;

__global__ void __launch_bounds__(256, 2)
flash_mma(const uint32_t* __restrict__ Qh, const uint32_t* __restrict__ Ql,
          const uint32_t* __restrict__ Kh, const uint32_t* __restrict__ Kl,
          const uint32_t* __restrict__ Vt, const int* __restrict__ mask,
          float* __restrict__ O)
{
    extern __shared__ uint32_t s4[];
    uint32_t* sQh = s4;
    uint32_t* sQl = sQh + 64 * BST;
    uint32_t* sKh = sQl + 64 * BST;
    uint32_t* sKl = sKh + 64 * BST;   // aliased by Ps after the S phase
    uint32_t* sPs = sKl;
    uint32_t* sVs = sKl + 64 * BST;
    float*    pmx = (float*)(sVs + 64 * VST);  // [2][64]

    const int tid = threadIdx.x, lane = tid & 31, warp = tid >> 5;
    const int rg = warp & 3, cg = warp >> 2;
    const int gid = lane >> 2, tig = lane & 3;
    const int q0 = blockIdx.x * 64, h = blockIdx.y, b = blockIdx.z;
    const int kh = h & (NKV_ - 1);
    const int lr = rg * 16 + gid;

    const uint32_t* qhb = Qh + ((size_t)b * NH_  + h ) * ((size_t)T_ * 64) + (size_t)q0 * 64;
    const uint32_t* qlb = Ql + ((size_t)b * NH_  + h ) * ((size_t)T_ * 64) + (size_t)q0 * 64;
    const uint32_t* khb = Kh + ((size_t)b * NKV_ + kh) * ((size_t)T_ * 64);
    const uint32_t* klb = Kl + ((size_t)b * NKV_ + kh) * ((size_t)T_ * 64);
    const uint32_t* vtb = Vt + ((size_t)b * NKV_ + kh) * ((size_t)T_ * 128);
    const int*      mb  = mask + (size_t)b * T_ * T_;

    // Q planes: pure copy
    #pragma unroll
    for (int i = 0; i < 4; i++) {
        int idx = i * 256 + tid;
        int r = idx >> 4, c = (idx & 15) * 4;
        *(uint4*)&sQh[r * BST + c] = *(const uint4*)(qhb + r * 64 + c);
        *(uint4*)&sQl[r * BST + c] = *(const uint4*)(qlb + r * 64 + c);
    }

    float m0 = -1e30f, m1 = -1e30f, l0 = 0.f, l1 = 0.f;
    float oacc[8][4];
    #pragma unroll
    for (int j = 0; j < 8; j++)
        #pragma unroll
        for (int c = 0; c < 4; c++) oacc[j][c] = 0.f;

    for (int k0 = 0; k0 < T_; k0 += 64) {
        // mask prefetch (latency covered by barrier + copies + S-mma)
        int2 mq0[4], mq1[4];
        #pragma unroll
        for (int j = 0; j < 4; j++) {
            const int col = k0 + cg * 32 + j * 8 + 2 * tig;
            mq0[j] = *(const int2*)(mb + (size_t)(q0 + lr)     * T_ + col);
            mq1[j] = *(const int2*)(mb + (size_t)(q0 + lr + 8) * T_ + col);
        }
        __syncthreads();   // prior PV reads of Ps/Vs done
        // K planes + V: pure copies
        #pragma unroll
        for (int i = 0; i < 4; i++) {
            int idx = i * 256 + tid;
            int r = idx >> 4, c = (idx & 15) * 4;
            uint4 xh = *(const uint4*)(khb + (size_t)(k0 + r) * 64 + c);
            uint4 xl = *(const uint4*)(klb + (size_t)(k0 + r) * 64 + c);
            *(uint4*)&sKh[r * BST + c] = xh;
            *(uint4*)&sKl[r * BST + c] = xl;
        }
        #pragma unroll
        for (int i = 0; i < 8; i++) {
            int idx = i * 256 + tid;
            int r = idx >> 5, c = (idx & 31) * 4;
            *(uint4*)&sVs[r * VST + c] = *(const uint4*)(vtb + (size_t)(k0 + r) * 128 + c);
        }
        __syncthreads();

        // S = Q K^T (bf16 3-term)
        float sacc[4][4];
        #pragma unroll
        for (int j = 0; j < 4; j++)
            #pragma unroll
            for (int c = 0; c < 4; c++) sacc[j][c] = 0.f;

        #pragma unroll
        for (int s = 0; s < 8; s++) {
            const int qa = lr * BST + 8 * s;
            uint32_t ah[4] = {sQh[qa + tig], sQh[qa + 8 * BST + tig],
                              sQh[qa + tig + 4], sQh[qa + 8 * BST + tig + 4]};
            uint32_t al[4] = {sQl[qa + tig], sQl[qa + 8 * BST + tig],
                              sQl[qa + tig + 4], sQl[qa + 8 * BST + tig + 4]};
            #pragma unroll
            for (int j = 0; j < 4; j++) {
                const int kbase = (cg * 32 + j * 8 + gid) * BST + 8 * s;
                uint32_t bh[2] = {sKh[kbase + tig], sKh[kbase + tig + 4]};
                uint32_t bl[2] = {sKl[kbase + tig], sKl[kbase + tig + 4]};
                mma_bf16(sacc[j], ah, bh);
                mma_bf16(sacc[j], ah, bl);
                mma_bf16(sacc[j], al, bh);
            }
        }

        float mx0 = -1e30f, mx1 = -1e30f;
        #pragma unroll
        for (int j = 0; j < 4; j++) {
            sacc[j][0] = mq0[j].x ? sacc[j][0] * SCL2_ : MSK2_;
            sacc[j][1] = mq0[j].y ? sacc[j][1] * SCL2_ : MSK2_;
            sacc[j][2] = mq1[j].x ? sacc[j][2] * SCL2_ : MSK2_;
            sacc[j][3] = mq1[j].y ? sacc[j][3] * SCL2_ : MSK2_;
            mx0 = fmaxf(mx0, fmaxf(sacc[j][0], sacc[j][1]));
            mx1 = fmaxf(mx1, fmaxf(sacc[j][2], sacc[j][3]));
        }
        mx0 = fmaxf(mx0, __shfl_xor_sync(0xffffffffu, mx0, 1));
        mx0 = fmaxf(mx0, __shfl_xor_sync(0xffffffffu, mx0, 2));
        mx1 = fmaxf(mx1, __shfl_xor_sync(0xffffffffu, mx1, 1));
        mx1 = fmaxf(mx1, __shfl_xor_sync(0xffffffffu, mx1, 2));
        if (tig == 0) { pmx[cg * 64 + lr] = mx0; pmx[cg * 64 + lr + 8] = mx1; }
        __syncthreads();   // full: pmx exchange AND sKl->sPs alias guard

        float mn0 = fmaxf(m0, fmaxf(pmx[lr],     pmx[64 + lr]));
        float mn1 = fmaxf(m1, fmaxf(pmx[lr + 8], pmx[64 + lr + 8]));
        float a0 = ex2f(m0 - mn0), a1 = ex2f(m1 - mn1);
        m0 = mn0; m1 = mn1;

        float sum0 = 0.f, sum1 = 0.f;
        #pragma unroll
        for (int j = 0; j < 4; j++) {
            float p0 = ex2f(sacc[j][0] - mn0), p1 = ex2f(sacc[j][1] - mn0);
            float p2 = ex2f(sacc[j][2] - mn1), p3 = ex2f(sacc[j][3] - mn1);
            sum0 += p0 + p1; sum1 += p2 + p3;
            const int pc = cg * 32 + j * 8 + 2 * tig;
            sPs[lr * BST + pc]           = f2tf(p0);
            sPs[lr * BST + pc + 1]       = f2tf(p1);
            sPs[(lr + 8) * BST + pc]     = f2tf(p2);
            sPs[(lr + 8) * BST + pc + 1] = f2tf(p3);
        }
        sum0 += __shfl_xor_sync(0xffffffffu, sum0, 1);
        sum0 += __shfl_xor_sync(0xffffffffu, sum0, 2);
        sum1 += __shfl_xor_sync(0xffffffffu, sum1, 1);
        sum1 += __shfl_xor_sync(0xffffffffu, sum1, 2);
        l0 = l0 * a0 + sum0;
        l1 = l1 * a1 + sum1;
        #pragma unroll
        for (int j = 0; j < 8; j++) {
            oacc[j][0] *= a0; oacc[j][1] *= a0;
            oacc[j][2] *= a1; oacc[j][3] *= a1;
        }
        asm volatile("bar.sync %0, 64;" :: "r"(rg + 1) : "memory");

        // O += P V (1xTF32)
        #pragma unroll
        for (int s = 0; s < 8; s++) {
            const int pa0 = lr * BST + 8 * s, pa1 = (lr + 8) * BST + 8 * s;
            uint32_t pa[4] = {sPs[pa0 + tig], sPs[pa1 + tig],
                              sPs[pa0 + tig + 4], sPs[pa1 + tig + 4]};
            #pragma unroll
            for (int j = 0; j < 8; j++) {
                const int vn = cg * 64 + j * 8 + gid;
                uint32_t vbf[2] = {sVs[(8 * s + tig) * VST + vn],
                                   sVs[(8 * s + tig + 4) * VST + vn]};
                mma_tf32(oacc[j], pa, vbf);
            }
        }
    }

    asm volatile("bar.sync %0, 64;" :: "r"(rg + 1) : "memory");
    if (tig == 0) { pmx[cg * 64 + lr] = l0; pmx[cg * 64 + lr + 8] = l1; }
    asm volatile("bar.sync %0, 64;" :: "r"(rg + 1) : "memory");
    const float inv0 = 1.f / (pmx[lr] + pmx[64 + lr]);
    const float inv1 = 1.f / (pmx[lr + 8] + pmx[64 + lr + 8]);
    float* ob = O + ((size_t)b * T_ + q0 + lr) * E_ + h * HD_ + cg * 64 + 2 * tig;
    #pragma unroll
    for (int j = 0; j < 8; j++) {
        *(float2*)(ob + j * 8)                  = make_float2(oacc[j][0] * inv0, oacc[j][1] * inv0);
        *(float2*)(ob + 8 * (size_t)E_ + j * 8) = make_float2(oacc[j][2] * inv1, oacc[j][3] * inv1);
    }
}

// ---------------- launcher ----------------
extern "C" void kernel_launch(void* const* d_in, const int* in_sizes, int n_in,
                              void* d_out, int out_size)
{
    const float* x  = (const float*)d_in[0];
    const int*   am = (const int*)  d_in[1];
    const float* Wq = (const float*)d_in[2];
    const float* bq = (const float*)d_in[3];
    const float* Wk = (const float*)d_in[4];
    const float* bk = (const float*)d_in[5];
    const float* Wv = (const float*)d_in[6];
    const float* bv = (const float*)d_in[7];
    const float* Wo = (const float*)d_in[8];
    const float* bo = (const float*)d_in[9];
    float* out = (float*)d_out;

    float *q, *k, *v, *att;
    uint32_t *qh, *ql, *kh, *kl, *vt;
    cudaGetSymbolAddress((void**)&q,   g_q);
    cudaGetSymbolAddress((void**)&k,   g_k);
    cudaGetSymbolAddress((void**)&v,   g_v);
    cudaGetSymbolAddress((void**)&att, g_att);
    cudaGetSymbolAddress((void**)&qh,  g_qh);
    cudaGetSymbolAddress((void**)&ql,  g_ql);
    cudaGetSymbolAddress((void**)&kh,  g_kh);
    cudaGetSymbolAddress((void**)&kl,  g_kl);
    cudaGetSymbolAddress((void**)&vt,  g_vt);

    const int M = B_ * T_;

    gemm_bf16<true ><<<dim3(E_ / 128,   M / 128), 256>>>(x, Wq, bq, q, qh, ql, M, E_,   E_);
    gemm_bf16<false><<<dim3(KVD_ / 128, M / 128), 256>>>(x, Wk, bk, k, qh, ql, M, KVD_, E_);
    gemm_tf32<<<dim3(KVD_ / 128, M / 128), 256>>>(x, Wv, bv, v, M, KVD_, E_);

    rope_split<<<(B_ * NKV_ * T_ * 64) / 256, 256>>>(k, v, kh, kl, vt);

    const int fsmem = (4 * 64 * BST + 64 * VST + 128) * 4;  // 103936 B
    cudaFuncSetAttribute(flash_mma, cudaFuncAttributeMaxDynamicSharedMemorySize, fsmem);
    flash_mma<<<dim3(T_ / 64, NH_, B_), 256, fsmem>>>(qh, ql, kh, kl, vt, am, att);

    gemm_tf32<<<dim3(E_ / 128, M / 128), 256>>>(att, Wo, bo, out, M, E_, E_);
}

// round 14
// speedup vs baseline: 3.6979x; 1.1502x over previous
#include <cuda_runtime.h>
#include <cuda_bf16.h>
#include <cuda_fp16.h>
#include <math.h>
#include <stdint.h>

constexpr int B_   = 4;
constexpr int T_   = 2048;
constexpr int E_   = 2048;
constexpr int NH_  = 16;
constexpr int NKV_ = 4;
constexpr int HD_  = 128;
constexpr int KVD_ = NKV_ * HD_;
constexpr float SCL2_ = 16.32232319089277f;     // sqrt(128) * log2(e)
constexpr float MSK2_ = 1.4426950408889634e-9f; // 1e-9 * log2(e)

__device__ float g_k[(size_t)B_ * T_ * KVD_];          // f32 K (rope input)
__device__ float g_v[(size_t)B_ * T_ * KVD_];          // f32 V (rope input)
__device__ float g_att[(size_t)B_ * T_ * E_];
__device__ uint32_t g_qh[(size_t)B_ * NH_  * T_ * 64]; // Q bf16-pair hi plane (view layout)
__device__ uint32_t g_ql[(size_t)B_ * NH_  * T_ * 64]; // Q lo plane
__device__ uint32_t g_kh[(size_t)B_ * NKV_ * T_ * 64]; // K hi plane (post-rope)
__device__ uint32_t g_kl[(size_t)B_ * NKV_ * T_ * 64]; // K lo plane
__device__ uint32_t g_vt[(size_t)B_ * NKV_ * T_ * 64]; // V fp16x2 (d-pairs, post-rope)

// ---------------- helpers ----------------
__device__ __forceinline__ float bfhi(float f) {
    return __bfloat162float(__float2bfloat16(f));
}
__device__ __forceinline__ uint32_t packbf(float f0, float f1) {
    __nv_bfloat162 h = __floats2bfloat162_rn(f0, f1);
    return *(uint32_t*)&h;
}
__device__ __forceinline__ uint32_t packh(float f0, float f1) {
    __half2 h = __floats2half2_rn(f0, f1);
    return *(uint32_t*)&h;
}
__device__ __forceinline__ float ex2f(float x) {
    float r; asm("ex2.approx.f32 %0, %1;" : "=f"(r) : "f"(x)); return r;
}
__device__ __forceinline__ void mma_bf16(float c[4], const uint32_t a[4], const uint32_t b[2]) {
    asm volatile("mma.sync.aligned.m16n8k16.row.col.f32.bf16.bf16.f32 "
        "{%0,%1,%2,%3}, {%4,%5,%6,%7}, {%8,%9}, {%0,%1,%2,%3};"
        : "+f"(c[0]), "+f"(c[1]), "+f"(c[2]), "+f"(c[3])
        : "r"(a[0]), "r"(a[1]), "r"(a[2]), "r"(a[3]), "r"(b[0]), "r"(b[1]));
}
__device__ __forceinline__ void mma_fp16(float c[4], const uint32_t a[4], const uint32_t b[2]) {
    asm volatile("mma.sync.aligned.m16n8k16.row.col.f32.f16.f16.f32 "
        "{%0,%1,%2,%3}, {%4,%5,%6,%7}, {%8,%9}, {%0,%1,%2,%3};"
        : "+f"(c[0]), "+f"(c[1]), "+f"(c[2]), "+f"(c[3])
        : "r"(a[0]), "r"(a[1]), "r"(a[2]), "r"(a[3]), "r"(b[0]), "r"(b[1]));
}

// ---------------------------------------------------------------------------
// bf16 2-plane / 3-term GEMM (Q/K projections). POUT=true: write bf16 hi/lo
// planes into the RESHAPE-VIEW layout (b,h,t,dpair):
//   rr = row % T;  h = rr>>7;  t = ((rr&127)<<4)|(col>>7);  d = col&127
// ---------------------------------------------------------------------------
template<bool POUT>
__global__ void __launch_bounds__(256, 1)
gemm_bf16(const float* __restrict__ A, const float* __restrict__ W,
          const float* __restrict__ bias, float* __restrict__ C,
          uint32_t* __restrict__ Ph, uint32_t* __restrict__ Pl,
          int M, int N, int K)
{
    constexpr int AS = 20;
    constexpr int BS = 132;
    __shared__ uint32_t Ah[128 * AS], Al[128 * AS];
    __shared__ uint32_t Bh[16 * BS],  Bl[16 * BS];

    const int tid = threadIdx.x, lane = tid & 31, warp = tid >> 5;
    const int wm = (warp >> 2) * 64, wn = (warp & 3) * 32;
    const int gid = lane >> 2, tig = lane & 3;
    const int bm = blockIdx.y * 128, bn = blockIdx.x * 128;

    const int la_m = tid >> 1, la_k = (tid & 1) * 16;
    const float* Ap = A + (size_t)(bm + la_m) * K + la_k;
    const float* Bp = W + bn + lane * 4;
    const int kr0 = 2 * warp, kr1 = 2 * warp + 1;
    const int kr2 = 2 * warp + 16, kr3 = 2 * warp + 17;

    float4 ar[4], br[4];
    #pragma unroll
    for (int j = 0; j < 4; j++) ar[j] = *(const float4*)(Ap + 4 * j);
    br[0] = *(const float4*)(Bp + (size_t)kr0 * N);
    br[1] = *(const float4*)(Bp + (size_t)kr1 * N);
    br[2] = *(const float4*)(Bp + (size_t)kr2 * N);
    br[3] = *(const float4*)(Bp + (size_t)kr3 * N);

    float acc[4][4][4];
    #pragma unroll
    for (int i = 0; i < 4; i++)
        #pragma unroll
        for (int j = 0; j < 4; j++)
            #pragma unroll
            for (int c = 0; c < 4; c++) acc[i][j][c] = 0.f;

    for (int kt = 0; kt < K; kt += 32) {
        #pragma unroll
        for (int j = 0; j < 4; j++) {
            float4 x = ar[j];
            float hx = bfhi(x.x), hy = bfhi(x.y), hz = bfhi(x.z), hw = bfhi(x.w);
            uint2 hh = make_uint2(packbf(hx, hy), packbf(hz, hw));
            uint2 ll = make_uint2(packbf(x.x - hx, x.y - hy), packbf(x.z - hz, x.w - hw));
            int off = la_m * AS + (la_k >> 1) + 2 * j;
            *(uint2*)&Ah[off] = hh;
            *(uint2*)&Al[off] = ll;
        }
        {
            uint4 h0, l0, h1, l1;
            #pragma unroll
            for (int e = 0; e < 4; e++) {
                float a0 = ((const float*)&br[0])[e], a1 = ((const float*)&br[1])[e];
                float b0 = ((const float*)&br[2])[e], b1 = ((const float*)&br[3])[e];
                float ha0 = bfhi(a0), ha1 = bfhi(a1), hb0 = bfhi(b0), hb1 = bfhi(b1);
                ((uint32_t*)&h0)[e] = packbf(ha0, ha1);
                ((uint32_t*)&l0)[e] = packbf(a0 - ha0, a1 - ha1);
                ((uint32_t*)&h1)[e] = packbf(hb0, hb1);
                ((uint32_t*)&l1)[e] = packbf(b0 - hb0, b1 - hb1);
            }
            *(uint4*)&Bh[warp * BS + 4 * lane]       = h0;
            *(uint4*)&Bl[warp * BS + 4 * lane]       = l0;
            *(uint4*)&Bh[(warp + 8) * BS + 4 * lane] = h1;
            *(uint4*)&Bl[(warp + 8) * BS + 4 * lane] = l1;
        }
        __syncthreads();

        if (kt + 32 < K) {
            #pragma unroll
            for (int j = 0; j < 4; j++) ar[j] = *(const float4*)(Ap + kt + 32 + 4 * j);
            br[0] = *(const float4*)(Bp + (size_t)(kt + 32 + kr0) * N);
            br[1] = *(const float4*)(Bp + (size_t)(kt + 32 + kr1) * N);
            br[2] = *(const float4*)(Bp + (size_t)(kt + 32 + kr2) * N);
            br[3] = *(const float4*)(Bp + (size_t)(kt + 32 + kr3) * N);
        }

        #pragma unroll
        for (int s = 0; s < 2; s++) {
            const int s8 = s * 8;
            uint32_t ah[4][4], al[4][4];
            #pragma unroll
            for (int i = 0; i < 4; i++) {
                const int r0 = (wm + i * 16 + gid) * AS + s8;
                const int r1 = r0 + 8 * AS;
                ah[i][0] = Ah[r0 + tig];     ah[i][1] = Ah[r1 + tig];
                ah[i][2] = Ah[r0 + tig + 4]; ah[i][3] = Ah[r1 + tig + 4];
                al[i][0] = Al[r0 + tig];     al[i][1] = Al[r1 + tig];
                al[i][2] = Al[r0 + tig + 4]; al[i][3] = Al[r1 + tig + 4];
            }
            #pragma unroll
            for (int j = 0; j < 4; j++) {
                const int cb = wn + j * 8 + gid;
                uint32_t bh[2] = {Bh[(s8 + tig) * BS + cb], Bh[(s8 + tig + 4) * BS + cb]};
                uint32_t bl[2] = {Bl[(s8 + tig) * BS + cb], Bl[(s8 + tig + 4) * BS + cb]};
                #pragma unroll
                for (int i = 0; i < 4; i++) {
                    mma_bf16(acc[i][j], ah[i], bh);
                    mma_bf16(acc[i][j], ah[i], bl);
                    mma_bf16(acc[i][j], al[i], bh);
                }
            }
        }
        __syncthreads();
    }

    #pragma unroll
    for (int j = 0; j < 4; j++) {
        const int col = bn + wn + j * 8 + tig * 2;
        const float b0 = bias[col], b1 = bias[col + 1];
        #pragma unroll
        for (int i = 0; i < 4; i++) {
            const int row0 = bm + wm + i * 16 + gid;
            if (POUT) {
                const int dp = (col & 127) >> 1;
                #pragma unroll
                for (int half = 0; half < 2; half++) {
                    const int row = row0 + 8 * half;
                    const float v0 = acc[i][j][2 * half]     + b0;
                    const float v1 = acc[i][j][2 * half + 1] + b1;
                    const float h0 = bfhi(v0), h1 = bfhi(v1);
                    const int bb = row >> 11;
                    const int rr = row & (T_ - 1);
                    const int hh = rr >> 7;
                    const int t  = ((rr & 127) << 4) | (col >> 7);
                    const size_t o = ((size_t)(bb * NH_ + hh) * T_ + t) * 64 + dp;
                    Ph[o] = packbf(h0, h1);
                    Pl[o] = packbf(v0 - h0, v1 - h1);
                }
            } else {
                *(float2*)&C[(size_t)row0 * N + col]       = make_float2(acc[i][j][0] + b0, acc[i][j][1] + b1);
                *(float2*)&C[(size_t)(row0 + 8) * N + col] = make_float2(acc[i][j][2] + b0, acc[i][j][3] + b1);
            }
        }
    }
}

// ---------------------------------------------------------------------------
// fp16 single-plane GEMM (V/O projections). Same precision class as 1xTF32
// (10+1 mantissa bits) but k16 -> half the mma instructions.
// ---------------------------------------------------------------------------
__global__ void __launch_bounds__(256, 1)
gemm_fp16(const float* __restrict__ A, const float* __restrict__ W,
          const float* __restrict__ bias, float* __restrict__ C,
          int M, int N, int K)
{
    constexpr int AS = 20;
    constexpr int BS = 132;
    __shared__ uint32_t Ah[128 * AS];
    __shared__ uint32_t Bh[16 * BS];

    const int tid = threadIdx.x, lane = tid & 31, warp = tid >> 5;
    const int wm = (warp >> 2) * 64, wn = (warp & 3) * 32;
    const int gid = lane >> 2, tig = lane & 3;
    const int bm = blockIdx.y * 128, bn = blockIdx.x * 128;

    const int la_m = tid >> 1, la_k = (tid & 1) * 16;
    const float* Ap = A + (size_t)(bm + la_m) * K + la_k;
    const float* Bp = W + bn + lane * 4;
    const int kr0 = 2 * warp, kr1 = 2 * warp + 1;
    const int kr2 = 2 * warp + 16, kr3 = 2 * warp + 17;

    float4 ar[4], br[4];
    #pragma unroll
    for (int j = 0; j < 4; j++) ar[j] = *(const float4*)(Ap + 4 * j);
    br[0] = *(const float4*)(Bp + (size_t)kr0 * N);
    br[1] = *(const float4*)(Bp + (size_t)kr1 * N);
    br[2] = *(const float4*)(Bp + (size_t)kr2 * N);
    br[3] = *(const float4*)(Bp + (size_t)kr3 * N);

    float acc[4][4][4];
    #pragma unroll
    for (int i = 0; i < 4; i++)
        #pragma unroll
        for (int j = 0; j < 4; j++)
            #pragma unroll
            for (int c = 0; c < 4; c++) acc[i][j][c] = 0.f;

    for (int kt = 0; kt < K; kt += 32) {
        #pragma unroll
        for (int j = 0; j < 4; j++) {
            float4 x = ar[j];
            uint2 hh = make_uint2(packh(x.x, x.y), packh(x.z, x.w));
            *(uint2*)&Ah[la_m * AS + (la_k >> 1) + 2 * j] = hh;
        }
        {
            uint4 h0, h1;
            #pragma unroll
            for (int e = 0; e < 4; e++) {
                ((uint32_t*)&h0)[e] = packh(((const float*)&br[0])[e], ((const float*)&br[1])[e]);
                ((uint32_t*)&h1)[e] = packh(((const float*)&br[2])[e], ((const float*)&br[3])[e]);
            }
            *(uint4*)&Bh[warp * BS + 4 * lane]       = h0;
            *(uint4*)&Bh[(warp + 8) * BS + 4 * lane] = h1;
        }
        __syncthreads();

        if (kt + 32 < K) {
            #pragma unroll
            for (int j = 0; j < 4; j++) ar[j] = *(const float4*)(Ap + kt + 32 + 4 * j);
            br[0] = *(const float4*)(Bp + (size_t)(kt + 32 + kr0) * N);
            br[1] = *(const float4*)(Bp + (size_t)(kt + 32 + kr1) * N);
            br[2] = *(const float4*)(Bp + (size_t)(kt + 32 + kr2) * N);
            br[3] = *(const float4*)(Bp + (size_t)(kt + 32 + kr3) * N);
        }

        #pragma unroll
        for (int s = 0; s < 2; s++) {
            const int s8 = s * 8;
            uint32_t ah[4][4];
            #pragma unroll
            for (int i = 0; i < 4; i++) {
                const int r0 = (wm + i * 16 + gid) * AS + s8;
                const int r1 = r0 + 8 * AS;
                ah[i][0] = Ah[r0 + tig];     ah[i][1] = Ah[r1 + tig];
                ah[i][2] = Ah[r0 + tig + 4]; ah[i][3] = Ah[r1 + tig + 4];
            }
            #pragma unroll
            for (int j = 0; j < 4; j++) {
                const int cb = wn + j * 8 + gid;
                uint32_t bh[2] = {Bh[(s8 + tig) * BS + cb], Bh[(s8 + tig + 4) * BS + cb]};
                #pragma unroll
                for (int i = 0; i < 4; i++) mma_fp16(acc[i][j], ah[i], bh);
            }
        }
        __syncthreads();
    }

    #pragma unroll
    for (int j = 0; j < 4; j++) {
        const int col = bn + wn + j * 8 + tig * 2;
        const float b0 = bias[col], b1 = bias[col + 1];
        #pragma unroll
        for (int i = 0; i < 4; i++) {
            const int row = bm + wm + i * 16 + gid;
            *(float2*)&C[(size_t)row * N + col]       = make_float2(acc[i][j][0] + b0, acc[i][j][1] + b1);
            *(float2*)&C[(size_t)(row + 8) * N + col] = make_float2(acc[i][j][2] + b0, acc[i][j][3] + b1);
        }
    }
}

// ---------------- RoPE + operand prep: K -> bf16 planes, V -> fp16x2 ------
__global__ void rope_split(const float* __restrict__ k, const float* __restrict__ v,
                           uint32_t* __restrict__ kh, uint32_t* __restrict__ kl,
                           uint32_t* __restrict__ vt)
{
    int p = blockIdx.x * 256 + threadIdx.x;
    int d2 = p & 63, rr = p >> 6, t = rr & (T_ - 1);
    double th = exp2((double)d2 * -0.20762050593046014);
    float angf = (float)t * (float)th;
    float s, c;
    sincosf(angf, &s, &c);
    size_t base = (size_t)rr * HD_ + 2 * d2;
    float2 kk = *(const float2*)(k + base), vv = *(const float2*)(v + base);
    float kx = kk.x * c - kk.y * s, ky = kk.x * s + kk.y * c;
    float vx = vv.x * c - vv.y * s, vy = vv.x * s + vv.y * c;
    float hx = bfhi(kx), hy = bfhi(ky);
    kh[(size_t)rr * 64 + d2] = packbf(hx, hy);
    kl[(size_t)rr * 64 + d2] = packbf(kx - hx, ky - hy);
    vt[(size_t)rr * 64 + d2] = packh(vx, vy);
}

// ---------------- Tensor-core flash attention ----------------
// S: bf16 3-term m16n8k16 (unchanged). PV: fp16 m16n8k16 (P/V fp16, 2^-11).
constexpr int BST = 68;   // Q/K plane row stride (u32)
constexpr int VST = 132;  // V token-pair row stride (u32): 128 d + pad
constexpr int PST = 36;   // Ps row stride (u32): 32 token-pairs + pad

__global__ void __launch_bounds__(256, 2)
flash_mma(const uint32_t* __restrict__ Qh, const uint32_t* __restrict__ Ql,
          const uint32_t* __restrict__ Kh, const uint32_t* __restrict__ Kl,
          const uint32_t* __restrict__ Vt, const int* __restrict__ mask,
          float* __restrict__ O)
{
    extern __shared__ uint32_t s4[];
    uint32_t* sQh = s4;
    uint32_t* sQl = sQh + 64 * BST;
    uint32_t* sKh = sQl + 64 * BST;
    uint32_t* sKl = sKh + 64 * BST;   // aliased by Ps after the S phase
    uint32_t* sPs = sKl;              // 64 * PST = 2304 <= 64 * BST
    uint32_t* sVs = sKl + 64 * BST;   // 32 token-pair rows x VST
    float*    pmx = (float*)(sVs + 32 * VST);  // [2][64]

    const int tid = threadIdx.x, lane = tid & 31, warp = tid >> 5;
    const int rg = warp & 3, cg = warp >> 2;
    const int gid = lane >> 2, tig = lane & 3;
    const int q0 = blockIdx.x * 64, h = blockIdx.y, b = blockIdx.z;
    const int kh = h & (NKV_ - 1);
    const int lr = rg * 16 + gid;

    const uint32_t* qhb = Qh + ((size_t)b * NH_  + h ) * ((size_t)T_ * 64) + (size_t)q0 * 64;
    const uint32_t* qlb = Ql + ((size_t)b * NH_  + h ) * ((size_t)T_ * 64) + (size_t)q0 * 64;
    const uint32_t* khb = Kh + ((size_t)b * NKV_ + kh) * ((size_t)T_ * 64);
    const uint32_t* klb = Kl + ((size_t)b * NKV_ + kh) * ((size_t)T_ * 64);
    const uint32_t* vtb = Vt + ((size_t)b * NKV_ + kh) * ((size_t)T_ * 64);
    const int*      mb  = mask + (size_t)b * T_ * T_;

    // Q planes: pure copy
    #pragma unroll
    for (int i = 0; i < 4; i++) {
        int idx = i * 256 + tid;
        int r = idx >> 4, c = (idx & 15) * 4;
        *(uint4*)&sQh[r * BST + c] = *(const uint4*)(qhb + r * 64 + c);
        *(uint4*)&sQl[r * BST + c] = *(const uint4*)(qlb + r * 64 + c);
    }

    float m0 = -1e30f, m1 = -1e30f, l0 = 0.f, l1 = 0.f;
    float oacc[8][4];
    #pragma unroll
    for (int j = 0; j < 8; j++)
        #pragma unroll
        for (int c = 0; c < 4; c++) oacc[j][c] = 0.f;

    for (int k0 = 0; k0 < T_; k0 += 64) {
        // mask prefetch
        int2 mq0[4], mq1[4];
        #pragma unroll
        for (int j = 0; j < 4; j++) {
            const int col = k0 + cg * 32 + j * 8 + 2 * tig;
            mq0[j] = *(const int2*)(mb + (size_t)(q0 + lr)     * T_ + col);
            mq1[j] = *(const int2*)(mb + (size_t)(q0 + lr + 8) * T_ + col);
        }
        __syncthreads();   // prior PV reads of Ps/Vs done
        // K planes: pure copies
        #pragma unroll
        for (int i = 0; i < 4; i++) {
            int idx = i * 256 + tid;
            int r = idx >> 4, c = (idx & 15) * 4;
            *(uint4*)&sKh[r * BST + c] = *(const uint4*)(khb + (size_t)(k0 + r) * 64 + c);
            *(uint4*)&sKl[r * BST + c] = *(const uint4*)(klb + (size_t)(k0 + r) * 64 + c);
        }
        // V: repack fp16 d-pairs -> token-pair rows (2 prmt per 2 u32)
        #pragma unroll
        for (int i = 0; i < 8; i++) {
            int idx = i * 256 + tid;
            int tp = idx >> 6, d2 = idx & 63;
            uint32_t va = vtb[(size_t)(k0 + 2 * tp) * 64 + d2];
            uint32_t vb = vtb[(size_t)(k0 + 2 * tp + 1) * 64 + d2];
            uint32_t lo = __byte_perm(va, vb, 0x5410);  // d even: tokens (2tp, 2tp+1)
            uint32_t hi = __byte_perm(va, vb, 0x7632);  // d odd
            *(uint2*)&sVs[tp * VST + 2 * d2] = make_uint2(lo, hi);
        }
        __syncthreads();

        // S = Q K^T (bf16 3-term)
        float sacc[4][4];
        #pragma unroll
        for (int j = 0; j < 4; j++)
            #pragma unroll
            for (int c = 0; c < 4; c++) sacc[j][c] = 0.f;

        #pragma unroll
        for (int s = 0; s < 8; s++) {
            const int qa = lr * BST + 8 * s;
            uint32_t ah[4] = {sQh[qa + tig], sQh[qa + 8 * BST + tig],
                              sQh[qa + tig + 4], sQh[qa + 8 * BST + tig + 4]};
            uint32_t al[4] = {sQl[qa + tig], sQl[qa + 8 * BST + tig],
                              sQl[qa + tig + 4], sQl[qa + 8 * BST + tig + 4]};
            #pragma unroll
            for (int j = 0; j < 4; j++) {
                const int kbase = (cg * 32 + j * 8 + gid) * BST + 8 * s;
                uint32_t bh[2] = {sKh[kbase + tig], sKh[kbase + tig + 4]};
                uint32_t bl[2] = {sKl[kbase + tig], sKl[kbase + tig + 4]};
                mma_bf16(sacc[j], ah, bh);
                mma_bf16(sacc[j], ah, bl);
                mma_bf16(sacc[j], al, bh);
            }
        }

        float mx0 = -1e30f, mx1 = -1e30f;
        #pragma unroll
        for (int j = 0; j < 4; j++) {
            sacc[j][0] = mq0[j].x ? sacc[j][0] * SCL2_ : MSK2_;
            sacc[j][1] = mq0[j].y ? sacc[j][1] * SCL2_ : MSK2_;
            sacc[j][2] = mq1[j].x ? sacc[j][2] * SCL2_ : MSK2_;
            sacc[j][3] = mq1[j].y ? sacc[j][3] * SCL2_ : MSK2_;
            mx0 = fmaxf(mx0, fmaxf(sacc[j][0], sacc[j][1]));
            mx1 = fmaxf(mx1, fmaxf(sacc[j][2], sacc[j][3]));
        }
        mx0 = fmaxf(mx0, __shfl_xor_sync(0xffffffffu, mx0, 1));
        mx0 = fmaxf(mx0, __shfl_xor_sync(0xffffffffu, mx0, 2));
        mx1 = fmaxf(mx1, __shfl_xor_sync(0xffffffffu, mx1, 1));
        mx1 = fmaxf(mx1, __shfl_xor_sync(0xffffffffu, mx1, 2));
        if (tig == 0) { pmx[cg * 64 + lr] = mx0; pmx[cg * 64 + lr + 8] = mx1; }
        __syncthreads();   // full: pmx exchange AND sKl->sPs alias guard

        float mn0 = fmaxf(m0, fmaxf(pmx[lr],     pmx[64 + lr]));
        float mn1 = fmaxf(m1, fmaxf(pmx[lr + 8], pmx[64 + lr + 8]));
        float a0 = ex2f(m0 - mn0), a1 = ex2f(m1 - mn1);
        m0 = mn0; m1 = mn1;

        float sum0 = 0.f, sum1 = 0.f;
        #pragma unroll
        for (int j = 0; j < 4; j++) {
            float p0 = ex2f(sacc[j][0] - mn0), p1 = ex2f(sacc[j][1] - mn0);
            float p2 = ex2f(sacc[j][2] - mn1), p3 = ex2f(sacc[j][3] - mn1);
            sum0 += p0 + p1; sum1 += p2 + p3;
            const int pc2 = cg * 16 + j * 4 + tig;   // token-pair index
            sPs[lr * PST + pc2]       = packh(p0, p1);
            sPs[(lr + 8) * PST + pc2] = packh(p2, p3);
        }
        sum0 += __shfl_xor_sync(0xffffffffu, sum0, 1);
        sum0 += __shfl_xor_sync(0xffffffffu, sum0, 2);
        sum1 += __shfl_xor_sync(0xffffffffu, sum1, 1);
        sum1 += __shfl_xor_sync(0xffffffffu, sum1, 2);
        l0 = l0 * a0 + sum0;
        l1 = l1 * a1 + sum1;
        #pragma unroll
        for (int j = 0; j < 8; j++) {
            oacc[j][0] *= a0; oacc[j][1] *= a0;
            oacc[j][2] *= a1; oacc[j][3] *= a1;
        }
        asm volatile("bar.sync %0, 64;" :: "r"(rg + 1) : "memory");

        // O += P V (fp16 k16, 4 steps)
        #pragma unroll
        for (int s = 0; s < 4; s++) {
            const int pa0 = lr * PST + 8 * s, pa1 = (lr + 8) * PST + 8 * s;
            uint32_t pa[4] = {sPs[pa0 + tig], sPs[pa1 + tig],
                              sPs[pa0 + tig + 4], sPs[pa1 + tig + 4]};
            #pragma unroll
            for (int j = 0; j < 8; j++) {
                const int vn = cg * 64 + j * 8 + gid;
                uint32_t vbf[2] = {sVs[(8 * s + tig) * VST + vn],
                                   sVs[(8 * s + tig + 4) * VST + vn]};
                mma_fp16(oacc[j], pa, vbf);
            }
        }
    }

    asm volatile("bar.sync %0, 64;" :: "r"(rg + 1) : "memory");
    if (tig == 0) { pmx[cg * 64 + lr] = l0; pmx[cg * 64 + lr + 8] = l1; }
    asm volatile("bar.sync %0, 64;" :: "r"(rg + 1) : "memory");
    const float inv0 = 1.f / (pmx[lr] + pmx[64 + lr]);
    const float inv1 = 1.f / (pmx[lr + 8] + pmx[64 + lr + 8]);
    float* ob = O + ((size_t)b * T_ + q0 + lr) * E_ + h * HD_ + cg * 64 + 2 * tig;
    #pragma unroll
    for (int j = 0; j < 8; j++) {
        *(float2*)(ob + j * 8)                  = make_float2(oacc[j][0] * inv0, oacc[j][1] * inv0);
        *(float2*)(ob + 8 * (size_t)E_ + j * 8) = make_float2(oacc[j][2] * inv1, oacc[j][3] * inv1);
    }
}

// ---------------- launcher ----------------
extern "C" void kernel_launch(void* const* d_in, const int* in_sizes, int n_in,
                              void* d_out, int out_size)
{
    const float* x  = (const float*)d_in[0];
    const int*   am = (const int*)  d_in[1];
    const float* Wq = (const float*)d_in[2];
    const float* bq = (const float*)d_in[3];
    const float* Wk = (const float*)d_in[4];
    const float* bk = (const float*)d_in[5];
    const float* Wv = (const float*)d_in[6];
    const float* bv = (const float*)d_in[7];
    const float* Wo = (const float*)d_in[8];
    const float* bo = (const float*)d_in[9];
    float* out = (float*)d_out;

    float *k, *v, *att;
    uint32_t *qh, *ql, *kh, *kl, *vt;
    cudaGetSymbolAddress((void**)&k,   g_k);
    cudaGetSymbolAddress((void**)&v,   g_v);
    cudaGetSymbolAddress((void**)&att, g_att);
    cudaGetSymbolAddress((void**)&qh,  g_qh);
    cudaGetSymbolAddress((void**)&ql,  g_ql);
    cudaGetSymbolAddress((void**)&kh,  g_kh);
    cudaGetSymbolAddress((void**)&kl,  g_kl);
    cudaGetSymbolAddress((void**)&vt,  g_vt);

    const int M = B_ * T_;

    gemm_bf16<true ><<<dim3(E_ / 128,   M / 128), 256>>>(x, Wq, bq, nullptr, qh, ql, M, E_,   E_);
    gemm_bf16<false><<<dim3(KVD_ / 128, M / 128), 256>>>(x, Wk, bk, k, qh, ql, M, KVD_, E_);
    gemm_fp16<<<dim3(KVD_ / 128, M / 128), 256>>>(x, Wv, bv, v, M, KVD_, E_);

    rope_split<<<(B_ * NKV_ * T_ * 64) / 256, 256>>>(k, v, kh, kl, vt);

    const int fsmem = (4 * 64 * BST + 32 * VST + 128) * 4;  // 87040 B
    cudaFuncSetAttribute(flash_mma, cudaFuncAttributeMaxDynamicSharedMemorySize, fsmem);
    flash_mma<<<dim3(T_ / 64, NH_, B_), 256, fsmem>>>(qh, ql, kh, kl, vt, am, att);

    gemm_fp16<<<dim3(E_ / 128, M / 128), 256>>>(att, Wo, bo, out, M, E_, E_);
}

// round 15
// speedup vs baseline: 3.9885x; 1.0786x over previous
#include <cuda_runtime.h>
#include <cuda_bf16.h>
#include <cuda_fp16.h>
#include <math.h>
#include <stdint.h>

constexpr int B_   = 4;
constexpr int T_   = 2048;
constexpr int E_   = 2048;
constexpr int NH_  = 16;
constexpr int NKV_ = 4;
constexpr int HD_  = 128;
constexpr int KVD_ = NKV_ * HD_;
constexpr float SCL2_ = 16.32232319089277f;     // sqrt(128) * log2(e)
constexpr float MSK2_ = 1.4426950408889634e-9f; // 1e-9 * log2(e)

__device__ float g_k[(size_t)B_ * T_ * KVD_];          // f32 K (rope input)
__device__ float g_v[(size_t)B_ * T_ * KVD_];          // f32 V (rope input)
__device__ float g_att[(size_t)B_ * T_ * E_];
__device__ uint32_t g_qh[(size_t)B_ * NH_  * T_ * 64]; // Q bf16-pair hi plane (view layout)
__device__ uint32_t g_ql[(size_t)B_ * NH_  * T_ * 64]; // Q lo plane
__device__ uint32_t g_kh[(size_t)B_ * NKV_ * T_ * 64]; // K hi plane (post-rope)
__device__ uint32_t g_kl[(size_t)B_ * NKV_ * T_ * 64]; // K lo plane
__device__ uint32_t g_vt[(size_t)B_ * NKV_ * T_ * 64]; // V fp16x2 (d-pairs, post-rope)

// ---------------- helpers ----------------
__device__ __forceinline__ float bfhi(float f) {
    return __bfloat162float(__float2bfloat16(f));
}
__device__ __forceinline__ uint32_t packbf(float f0, float f1) {
    __nv_bfloat162 h = __floats2bfloat162_rn(f0, f1);
    return *(uint32_t*)&h;
}
__device__ __forceinline__ uint32_t packh(float f0, float f1) {
    __half2 h = __floats2half2_rn(f0, f1);
    return *(uint32_t*)&h;
}
__device__ __forceinline__ float ex2f(float x) {
    float r; asm("ex2.approx.f32 %0, %1;" : "=f"(r) : "f"(x)); return r;
}
__device__ __forceinline__ void mma_bf16(float c[4], const uint32_t a[4], const uint32_t b[2]) {
    asm volatile("mma.sync.aligned.m16n8k16.row.col.f32.bf16.bf16.f32 "
        "{%0,%1,%2,%3}, {%4,%5,%6,%7}, {%8,%9}, {%0,%1,%2,%3};"
        : "+f"(c[0]), "+f"(c[1]), "+f"(c[2]), "+f"(c[3])
        : "r"(a[0]), "r"(a[1]), "r"(a[2]), "r"(a[3]), "r"(b[0]), "r"(b[1]));
}
__device__ __forceinline__ void mma_fp16(float c[4], const uint32_t a[4], const uint32_t b[2]) {
    asm volatile("mma.sync.aligned.m16n8k16.row.col.f32.f16.f16.f32 "
        "{%0,%1,%2,%3}, {%4,%5,%6,%7}, {%8,%9}, {%0,%1,%2,%3};"
        : "+f"(c[0]), "+f"(c[1]), "+f"(c[2]), "+f"(c[3])
        : "r"(a[0]), "r"(a[1]), "r"(a[2]), "r"(a[3]), "r"(b[0]), "r"(b[1]));
}

// ---------------------------------------------------------------------------
// bf16 2-plane / 3-term GEMM (Q/K projections), term-outer inner loop,
// 2 CTAs/SM. POUT=true: write bf16 hi/lo planes into the RESHAPE-VIEW layout
// (b,h,t,dpair): rr=row%T; h=rr>>7; t=((rr&127)<<4)|(col>>7); d=col&127.
// ---------------------------------------------------------------------------
template<bool POUT>
__global__ void __launch_bounds__(256, 2)
gemm_bf16(const float* __restrict__ A, const float* __restrict__ W,
          const float* __restrict__ bias, float* __restrict__ C,
          uint32_t* __restrict__ Ph, uint32_t* __restrict__ Pl,
          int M, int N, int K)
{
    constexpr int AS = 20;
    constexpr int BS = 132;
    __shared__ uint32_t Ah[128 * AS], Al[128 * AS];
    __shared__ uint32_t Bh[16 * BS],  Bl[16 * BS];

    const int tid = threadIdx.x, lane = tid & 31, warp = tid >> 5;
    const int wm = (warp >> 2) * 64, wn = (warp & 3) * 32;
    const int gid = lane >> 2, tig = lane & 3;
    const int bm = blockIdx.y * 128, bn = blockIdx.x * 128;

    const int la_m = tid >> 1, la_k = (tid & 1) * 16;
    const float* Ap = A + (size_t)(bm + la_m) * K + la_k;
    const float* Bp = W + bn + lane * 4;
    const int kr0 = 2 * warp, kr1 = 2 * warp + 1;
    const int kr2 = 2 * warp + 16, kr3 = 2 * warp + 17;

    float4 ar[4], br[4];
    #pragma unroll
    for (int j = 0; j < 4; j++) ar[j] = *(const float4*)(Ap + 4 * j);
    br[0] = *(const float4*)(Bp + (size_t)kr0 * N);
    br[1] = *(const float4*)(Bp + (size_t)kr1 * N);
    br[2] = *(const float4*)(Bp + (size_t)kr2 * N);
    br[3] = *(const float4*)(Bp + (size_t)kr3 * N);

    float acc[4][4][4];
    #pragma unroll
    for (int i = 0; i < 4; i++)
        #pragma unroll
        for (int j = 0; j < 4; j++)
            #pragma unroll
            for (int c = 0; c < 4; c++) acc[i][j][c] = 0.f;

    for (int kt = 0; kt < K; kt += 32) {
        #pragma unroll
        for (int j = 0; j < 4; j++) {
            float4 x = ar[j];
            float hx = bfhi(x.x), hy = bfhi(x.y), hz = bfhi(x.z), hw = bfhi(x.w);
            uint2 hh = make_uint2(packbf(hx, hy), packbf(hz, hw));
            uint2 ll = make_uint2(packbf(x.x - hx, x.y - hy), packbf(x.z - hz, x.w - hw));
            int off = la_m * AS + (la_k >> 1) + 2 * j;
            *(uint2*)&Ah[off] = hh;
            *(uint2*)&Al[off] = ll;
        }
        {
            uint4 h0, l0, h1, l1;
            #pragma unroll
            for (int e = 0; e < 4; e++) {
                float a0 = ((const float*)&br[0])[e], a1 = ((const float*)&br[1])[e];
                float b0 = ((const float*)&br[2])[e], b1 = ((const float*)&br[3])[e];
                float ha0 = bfhi(a0), ha1 = bfhi(a1), hb0 = bfhi(b0), hb1 = bfhi(b1);
                ((uint32_t*)&h0)[e] = packbf(ha0, ha1);
                ((uint32_t*)&l0)[e] = packbf(a0 - ha0, a1 - ha1);
                ((uint32_t*)&h1)[e] = packbf(hb0, hb1);
                ((uint32_t*)&l1)[e] = packbf(b0 - hb0, b1 - hb1);
            }
            *(uint4*)&Bh[warp * BS + 4 * lane]       = h0;
            *(uint4*)&Bl[warp * BS + 4 * lane]       = l0;
            *(uint4*)&Bh[(warp + 8) * BS + 4 * lane] = h1;
            *(uint4*)&Bl[(warp + 8) * BS + 4 * lane] = l1;
        }
        __syncthreads();

        if (kt + 32 < K) {
            #pragma unroll
            for (int j = 0; j < 4; j++) ar[j] = *(const float4*)(Ap + kt + 32 + 4 * j);
            br[0] = *(const float4*)(Bp + (size_t)(kt + 32 + kr0) * N);
            br[1] = *(const float4*)(Bp + (size_t)(kt + 32 + kr1) * N);
            br[2] = *(const float4*)(Bp + (size_t)(kt + 32 + kr2) * N);
            br[3] = *(const float4*)(Bp + (size_t)(kt + 32 + kr3) * N);
        }

        // term-outer: per k8-step run passes hh, hl, lh.  Per-accumulator
        // order per step stays hh->hl->lh (bitwise identical to term-inner);
        // same-acc mma distance goes 1 -> >=4 and live regs drop.
        #pragma unroll
        for (int s = 0; s < 2; s++) {
            const int s8 = s * 8;
            #pragma unroll
            for (int t = 0; t < 3; t++) {
                const uint32_t* Aq = (t == 2) ? Al : Ah;
                const uint32_t* Bq = (t == 1) ? Bl : Bh;
                uint32_t af[4][4];
                #pragma unroll
                for (int i = 0; i < 4; i++) {
                    const int r0 = (wm + i * 16 + gid) * AS + s8;
                    const int r1 = r0 + 8 * AS;
                    af[i][0] = Aq[r0 + tig];     af[i][1] = Aq[r1 + tig];
                    af[i][2] = Aq[r0 + tig + 4]; af[i][3] = Aq[r1 + tig + 4];
                }
                #pragma unroll
                for (int j = 0; j < 4; j++) {
                    const int cb = wn + j * 8 + gid;
                    uint32_t b2[2] = {Bq[(s8 + tig) * BS + cb],
                                      Bq[(s8 + tig + 4) * BS + cb]};
                    #pragma unroll
                    for (int i = 0; i < 4; i++) mma_bf16(acc[i][j], af[i], b2);
                }
            }
        }
        __syncthreads();
    }

    #pragma unroll
    for (int j = 0; j < 4; j++) {
        const int col = bn + wn + j * 8 + tig * 2;
        const float b0 = bias[col], b1 = bias[col + 1];
        #pragma unroll
        for (int i = 0; i < 4; i++) {
            const int row0 = bm + wm + i * 16 + gid;
            if (POUT) {
                const int dp = (col & 127) >> 1;
                #pragma unroll
                for (int half = 0; half < 2; half++) {
                    const int row = row0 + 8 * half;
                    const float v0 = acc[i][j][2 * half]     + b0;
                    const float v1 = acc[i][j][2 * half + 1] + b1;
                    const float h0 = bfhi(v0), h1 = bfhi(v1);
                    const int bb = row >> 11;
                    const int rr = row & (T_ - 1);
                    const int hh = rr >> 7;
                    const int t  = ((rr & 127) << 4) | (col >> 7);
                    const size_t o = ((size_t)(bb * NH_ + hh) * T_ + t) * 64 + dp;
                    Ph[o] = packbf(h0, h1);
                    Pl[o] = packbf(v0 - h0, v1 - h1);
                }
            } else {
                *(float2*)&C[(size_t)row0 * N + col]       = make_float2(acc[i][j][0] + b0, acc[i][j][1] + b1);
                *(float2*)&C[(size_t)(row0 + 8) * N + col] = make_float2(acc[i][j][2] + b0, acc[i][j][3] + b1);
            }
        }
    }
}

// ---------------------------------------------------------------------------
// fp16 single-plane GEMM (V/O projections), 2 CTAs/SM.
// ---------------------------------------------------------------------------
__global__ void __launch_bounds__(256, 2)
gemm_fp16(const float* __restrict__ A, const float* __restrict__ W,
          const float* __restrict__ bias, float* __restrict__ C,
          int M, int N, int K)
{
    constexpr int AS = 20;
    constexpr int BS = 132;
    __shared__ uint32_t Ah[128 * AS];
    __shared__ uint32_t Bh[16 * BS];

    const int tid = threadIdx.x, lane = tid & 31, warp = tid >> 5;
    const int wm = (warp >> 2) * 64, wn = (warp & 3) * 32;
    const int gid = lane >> 2, tig = lane & 3;
    const int bm = blockIdx.y * 128, bn = blockIdx.x * 128;

    const int la_m = tid >> 1, la_k = (tid & 1) * 16;
    const float* Ap = A + (size_t)(bm + la_m) * K + la_k;
    const float* Bp = W + bn + lane * 4;
    const int kr0 = 2 * warp, kr1 = 2 * warp + 1;
    const int kr2 = 2 * warp + 16, kr3 = 2 * warp + 17;

    float4 ar[4], br[4];
    #pragma unroll
    for (int j = 0; j < 4; j++) ar[j] = *(const float4*)(Ap + 4 * j);
    br[0] = *(const float4*)(Bp + (size_t)kr0 * N);
    br[1] = *(const float4*)(Bp + (size_t)kr1 * N);
    br[2] = *(const float4*)(Bp + (size_t)kr2 * N);
    br[3] = *(const float4*)(Bp + (size_t)kr3 * N);

    float acc[4][4][4];
    #pragma unroll
    for (int i = 0; i < 4; i++)
        #pragma unroll
        for (int j = 0; j < 4; j++)
            #pragma unroll
            for (int c = 0; c < 4; c++) acc[i][j][c] = 0.f;

    for (int kt = 0; kt < K; kt += 32) {
        #pragma unroll
        for (int j = 0; j < 4; j++) {
            float4 x = ar[j];
            uint2 hh = make_uint2(packh(x.x, x.y), packh(x.z, x.w));
            *(uint2*)&Ah[la_m * AS + (la_k >> 1) + 2 * j] = hh;
        }
        {
            uint4 h0, h1;
            #pragma unroll
            for (int e = 0; e < 4; e++) {
                ((uint32_t*)&h0)[e] = packh(((const float*)&br[0])[e], ((const float*)&br[1])[e]);
                ((uint32_t*)&h1)[e] = packh(((const float*)&br[2])[e], ((const float*)&br[3])[e]);
            }
            *(uint4*)&Bh[warp * BS + 4 * lane]       = h0;
            *(uint4*)&Bh[(warp + 8) * BS + 4 * lane] = h1;
        }
        __syncthreads();

        if (kt + 32 < K) {
            #pragma unroll
            for (int j = 0; j < 4; j++) ar[j] = *(const float4*)(Ap + kt + 32 + 4 * j);
            br[0] = *(const float4*)(Bp + (size_t)(kt + 32 + kr0) * N);
            br[1] = *(const float4*)(Bp + (size_t)(kt + 32 + kr1) * N);
            br[2] = *(const float4*)(Bp + (size_t)(kt + 32 + kr2) * N);
            br[3] = *(const float4*)(Bp + (size_t)(kt + 32 + kr3) * N);
        }

        #pragma unroll
        for (int s = 0; s < 2; s++) {
            const int s8 = s * 8;
            uint32_t ah[4][4];
            #pragma unroll
            for (int i = 0; i < 4; i++) {
                const int r0 = (wm + i * 16 + gid) * AS + s8;
                const int r1 = r0 + 8 * AS;
                ah[i][0] = Ah[r0 + tig];     ah[i][1] = Ah[r1 + tig];
                ah[i][2] = Ah[r0 + tig + 4]; ah[i][3] = Ah[r1 + tig + 4];
            }
            #pragma unroll
            for (int j = 0; j < 4; j++) {
                const int cb = wn + j * 8 + gid;
                uint32_t bh[2] = {Bh[(s8 + tig) * BS + cb], Bh[(s8 + tig + 4) * BS + cb]};
                #pragma unroll
                for (int i = 0; i < 4; i++) mma_fp16(acc[i][j], ah[i], bh);
            }
        }
        __syncthreads();
    }

    #pragma unroll
    for (int j = 0; j < 4; j++) {
        const int col = bn + wn + j * 8 + tig * 2;
        const float b0 = bias[col], b1 = bias[col + 1];
        #pragma unroll
        for (int i = 0; i < 4; i++) {
            const int row = bm + wm + i * 16 + gid;
            *(float2*)&C[(size_t)row * N + col]       = make_float2(acc[i][j][0] + b0, acc[i][j][1] + b1);
            *(float2*)&C[(size_t)(row + 8) * N + col] = make_float2(acc[i][j][2] + b0, acc[i][j][3] + b1);
        }
    }
}

// ---------------- RoPE + operand prep: K -> bf16 planes, V -> fp16x2 ------
__global__ void rope_split(const float* __restrict__ k, const float* __restrict__ v,
                           uint32_t* __restrict__ kh, uint32_t* __restrict__ kl,
                           uint32_t* __restrict__ vt)
{
    int p = blockIdx.x * 256 + threadIdx.x;
    int d2 = p & 63, rr = p >> 6, t = rr & (T_ - 1);
    double th = exp2((double)d2 * -0.20762050593046014);
    float angf = (float)t * (float)th;
    float s, c;
    sincosf(angf, &s, &c);
    size_t base = (size_t)rr * HD_ + 2 * d2;
    float2 kk = *(const float2*)(k + base), vv = *(const float2*)(v + base);
    float kx = kk.x * c - kk.y * s, ky = kk.x * s + kk.y * c;
    float vx = vv.x * c - vv.y * s, vy = vv.x * s + vv.y * c;
    float hx = bfhi(kx), hy = bfhi(ky);
    kh[(size_t)rr * 64 + d2] = packbf(hx, hy);
    kl[(size_t)rr * 64 + d2] = packbf(kx - hx, ky - hy);
    vt[(size_t)rr * 64 + d2] = packh(vx, vy);
}

// ---------------- Tensor-core flash attention ----------------
// S: bf16 3-term m16n8k16 (term-outer). PV: fp16 m16n8k16.
constexpr int BST = 68;   // Q/K plane row stride (u32)
constexpr int VST = 132;  // V token-pair row stride (u32): 128 d + pad
constexpr int PST = 36;   // Ps row stride (u32): 32 token-pairs + pad

__global__ void __launch_bounds__(256, 2)
flash_mma(const uint32_t* __restrict__ Qh, const uint32_t* __restrict__ Ql,
          const uint32_t* __restrict__ Kh, const uint32_t* __restrict__ Kl,
          const uint32_t* __restrict__ Vt, const int* __restrict__ mask,
          float* __restrict__ O)
{
    extern __shared__ uint32_t s4[];
    uint32_t* sQh = s4;
    uint32_t* sQl = sQh + 64 * BST;
    uint32_t* sKh = sQl + 64 * BST;
    uint32_t* sKl = sKh + 64 * BST;   // aliased by Ps after the S phase
    uint32_t* sPs = sKl;              // 64 * PST <= 64 * BST
    uint32_t* sVs = sKl + 64 * BST;   // 32 token-pair rows x VST
    float*    pmx = (float*)(sVs + 32 * VST);  // [2][64]

    const int tid = threadIdx.x, lane = tid & 31, warp = tid >> 5;
    const int rg = warp & 3, cg = warp >> 2;
    const int gid = lane >> 2, tig = lane & 3;
    const int q0 = blockIdx.x * 64, h = blockIdx.y, b = blockIdx.z;
    const int kh = h & (NKV_ - 1);
    const int lr = rg * 16 + gid;

    const uint32_t* qhb = Qh + ((size_t)b * NH_  + h ) * ((size_t)T_ * 64) + (size_t)q0 * 64;
    const uint32_t* qlb = Ql + ((size_t)b * NH_  + h ) * ((size_t)T_ * 64) + (size_t)q0 * 64;
    const uint32_t* khb = Kh + ((size_t)b * NKV_ + kh) * ((size_t)T_ * 64);
    const uint32_t* klb = Kl + ((size_t)b * NKV_ + kh) * ((size_t)T_ * 64);
    const uint32_t* vtb = Vt + ((size_t)b * NKV_ + kh) * ((size_t)T_ * 64);
    const int*      mb  = mask + (size_t)b * T_ * T_;

    // Q planes: pure copy
    #pragma unroll
    for (int i = 0; i < 4; i++) {
        int idx = i * 256 + tid;
        int r = idx >> 4, c = (idx & 15) * 4;
        *(uint4*)&sQh[r * BST + c] = *(const uint4*)(qhb + r * 64 + c);
        *(uint4*)&sQl[r * BST + c] = *(const uint4*)(qlb + r * 64 + c);
    }

    float m0 = -1e30f, m1 = -1e30f, l0 = 0.f, l1 = 0.f;
    float oacc[8][4];
    #pragma unroll
    for (int j = 0; j < 8; j++)
        #pragma unroll
        for (int c = 0; c < 4; c++) oacc[j][c] = 0.f;

    for (int k0 = 0; k0 < T_; k0 += 64) {
        // mask prefetch
        int2 mq0[4], mq1[4];
        #pragma unroll
        for (int j = 0; j < 4; j++) {
            const int col = k0 + cg * 32 + j * 8 + 2 * tig;
            mq0[j] = *(const int2*)(mb + (size_t)(q0 + lr)     * T_ + col);
            mq1[j] = *(const int2*)(mb + (size_t)(q0 + lr + 8) * T_ + col);
        }
        __syncthreads();   // prior PV reads of Ps/Vs done
        // K planes: pure copies
        #pragma unroll
        for (int i = 0; i < 4; i++) {
            int idx = i * 256 + tid;
            int r = idx >> 4, c = (idx & 15) * 4;
            *(uint4*)&sKh[r * BST + c] = *(const uint4*)(khb + (size_t)(k0 + r) * 64 + c);
            *(uint4*)&sKl[r * BST + c] = *(const uint4*)(klb + (size_t)(k0 + r) * 64 + c);
        }
        // V: repack fp16 d-pairs -> token-pair rows
        #pragma unroll
        for (int i = 0; i < 8; i++) {
            int idx = i * 256 + tid;
            int tp = idx >> 6, d2 = idx & 63;
            uint32_t va = vtb[(size_t)(k0 + 2 * tp) * 64 + d2];
            uint32_t vb = vtb[(size_t)(k0 + 2 * tp + 1) * 64 + d2];
            uint32_t lo = __byte_perm(va, vb, 0x5410);
            uint32_t hi = __byte_perm(va, vb, 0x7632);
            *(uint2*)&sVs[tp * VST + 2 * d2] = make_uint2(lo, hi);
        }
        __syncthreads();

        // S = Q K^T (bf16 3-term, term-outer: same-acc mma distance 4)
        float sacc[4][4];
        #pragma unroll
        for (int j = 0; j < 4; j++)
            #pragma unroll
            for (int c = 0; c < 4; c++) sacc[j][c] = 0.f;

        #pragma unroll
        for (int s = 0; s < 8; s++) {
            const int qa = lr * BST + 8 * s;
            uint32_t ah[4] = {sQh[qa + tig], sQh[qa + 8 * BST + tig],
                              sQh[qa + tig + 4], sQh[qa + 8 * BST + tig + 4]};
            uint32_t al[4] = {sQl[qa + tig], sQl[qa + 8 * BST + tig],
                              sQl[qa + tig + 4], sQl[qa + 8 * BST + tig + 4]};
            uint32_t bh[4][2], bl[4][2];
            #pragma unroll
            for (int j = 0; j < 4; j++) {
                const int kbase = (cg * 32 + j * 8 + gid) * BST + 8 * s;
                bh[j][0] = sKh[kbase + tig]; bh[j][1] = sKh[kbase + tig + 4];
                bl[j][0] = sKl[kbase + tig]; bl[j][1] = sKl[kbase + tig + 4];
            }
            #pragma unroll
            for (int j = 0; j < 4; j++) mma_bf16(sacc[j], ah, bh[j]);
            #pragma unroll
            for (int j = 0; j < 4; j++) mma_bf16(sacc[j], ah, bl[j]);
            #pragma unroll
            for (int j = 0; j < 4; j++) mma_bf16(sacc[j], al, bh[j]);
        }

        float mx0 = -1e30f, mx1 = -1e30f;
        #pragma unroll
        for (int j = 0; j < 4; j++) {
            sacc[j][0] = mq0[j].x ? sacc[j][0] * SCL2_ : MSK2_;
            sacc[j][1] = mq0[j].y ? sacc[j][1] * SCL2_ : MSK2_;
            sacc[j][2] = mq1[j].x ? sacc[j][2] * SCL2_ : MSK2_;
            sacc[j][3] = mq1[j].y ? sacc[j][3] * SCL2_ : MSK2_;
            mx0 = fmaxf(mx0, fmaxf(sacc[j][0], sacc[j][1]));
            mx1 = fmaxf(mx1, fmaxf(sacc[j][2], sacc[j][3]));
        }
        mx0 = fmaxf(mx0, __shfl_xor_sync(0xffffffffu, mx0, 1));
        mx0 = fmaxf(mx0, __shfl_xor_sync(0xffffffffu, mx0, 2));
        mx1 = fmaxf(mx1, __shfl_xor_sync(0xffffffffu, mx1, 1));
        mx1 = fmaxf(mx1, __shfl_xor_sync(0xffffffffu, mx1, 2));
        if (tig == 0) { pmx[cg * 64 + lr] = mx0; pmx[cg * 64 + lr + 8] = mx1; }
        __syncthreads();   // full: pmx exchange AND sKl->sPs alias guard

        float mn0 = fmaxf(m0, fmaxf(pmx[lr],     pmx[64 + lr]));
        float mn1 = fmaxf(m1, fmaxf(pmx[lr + 8], pmx[64 + lr + 8]));
        float a0 = ex2f(m0 - mn0), a1 = ex2f(m1 - mn1);
        m0 = mn0; m1 = mn1;

        float sum0 = 0.f, sum1 = 0.f;
        #pragma unroll
        for (int j = 0; j < 4; j++) {
            float p0 = ex2f(sacc[j][0] - mn0), p1 = ex2f(sacc[j][1] - mn0);
            float p2 = ex2f(sacc[j][2] - mn1), p3 = ex2f(sacc[j][3] - mn1);
            sum0 += p0 + p1; sum1 += p2 + p3;
            const int pc2 = cg * 16 + j * 4 + tig;   // token-pair index
            sPs[lr * PST + pc2]       = packh(p0, p1);
            sPs[(lr + 8) * PST + pc2] = packh(p2, p3);
        }
        sum0 += __shfl_xor_sync(0xffffffffu, sum0, 1);
        sum0 += __shfl_xor_sync(0xffffffffu, sum0, 2);
        sum1 += __shfl_xor_sync(0xffffffffu, sum1, 1);
        sum1 += __shfl_xor_sync(0xffffffffu, sum1, 2);
        l0 = l0 * a0 + sum0;
        l1 = l1 * a1 + sum1;
        #pragma unroll
        for (int j = 0; j < 8; j++) {
            oacc[j][0] *= a0; oacc[j][1] *= a0;
            oacc[j][2] *= a1; oacc[j][3] *= a1;
        }
        asm volatile("bar.sync %0, 64;" :: "r"(rg + 1) : "memory");

        // O += P V (fp16 k16, 4 steps)
        #pragma unroll
        for (int s = 0; s < 4; s++) {
            const int pa0 = lr * PST + 8 * s, pa1 = (lr + 8) * PST + 8 * s;
            uint32_t pa[4] = {sPs[pa0 + tig], sPs[pa1 + tig],
                              sPs[pa0 + tig + 4], sPs[pa1 + tig + 4]};
            #pragma unroll
            for (int j = 0; j < 8; j++) {
                const int vn = cg * 64 + j * 8 + gid;
                uint32_t vbf[2] = {sVs[(8 * s + tig) * VST + vn],
                                   sVs[(8 * s + tig + 4) * VST + vn]};
                mma_fp16(oacc[j], pa, vbf);
            }
        }
    }

    asm volatile("bar.sync %0, 64;" :: "r"(rg + 1) : "memory");
    if (tig == 0) { pmx[cg * 64 + lr] = l0; pmx[cg * 64 + lr + 8] = l1; }
    asm volatile("bar.sync %0, 64;" :: "r"(rg + 1) : "memory");
    const float inv0 = 1.f / (pmx[lr] + pmx[64 + lr]);
    const float inv1 = 1.f / (pmx[lr + 8] + pmx[64 + lr + 8]);
    float* ob = O + ((size_t)b * T_ + q0 + lr) * E_ + h * HD_ + cg * 64 + 2 * tig;
    #pragma unroll
    for (int j = 0; j < 8; j++) {
        *(float2*)(ob + j * 8)                  = make_float2(oacc[j][0] * inv0, oacc[j][1] * inv0);
        *(float2*)(ob + 8 * (size_t)E_ + j * 8) = make_float2(oacc[j][2] * inv1, oacc[j][3] * inv1);
    }
}

// ---------------- launcher ----------------
extern "C" void kernel_launch(void* const* d_in, const int* in_sizes, int n_in,
                              void* d_out, int out_size)
{
    const float* x  = (const float*)d_in[0];
    const int*   am = (const int*)  d_in[1];
    const float* Wq = (const float*)d_in[2];
    const float* bq = (const float*)d_in[3];
    const float* Wk = (const float*)d_in[4];
    const float* bk = (const float*)d_in[5];
    const float* Wv = (const float*)d_in[6];
    const float* bv = (const float*)d_in[7];
    const float* Wo = (const float*)d_in[8];
    const float* bo = (const float*)d_in[9];
    float* out = (float*)d_out;

    float *k, *v, *att;
    uint32_t *qh, *ql, *kh, *kl, *vt;
    cudaGetSymbolAddress((void**)&k,   g_k);
    cudaGetSymbolAddress((void**)&v,   g_v);
    cudaGetSymbolAddress((void**)&att, g_att);
    cudaGetSymbolAddress((void**)&qh,  g_qh);
    cudaGetSymbolAddress((void**)&ql,  g_ql);
    cudaGetSymbolAddress((void**)&kh,  g_kh);
    cudaGetSymbolAddress((void**)&kl,  g_kl);
    cudaGetSymbolAddress((void**)&vt,  g_vt);

    const int M = B_ * T_;

    gemm_bf16<true ><<<dim3(E_ / 128,   M / 128), 256>>>(x, Wq, bq, nullptr, qh, ql, M, E_,   E_);
    gemm_bf16<false><<<dim3(KVD_ / 128, M / 128), 256>>>(x, Wk, bk, k, qh, ql, M, KVD_, E_);
    gemm_fp16<<<dim3(KVD_ / 128, M / 128), 256>>>(x, Wv, bv, v, M, KVD_, E_);

    rope_split<<<(B_ * NKV_ * T_ * 64) / 256, 256>>>(k, v, kh, kl, vt);

    const int fsmem = (4 * 64 * BST + 32 * VST + 128) * 4;  // 87040 B
    cudaFuncSetAttribute(flash_mma, cudaFuncAttributeMaxDynamicSharedMemorySize, fsmem);
    flash_mma<<<dim3(T_ / 64, NH_, B_), 256, fsmem>>>(qh, ql, kh, kl, vt, am, att);

    gemm_fp16<<<dim3(E_ / 128, M / 128), 256>>>(att, Wo, bo, out, M, E_, E_);
}

// round 16
// speedup vs baseline: 4.3585x; 1.0928x over previous
#include <cuda_runtime.h>
#include <cuda_bf16.h>
#include <cuda_fp16.h>
#include <math.h>
#include <stdint.h>

constexpr int B_   = 4;
constexpr int T_   = 2048;
constexpr int E_   = 2048;
constexpr int NH_  = 16;
constexpr int NKV_ = 4;
constexpr int HD_  = 128;
constexpr int KVD_ = NKV_ * HD_;
constexpr float SCL2_ = 16.32232319089277f;     // sqrt(128) * log2(e)
constexpr float MSK2_ = 1.4426950408889634e-9f; // 1e-9 * log2(e)

__device__ float g_k[(size_t)B_ * T_ * KVD_];
__device__ float g_v[(size_t)B_ * T_ * KVD_];
__device__ float g_att[(size_t)B_ * T_ * E_];
__device__ uint32_t g_qh[(size_t)B_ * NH_  * T_ * 64];
__device__ uint32_t g_ql[(size_t)B_ * NH_  * T_ * 64];
__device__ uint32_t g_kh[(size_t)B_ * NKV_ * T_ * 64];
__device__ uint32_t g_kl[(size_t)B_ * NKV_ * T_ * 64];
__device__ uint32_t g_vt[(size_t)B_ * NKV_ * T_ * 64];

// ---------------- helpers ----------------
__device__ __forceinline__ float bfhi(float f) {
    return __bfloat162float(__float2bfloat16(f));
}
__device__ __forceinline__ uint32_t packbf(float f0, float f1) {
    __nv_bfloat162 h = __floats2bfloat162_rn(f0, f1);
    return *(uint32_t*)&h;
}
__device__ __forceinline__ uint32_t packh(float f0, float f1) {
    __half2 h = __floats2half2_rn(f0, f1);
    return *(uint32_t*)&h;
}
__device__ __forceinline__ float ex2f(float x) {
    float r; asm("ex2.approx.f32 %0, %1;" : "=f"(r) : "f"(x)); return r;
}
__device__ __forceinline__ void mma_bf16(float c[4], const uint32_t a[4], const uint32_t b[2]) {
    asm volatile("mma.sync.aligned.m16n8k16.row.col.f32.bf16.bf16.f32 "
        "{%0,%1,%2,%3}, {%4,%5,%6,%7}, {%8,%9}, {%0,%1,%2,%3};"
        : "+f"(c[0]), "+f"(c[1]), "+f"(c[2]), "+f"(c[3])
        : "r"(a[0]), "r"(a[1]), "r"(a[2]), "r"(a[3]), "r"(b[0]), "r"(b[1]));
}
__device__ __forceinline__ void mma_fp16(float c[4], const uint32_t a[4], const uint32_t b[2]) {
    asm volatile("mma.sync.aligned.m16n8k16.row.col.f32.f16.f16.f32 "
        "{%0,%1,%2,%3}, {%4,%5,%6,%7}, {%8,%9}, {%0,%1,%2,%3};"
        : "+f"(c[0]), "+f"(c[1]), "+f"(c[2]), "+f"(c[3])
        : "r"(a[0]), "r"(a[1]), "r"(a[2]), "r"(a[3]), "r"(b[0]), "r"(b[1]));
}

// ---------------------------------------------------------------------------
// bf16 2-plane / 3-term GEMM (Q/K projections) — unchanged from round 15.
// ---------------------------------------------------------------------------
template<bool POUT>
__global__ void __launch_bounds__(256, 2)
gemm_bf16(const float* __restrict__ A, const float* __restrict__ W,
          const float* __restrict__ bias, float* __restrict__ C,
          uint32_t* __restrict__ Ph, uint32_t* __restrict__ Pl,
          int M, int N, int K)
{
    constexpr int AS = 20;
    constexpr int BS = 132;
    __shared__ uint32_t Ah[128 * AS], Al[128 * AS];
    __shared__ uint32_t Bh[16 * BS],  Bl[16 * BS];

    const int tid = threadIdx.x, lane = tid & 31, warp = tid >> 5;
    const int wm = (warp >> 2) * 64, wn = (warp & 3) * 32;
    const int gid = lane >> 2, tig = lane & 3;
    const int bm = blockIdx.y * 128, bn = blockIdx.x * 128;

    const int la_m = tid >> 1, la_k = (tid & 1) * 16;
    const float* Ap = A + (size_t)(bm + la_m) * K + la_k;
    const float* Bp = W + bn + lane * 4;
    const int kr0 = 2 * warp, kr1 = 2 * warp + 1;
    const int kr2 = 2 * warp + 16, kr3 = 2 * warp + 17;

    float4 ar[4], br[4];
    #pragma unroll
    for (int j = 0; j < 4; j++) ar[j] = *(const float4*)(Ap + 4 * j);
    br[0] = *(const float4*)(Bp + (size_t)kr0 * N);
    br[1] = *(const float4*)(Bp + (size_t)kr1 * N);
    br[2] = *(const float4*)(Bp + (size_t)kr2 * N);
    br[3] = *(const float4*)(Bp + (size_t)kr3 * N);

    float acc[4][4][4];
    #pragma unroll
    for (int i = 0; i < 4; i++)
        #pragma unroll
        for (int j = 0; j < 4; j++)
            #pragma unroll
            for (int c = 0; c < 4; c++) acc[i][j][c] = 0.f;

    for (int kt = 0; kt < K; kt += 32) {
        #pragma unroll
        for (int j = 0; j < 4; j++) {
            float4 x = ar[j];
            float hx = bfhi(x.x), hy = bfhi(x.y), hz = bfhi(x.z), hw = bfhi(x.w);
            uint2 hh = make_uint2(packbf(hx, hy), packbf(hz, hw));
            uint2 ll = make_uint2(packbf(x.x - hx, x.y - hy), packbf(x.z - hz, x.w - hw));
            int off = la_m * AS + (la_k >> 1) + 2 * j;
            *(uint2*)&Ah[off] = hh;
            *(uint2*)&Al[off] = ll;
        }
        {
            uint4 h0, l0, h1, l1;
            #pragma unroll
            for (int e = 0; e < 4; e++) {
                float a0 = ((const float*)&br[0])[e], a1 = ((const float*)&br[1])[e];
                float b0 = ((const float*)&br[2])[e], b1 = ((const float*)&br[3])[e];
                float ha0 = bfhi(a0), ha1 = bfhi(a1), hb0 = bfhi(b0), hb1 = bfhi(b1);
                ((uint32_t*)&h0)[e] = packbf(ha0, ha1);
                ((uint32_t*)&l0)[e] = packbf(a0 - ha0, a1 - ha1);
                ((uint32_t*)&h1)[e] = packbf(hb0, hb1);
                ((uint32_t*)&l1)[e] = packbf(b0 - hb0, b1 - hb1);
            }
            *(uint4*)&Bh[warp * BS + 4 * lane]       = h0;
            *(uint4*)&Bl[warp * BS + 4 * lane]       = l0;
            *(uint4*)&Bh[(warp + 8) * BS + 4 * lane] = h1;
            *(uint4*)&Bl[(warp + 8) * BS + 4 * lane] = l1;
        }
        __syncthreads();

        if (kt + 32 < K) {
            #pragma unroll
            for (int j = 0; j < 4; j++) ar[j] = *(const float4*)(Ap + kt + 32 + 4 * j);
            br[0] = *(const float4*)(Bp + (size_t)(kt + 32 + kr0) * N);
            br[1] = *(const float4*)(Bp + (size_t)(kt + 32 + kr1) * N);
            br[2] = *(const float4*)(Bp + (size_t)(kt + 32 + kr2) * N);
            br[3] = *(const float4*)(Bp + (size_t)(kt + 32 + kr3) * N);
        }

        #pragma unroll
        for (int s = 0; s < 2; s++) {
            const int s8 = s * 8;
            #pragma unroll
            for (int t = 0; t < 3; t++) {
                const uint32_t* Aq = (t == 2) ? Al : Ah;
                const uint32_t* Bq = (t == 1) ? Bl : Bh;
                uint32_t af[4][4];
                #pragma unroll
                for (int i = 0; i < 4; i++) {
                    const int r0 = (wm + i * 16 + gid) * AS + s8;
                    const int r1 = r0 + 8 * AS;
                    af[i][0] = Aq[r0 + tig];     af[i][1] = Aq[r1 + tig];
                    af[i][2] = Aq[r0 + tig + 4]; af[i][3] = Aq[r1 + tig + 4];
                }
                #pragma unroll
                for (int j = 0; j < 4; j++) {
                    const int cb = wn + j * 8 + gid;
                    uint32_t b2[2] = {Bq[(s8 + tig) * BS + cb],
                                      Bq[(s8 + tig + 4) * BS + cb]};
                    #pragma unroll
                    for (int i = 0; i < 4; i++) mma_bf16(acc[i][j], af[i], b2);
                }
            }
        }
        __syncthreads();
    }

    #pragma unroll
    for (int j = 0; j < 4; j++) {
        const int col = bn + wn + j * 8 + tig * 2;
        const float b0 = bias[col], b1 = bias[col + 1];
        #pragma unroll
        for (int i = 0; i < 4; i++) {
            const int row0 = bm + wm + i * 16 + gid;
            if (POUT) {
                const int dp = (col & 127) >> 1;
                #pragma unroll
                for (int half = 0; half < 2; half++) {
                    const int row = row0 + 8 * half;
                    const float v0 = acc[i][j][2 * half]     + b0;
                    const float v1 = acc[i][j][2 * half + 1] + b1;
                    const float h0 = bfhi(v0), h1 = bfhi(v1);
                    const int bb = row >> 11;
                    const int rr = row & (T_ - 1);
                    const int hh = rr >> 7;
                    const int t  = ((rr & 127) << 4) | (col >> 7);
                    const size_t o = ((size_t)(bb * NH_ + hh) * T_ + t) * 64 + dp;
                    Ph[o] = packbf(h0, h1);
                    Pl[o] = packbf(v0 - h0, v1 - h1);
                }
            } else {
                *(float2*)&C[(size_t)row0 * N + col]       = make_float2(acc[i][j][0] + b0, acc[i][j][1] + b1);
                *(float2*)&C[(size_t)(row0 + 8) * N + col] = make_float2(acc[i][j][2] + b0, acc[i][j][3] + b1);
            }
        }
    }
}

// ---------------------------------------------------------------------------
// fp16 single-plane GEMM (V/O projections) — unchanged from round 15.
// ---------------------------------------------------------------------------
__global__ void __launch_bounds__(256, 2)
gemm_fp16(const float* __restrict__ A, const float* __restrict__ W,
          const float* __restrict__ bias, float* __restrict__ C,
          int M, int N, int K)
{
    constexpr int AS = 20;
    constexpr int BS = 132;
    __shared__ uint32_t Ah[128 * AS];
    __shared__ uint32_t Bh[16 * BS];

    const int tid = threadIdx.x, lane = tid & 31, warp = tid >> 5;
    const int wm = (warp >> 2) * 64, wn = (warp & 3) * 32;
    const int gid = lane >> 2, tig = lane & 3;
    const int bm = blockIdx.y * 128, bn = blockIdx.x * 128;

    const int la_m = tid >> 1, la_k = (tid & 1) * 16;
    const float* Ap = A + (size_t)(bm + la_m) * K + la_k;
    const float* Bp = W + bn + lane * 4;
    const int kr0 = 2 * warp, kr1 = 2 * warp + 1;
    const int kr2 = 2 * warp + 16, kr3 = 2 * warp + 17;

    float4 ar[4], br[4];
    #pragma unroll
    for (int j = 0; j < 4; j++) ar[j] = *(const float4*)(Ap + 4 * j);
    br[0] = *(const float4*)(Bp + (size_t)kr0 * N);
    br[1] = *(const float4*)(Bp + (size_t)kr1 * N);
    br[2] = *(const float4*)(Bp + (size_t)kr2 * N);
    br[3] = *(const float4*)(Bp + (size_t)kr3 * N);

    float acc[4][4][4];
    #pragma unroll
    for (int i = 0; i < 4; i++)
        #pragma unroll
        for (int j = 0; j < 4; j++)
            #pragma unroll
            for (int c = 0; c < 4; c++) acc[i][j][c] = 0.f;

    for (int kt = 0; kt < K; kt += 32) {
        #pragma unroll
        for (int j = 0; j < 4; j++) {
            float4 x = ar[j];
            uint2 hh = make_uint2(packh(x.x, x.y), packh(x.z, x.w));
            *(uint2*)&Ah[la_m * AS + (la_k >> 1) + 2 * j] = hh;
        }
        {
            uint4 h0, h1;
            #pragma unroll
            for (int e = 0; e < 4; e++) {
                ((uint32_t*)&h0)[e] = packh(((const float*)&br[0])[e], ((const float*)&br[1])[e]);
                ((uint32_t*)&h1)[e] = packh(((const float*)&br[2])[e], ((const float*)&br[3])[e]);
            }
            *(uint4*)&Bh[warp * BS + 4 * lane]       = h0;
            *(uint4*)&Bh[(warp + 8) * BS + 4 * lane] = h1;
        }
        __syncthreads();

        if (kt + 32 < K) {
            #pragma unroll
            for (int j = 0; j < 4; j++) ar[j] = *(const float4*)(Ap + kt + 32 + 4 * j);
            br[0] = *(const float4*)(Bp + (size_t)(kt + 32 + kr0) * N);
            br[1] = *(const float4*)(Bp + (size_t)(kt + 32 + kr1) * N);
            br[2] = *(const float4*)(Bp + (size_t)(kt + 32 + kr2) * N);
            br[3] = *(const float4*)(Bp + (size_t)(kt + 32 + kr3) * N);
        }

        #pragma unroll
        for (int s = 0; s < 2; s++) {
            const int s8 = s * 8;
            uint32_t ah[4][4];
            #pragma unroll
            for (int i = 0; i < 4; i++) {
                const int r0 = (wm + i * 16 + gid) * AS + s8;
                const int r1 = r0 + 8 * AS;
                ah[i][0] = Ah[r0 + tig];     ah[i][1] = Ah[r1 + tig];
                ah[i][2] = Ah[r0 + tig + 4]; ah[i][3] = Ah[r1 + tig + 4];
            }
            #pragma unroll
            for (int j = 0; j < 4; j++) {
                const int cb = wn + j * 8 + gid;
                uint32_t bh[2] = {Bh[(s8 + tig) * BS + cb], Bh[(s8 + tig + 4) * BS + cb]};
                #pragma unroll
                for (int i = 0; i < 4; i++) mma_fp16(acc[i][j], ah[i], bh);
            }
        }
        __syncthreads();
    }

    #pragma unroll
    for (int j = 0; j < 4; j++) {
        const int col = bn + wn + j * 8 + tig * 2;
        const float b0 = bias[col], b1 = bias[col + 1];
        #pragma unroll
        for (int i = 0; i < 4; i++) {
            const int row = bm + wm + i * 16 + gid;
            *(float2*)&C[(size_t)row * N + col]       = make_float2(acc[i][j][0] + b0, acc[i][j][1] + b1);
            *(float2*)&C[(size_t)(row + 8) * N + col] = make_float2(acc[i][j][2] + b0, acc[i][j][3] + b1);
        }
    }
}

// ---------------- RoPE + operand prep (unchanged) ----------------
__global__ void rope_split(const float* __restrict__ k, const float* __restrict__ v,
                           uint32_t* __restrict__ kh, uint32_t* __restrict__ kl,
                           uint32_t* __restrict__ vt)
{
    int p = blockIdx.x * 256 + threadIdx.x;
    int d2 = p & 63, rr = p >> 6, t = rr & (T_ - 1);
    double th = exp2((double)d2 * -0.20762050593046014);
    float angf = (float)t * (float)th;
    float s, c;
    sincosf(angf, &s, &c);
    size_t base = (size_t)rr * HD_ + 2 * d2;
    float2 kk = *(const float2*)(k + base), vv = *(const float2*)(v + base);
    float kx = kk.x * c - kk.y * s, ky = kk.x * s + kk.y * c;
    float vx = vv.x * c - vv.y * s, vy = vv.x * s + vv.y * c;
    float hx = bfhi(kx), hy = bfhi(ky);
    kh[(size_t)rr * 64 + d2] = packbf(hx, hy);
    kl[(size_t)rr * 64 + d2] = packbf(kx - hx, ky - hy);
    vt[(size_t)rr * 64 + d2] = packh(vx, vy);
}

// ---------------- Flash attention: 128q x 64k, warp-local softmax ----------
// 8 warps, warp w owns q rows [16w,16w+16) x ALL 64 k cols.
// S: bf16 3-term.  P stays in registers (C-frag == A-frag layout).  PV: fp16.
// 2 barriers/iter (K/V reuse only).  1 CTA/SM, regs up to 255.
constexpr int BST = 68;
constexpr int VST = 132;

__global__ void __launch_bounds__(256, 1)
flash_mma(const uint32_t* __restrict__ Qh, const uint32_t* __restrict__ Ql,
          const uint32_t* __restrict__ Kh, const uint32_t* __restrict__ Kl,
          const uint32_t* __restrict__ Vt, const int* __restrict__ mask,
          float* __restrict__ O)
{
    extern __shared__ uint32_t s4[];
    uint32_t* sQh = s4;                // 128*BST
    uint32_t* sQl = sQh + 128 * BST;
    uint32_t* sKh = sQl + 128 * BST;   // 64*BST
    uint32_t* sKl = sKh + 64 * BST;
    uint32_t* sVs = sKl + 64 * BST;    // 32*VST

    const int tid = threadIdx.x, lane = tid & 31, warp = tid >> 5;
    const int gid = lane >> 2, tig = lane & 3;
    const int q0 = blockIdx.x * 128, h = blockIdx.y, b = blockIdx.z;
    const int kh = h & (NKV_ - 1);
    const int lr = warp * 16 + gid;    // local q row (first of the pair)

    const uint32_t* qhb = Qh + ((size_t)b * NH_  + h ) * ((size_t)T_ * 64) + (size_t)q0 * 64;
    const uint32_t* qlb = Ql + ((size_t)b * NH_  + h ) * ((size_t)T_ * 64) + (size_t)q0 * 64;
    const uint32_t* khb = Kh + ((size_t)b * NKV_ + kh) * ((size_t)T_ * 64);
    const uint32_t* klb = Kl + ((size_t)b * NKV_ + kh) * ((size_t)T_ * 64);
    const uint32_t* vtb = Vt + ((size_t)b * NKV_ + kh) * ((size_t)T_ * 64);
    const int*      mb  = mask + (size_t)b * T_ * T_;

    // Q planes (128 rows): pure copy
    #pragma unroll
    for (int i = 0; i < 8; i++) {
        int idx = i * 256 + tid;
        int r = idx >> 4, c = (idx & 15) * 4;
        *(uint4*)&sQh[r * BST + c] = *(const uint4*)(qhb + r * 64 + c);
        *(uint4*)&sQl[r * BST + c] = *(const uint4*)(qlb + r * 64 + c);
    }

    float m0 = -1e30f, m1 = -1e30f, l0 = 0.f, l1 = 0.f;
    float oacc[16][4];
    #pragma unroll
    for (int j = 0; j < 16; j++)
        #pragma unroll
        for (int c = 0; c < 4; c++) oacc[j][c] = 0.f;

    for (int k0 = 0; k0 < T_; k0 += 64) {
        // prefetch mask (rows lr, lr+8 x 64 cols) and K tile into registers
        int2 mq0[8], mq1[8];
        #pragma unroll
        for (int j = 0; j < 8; j++) {
            const int col = k0 + j * 8 + 2 * tig;
            mq0[j] = *(const int2*)(mb + (size_t)(q0 + lr)     * T_ + col);
            mq1[j] = *(const int2*)(mb + (size_t)(q0 + lr + 8) * T_ + col);
        }
        uint4 krh[4], krl[4];
        #pragma unroll
        for (int i = 0; i < 4; i++) {
            int idx = i * 256 + tid;
            int r = idx >> 4, c = (idx & 15) * 4;
            krh[i] = *(const uint4*)(khb + (size_t)(k0 + r) * 64 + c);
            krl[i] = *(const uint4*)(klb + (size_t)(k0 + r) * 64 + c);
        }
        __syncthreads();   // all warps done reading prior K/V tiles
        #pragma unroll
        for (int i = 0; i < 4; i++) {
            int idx = i * 256 + tid;
            int r = idx >> 4, c = (idx & 15) * 4;
            *(uint4*)&sKh[r * BST + c] = krh[i];
            *(uint4*)&sKl[r * BST + c] = krl[i];
        }
        #pragma unroll
        for (int i = 0; i < 8; i++) {
            int idx = i * 256 + tid;
            int tp = idx >> 6, d2 = idx & 63;
            uint32_t va = vtb[(size_t)(k0 + 2 * tp) * 64 + d2];
            uint32_t vb = vtb[(size_t)(k0 + 2 * tp + 1) * 64 + d2];
            uint32_t lo = __byte_perm(va, vb, 0x5410);
            uint32_t hi = __byte_perm(va, vb, 0x7632);
            *(uint2*)&sVs[tp * VST + 2 * d2] = make_uint2(lo, hi);
        }
        __syncthreads();

        // S = Q K^T over all 64 cols (bf16 3-term, term-outer)
        float sacc[8][4];
        #pragma unroll
        for (int j = 0; j < 8; j++)
            #pragma unroll
            for (int c = 0; c < 4; c++) sacc[j][c] = 0.f;

        #pragma unroll
        for (int s = 0; s < 8; s++) {
            const int qa = lr * BST + 8 * s;
            uint32_t ah[4] = {sQh[qa + tig], sQh[qa + 8 * BST + tig],
                              sQh[qa + tig + 4], sQh[qa + 8 * BST + tig + 4]};
            uint32_t al[4] = {sQl[qa + tig], sQl[qa + 8 * BST + tig],
                              sQl[qa + tig + 4], sQl[qa + 8 * BST + tig + 4]};
            uint32_t bh[8][2], bl[8][2];
            #pragma unroll
            for (int j = 0; j < 8; j++) {
                const int kb2 = (j * 8 + gid) * BST + 8 * s;
                bh[j][0] = sKh[kb2 + tig]; bh[j][1] = sKh[kb2 + tig + 4];
                bl[j][0] = sKl[kb2 + tig]; bl[j][1] = sKl[kb2 + tig + 4];
            }
            #pragma unroll
            for (int j = 0; j < 8; j++) mma_bf16(sacc[j], ah, bh[j]);
            #pragma unroll
            for (int j = 0; j < 8; j++) mma_bf16(sacc[j], ah, bl[j]);
            #pragma unroll
            for (int j = 0; j < 8; j++) mma_bf16(sacc[j], al, bh[j]);
        }

        // mask + scale + warp-local row max (quad shuffles over tig)
        float mx0 = -1e30f, mx1 = -1e30f;
        #pragma unroll
        for (int j = 0; j < 8; j++) {
            sacc[j][0] = mq0[j].x ? sacc[j][0] * SCL2_ : MSK2_;
            sacc[j][1] = mq0[j].y ? sacc[j][1] * SCL2_ : MSK2_;
            sacc[j][2] = mq1[j].x ? sacc[j][2] * SCL2_ : MSK2_;
            sacc[j][3] = mq1[j].y ? sacc[j][3] * SCL2_ : MSK2_;
            mx0 = fmaxf(mx0, fmaxf(sacc[j][0], sacc[j][1]));
            mx1 = fmaxf(mx1, fmaxf(sacc[j][2], sacc[j][3]));
        }
        mx0 = fmaxf(mx0, __shfl_xor_sync(0xffffffffu, mx0, 1));
        mx0 = fmaxf(mx0, __shfl_xor_sync(0xffffffffu, mx0, 2));
        mx1 = fmaxf(mx1, __shfl_xor_sync(0xffffffffu, mx1, 1));
        mx1 = fmaxf(mx1, __shfl_xor_sync(0xffffffffu, mx1, 2));

        float mn0 = fmaxf(m0, mx0);
        float mn1 = fmaxf(m1, mx1);
        float a0 = ex2f(m0 - mn0), a1 = ex2f(m1 - mn1);
        m0 = mn0; m1 = mn1;

        // exp2 + register-resident P fragments (C-frag layout == A-frag layout)
        float sum0 = 0.f, sum1 = 0.f;
        uint32_t pa[4][4];
        #pragma unroll
        for (int s2 = 0; s2 < 4; s2++) {
            const int j0 = 2 * s2, j1 = 2 * s2 + 1;
            float p00 = ex2f(sacc[j0][0] - mn0), p01 = ex2f(sacc[j0][1] - mn0);
            float p02 = ex2f(sacc[j0][2] - mn1), p03 = ex2f(sacc[j0][3] - mn1);
            float p10 = ex2f(sacc[j1][0] - mn0), p11 = ex2f(sacc[j1][1] - mn0);
            float p12 = ex2f(sacc[j1][2] - mn1), p13 = ex2f(sacc[j1][3] - mn1);
            sum0 += p00 + p01 + p10 + p11;
            sum1 += p02 + p03 + p12 + p13;
            pa[s2][0] = packh(p00, p01);   // row lr,   k-cols 16s2+2tig..
            pa[s2][1] = packh(p02, p03);   // row lr+8, same k
            pa[s2][2] = packh(p10, p11);   // row lr,   k+8
            pa[s2][3] = packh(p12, p13);   // row lr+8, k+8
        }
        sum0 += __shfl_xor_sync(0xffffffffu, sum0, 1);
        sum0 += __shfl_xor_sync(0xffffffffu, sum0, 2);
        sum1 += __shfl_xor_sync(0xffffffffu, sum1, 1);
        sum1 += __shfl_xor_sync(0xffffffffu, sum1, 2);
        l0 = l0 * a0 + sum0;
        l1 = l1 * a1 + sum1;
        #pragma unroll
        for (int j = 0; j < 16; j++) {
            oacc[j][0] *= a0; oacc[j][1] *= a0;
            oacc[j][2] *= a1; oacc[j][3] *= a1;
        }

        // O += P V  (fp16, P from registers — no barrier needed)
        #pragma unroll
        for (int s2 = 0; s2 < 4; s2++) {
            #pragma unroll
            for (int j = 0; j < 16; j++) {
                const int vn = j * 8 + gid;
                uint32_t vbf[2] = {sVs[(8 * s2 + tig) * VST + vn],
                                   sVs[(8 * s2 + tig + 4) * VST + vn]};
                mma_fp16(oacc[j], pa[s2], vbf);
            }
        }
    }

    const float inv0 = 1.f / l0;
    const float inv1 = 1.f / l1;
    float* ob = O + ((size_t)b * T_ + q0 + lr) * E_ + h * HD_ + 2 * tig;
    #pragma unroll
    for (int j = 0; j < 16; j++) {
        *(float2*)(ob + j * 8)                  = make_float2(oacc[j][0] * inv0, oacc[j][1] * inv0);
        *(float2*)(ob + 8 * (size_t)E_ + j * 8) = make_float2(oacc[j][2] * inv1, oacc[j][3] * inv1);
    }
}

// ---------------- launcher ----------------
extern "C" void kernel_launch(void* const* d_in, const int* in_sizes, int n_in,
                              void* d_out, int out_size)
{
    const float* x  = (const float*)d_in[0];
    const int*   am = (const int*)  d_in[1];
    const float* Wq = (const float*)d_in[2];
    const float* bq = (const float*)d_in[3];
    const float* Wk = (const float*)d_in[4];
    const float* bk = (const float*)d_in[5];
    const float* Wv = (const float*)d_in[6];
    const float* bv = (const float*)d_in[7];
    const float* Wo = (const float*)d_in[8];
    const float* bo = (const float*)d_in[9];
    float* out = (float*)d_out;

    float *k, *v, *att;
    uint32_t *qh, *ql, *kh, *kl, *vt;
    cudaGetSymbolAddress((void**)&k,   g_k);
    cudaGetSymbolAddress((void**)&v,   g_v);
    cudaGetSymbolAddress((void**)&att, g_att);
    cudaGetSymbolAddress((void**)&qh,  g_qh);
    cudaGetSymbolAddress((void**)&ql,  g_ql);
    cudaGetSymbolAddress((void**)&kh,  g_kh);
    cudaGetSymbolAddress((void**)&kl,  g_kl);
    cudaGetSymbolAddress((void**)&vt,  g_vt);

    const int M = B_ * T_;

    gemm_bf16<true ><<<dim3(E_ / 128,   M / 128), 256>>>(x, Wq, bq, nullptr, qh, ql, M, E_,   E_);
    gemm_bf16<false><<<dim3(KVD_ / 128, M / 128), 256>>>(x, Wk, bk, k, qh, ql, M, KVD_, E_);
    gemm_fp16<<<dim3(KVD_ / 128, M / 128), 256>>>(x, Wv, bv, v, M, KVD_, E_);

    rope_split<<<(B_ * NKV_ * T_ * 64) / 256, 256>>>(k, v, kh, kl, vt);

    const int fsmem = (2 * 128 * BST + 2 * 64 * BST + 32 * VST) * 4;  // 121344 B
    cudaFuncSetAttribute(flash_mma, cudaFuncAttributeMaxDynamicSharedMemorySize, fsmem);
    flash_mma<<<dim3(T_ / 128, NH_, B_), 256, fsmem>>>(qh, ql, kh, kl, vt, am, att);

    gemm_fp16<<<dim3(E_ / 128, M / 128), 256>>>(att, Wo, bo, out, M, E_, E_);
}

// round 17
// speedup vs baseline: 4.5113x; 1.0351x over previous
#include <cuda_runtime.h>
#include <cuda_bf16.h>
#include <cuda_fp16.h>
#include <math.h>
#include <stdint.h>

constexpr int B_   = 4;
constexpr int T_   = 2048;
constexpr int E_   = 2048;
constexpr int NH_  = 16;
constexpr int NKV_ = 4;
constexpr int HD_  = 128;
constexpr int KVD_ = NKV_ * HD_;
constexpr float SCL2_ = 16.32232319089277f;     // sqrt(128) * log2(e)
constexpr float MSK2_ = 1.4426950408889634e-9f; // 1e-9 * log2(e)

__device__ float g_k[(size_t)B_ * T_ * KVD_];
__device__ float g_v[(size_t)B_ * T_ * KVD_];
__device__ float g_att[(size_t)B_ * T_ * E_];
__device__ uint32_t g_qh[(size_t)B_ * NH_  * T_ * 64];
__device__ uint32_t g_ql[(size_t)B_ * NH_  * T_ * 64];
__device__ uint32_t g_kh[(size_t)B_ * NKV_ * T_ * 64];
__device__ uint32_t g_kl[(size_t)B_ * NKV_ * T_ * 64];
__device__ uint32_t g_vt[(size_t)B_ * NKV_ * (T_ / 2) * 128]; // V fp16 token-pair-major

// ---------------- helpers ----------------
__device__ __forceinline__ float bfhi(float f) {
    return __bfloat162float(__float2bfloat16(f));
}
__device__ __forceinline__ uint32_t packbf(float f0, float f1) {
    __nv_bfloat162 h = __floats2bfloat162_rn(f0, f1);
    return *(uint32_t*)&h;
}
__device__ __forceinline__ uint32_t packh(float f0, float f1) {
    __half2 h = __floats2half2_rn(f0, f1);
    return *(uint32_t*)&h;
}
__device__ __forceinline__ float ex2f(float x) {
    float r; asm("ex2.approx.f32 %0, %1;" : "=f"(r) : "f"(x)); return r;
}
__device__ __forceinline__ void mma_bf16(float c[4], const uint32_t a[4], const uint32_t b[2]) {
    asm volatile("mma.sync.aligned.m16n8k16.row.col.f32.bf16.bf16.f32 "
        "{%0,%1,%2,%3}, {%4,%5,%6,%7}, {%8,%9}, {%0,%1,%2,%3};"
        : "+f"(c[0]), "+f"(c[1]), "+f"(c[2]), "+f"(c[3])
        : "r"(a[0]), "r"(a[1]), "r"(a[2]), "r"(a[3]), "r"(b[0]), "r"(b[1]));
}
__device__ __forceinline__ void mma_fp16(float c[4], const uint32_t a[4], const uint32_t b[2]) {
    asm volatile("mma.sync.aligned.m16n8k16.row.col.f32.f16.f16.f32 "
        "{%0,%1,%2,%3}, {%4,%5,%6,%7}, {%8,%9}, {%0,%1,%2,%3};"
        : "+f"(c[0]), "+f"(c[1]), "+f"(c[2]), "+f"(c[3])
        : "r"(a[0]), "r"(a[1]), "r"(a[2]), "r"(a[3]), "r"(b[0]), "r"(b[1]));
}

constexpr int AS = 20;    // A smem row stride (u32)
constexpr int BS = 132;   // B smem kpair-row stride (u32)
constexpr int GEMM_SMEM_U32 = 2 * 128 * AS + 2 * 16 * BS;  // 9344 u32 = 37376 B

// ---------------------------------------------------------------------------
// bf16 2-plane / 3-term GEMM body (Q/K projections). POUT: planes out in the
// reshape-view layout: rr=row%T; h=rr>>7; t=((rr&127)<<4)|(col>>7); d=col&127.
// ---------------------------------------------------------------------------
template<bool POUT>
__device__ __forceinline__ void gemm_bf16_body(
    const float* __restrict__ A, const float* __restrict__ W,
    const float* __restrict__ bias, float* __restrict__ C,
    uint32_t* __restrict__ Ph, uint32_t* __restrict__ Pl,
    int M, int N, int K, int bxe, int bye, uint32_t* sm)
{
    uint32_t* Ah = sm;
    uint32_t* Al = Ah + 128 * AS;
    uint32_t* Bh = Al + 128 * AS;
    uint32_t* Bl = Bh + 16 * BS;

    const int tid = threadIdx.x, lane = tid & 31, warp = tid >> 5;
    const int wm = (warp >> 2) * 64, wn = (warp & 3) * 32;
    const int gid = lane >> 2, tig = lane & 3;
    const int bm = bye * 128, bn = bxe * 128;

    const int la_m = tid >> 1, la_k = (tid & 1) * 16;
    const float* Ap = A + (size_t)(bm + la_m) * K + la_k;
    const float* Bp = W + bn + lane * 4;
    const int kr0 = 2 * warp, kr1 = 2 * warp + 1;
    const int kr2 = 2 * warp + 16, kr3 = 2 * warp + 17;

    float4 ar[4], br[4];
    #pragma unroll
    for (int j = 0; j < 4; j++) ar[j] = *(const float4*)(Ap + 4 * j);
    br[0] = *(const float4*)(Bp + (size_t)kr0 * N);
    br[1] = *(const float4*)(Bp + (size_t)kr1 * N);
    br[2] = *(const float4*)(Bp + (size_t)kr2 * N);
    br[3] = *(const float4*)(Bp + (size_t)kr3 * N);

    float acc[4][4][4];
    #pragma unroll
    for (int i = 0; i < 4; i++)
        #pragma unroll
        for (int j = 0; j < 4; j++)
            #pragma unroll
            for (int c = 0; c < 4; c++) acc[i][j][c] = 0.f;

    for (int kt = 0; kt < K; kt += 32) {
        #pragma unroll
        for (int j = 0; j < 4; j++) {
            float4 x = ar[j];
            float hx = bfhi(x.x), hy = bfhi(x.y), hz = bfhi(x.z), hw = bfhi(x.w);
            uint2 hh = make_uint2(packbf(hx, hy), packbf(hz, hw));
            uint2 ll = make_uint2(packbf(x.x - hx, x.y - hy), packbf(x.z - hz, x.w - hw));
            int off = la_m * AS + (la_k >> 1) + 2 * j;
            *(uint2*)&Ah[off] = hh;
            *(uint2*)&Al[off] = ll;
        }
        {
            uint4 h0, l0, h1, l1;
            #pragma unroll
            for (int e = 0; e < 4; e++) {
                float a0 = ((const float*)&br[0])[e], a1 = ((const float*)&br[1])[e];
                float b0 = ((const float*)&br[2])[e], b1 = ((const float*)&br[3])[e];
                float ha0 = bfhi(a0), ha1 = bfhi(a1), hb0 = bfhi(b0), hb1 = bfhi(b1);
                ((uint32_t*)&h0)[e] = packbf(ha0, ha1);
                ((uint32_t*)&l0)[e] = packbf(a0 - ha0, a1 - ha1);
                ((uint32_t*)&h1)[e] = packbf(hb0, hb1);
                ((uint32_t*)&l1)[e] = packbf(b0 - hb0, b1 - hb1);
            }
            *(uint4*)&Bh[warp * BS + 4 * lane]       = h0;
            *(uint4*)&Bl[warp * BS + 4 * lane]       = l0;
            *(uint4*)&Bh[(warp + 8) * BS + 4 * lane] = h1;
            *(uint4*)&Bl[(warp + 8) * BS + 4 * lane] = l1;
        }
        __syncthreads();

        if (kt + 32 < K) {
            #pragma unroll
            for (int j = 0; j < 4; j++) ar[j] = *(const float4*)(Ap + kt + 32 + 4 * j);
            br[0] = *(const float4*)(Bp + (size_t)(kt + 32 + kr0) * N);
            br[1] = *(const float4*)(Bp + (size_t)(kt + 32 + kr1) * N);
            br[2] = *(const float4*)(Bp + (size_t)(kt + 32 + kr2) * N);
            br[3] = *(const float4*)(Bp + (size_t)(kt + 32 + kr3) * N);
        }

        #pragma unroll
        for (int s = 0; s < 2; s++) {
            const int s8 = s * 8;
            #pragma unroll
            for (int t = 0; t < 3; t++) {
                const uint32_t* Aq = (t == 2) ? Al : Ah;
                const uint32_t* Bq = (t == 1) ? Bl : Bh;
                uint32_t af[4][4];
                #pragma unroll
                for (int i = 0; i < 4; i++) {
                    const int r0 = (wm + i * 16 + gid) * AS + s8;
                    const int r1 = r0 + 8 * AS;
                    af[i][0] = Aq[r0 + tig];     af[i][1] = Aq[r1 + tig];
                    af[i][2] = Aq[r0 + tig + 4]; af[i][3] = Aq[r1 + tig + 4];
                }
                #pragma unroll
                for (int j = 0; j < 4; j++) {
                    const int cb = wn + j * 8 + gid;
                    uint32_t b2[2] = {Bq[(s8 + tig) * BS + cb],
                                      Bq[(s8 + tig + 4) * BS + cb]};
                    #pragma unroll
                    for (int i = 0; i < 4; i++) mma_bf16(acc[i][j], af[i], b2);
                }
            }
        }
        __syncthreads();
    }

    #pragma unroll
    for (int j = 0; j < 4; j++) {
        const int col = bn + wn + j * 8 + tig * 2;
        const float b0 = bias[col], b1 = bias[col + 1];
        #pragma unroll
        for (int i = 0; i < 4; i++) {
            const int row0 = bm + wm + i * 16 + gid;
            if (POUT) {
                const int dp = (col & 127) >> 1;
                #pragma unroll
                for (int half = 0; half < 2; half++) {
                    const int row = row0 + 8 * half;
                    const float v0 = acc[i][j][2 * half]     + b0;
                    const float v1 = acc[i][j][2 * half + 1] + b1;
                    const float h0 = bfhi(v0), h1 = bfhi(v1);
                    const int bb = row >> 11;
                    const int rr = row & (T_ - 1);
                    const int hh = rr >> 7;
                    const int t  = ((rr & 127) << 4) | (col >> 7);
                    const size_t o = ((size_t)(bb * NH_ + hh) * T_ + t) * 64 + dp;
                    Ph[o] = packbf(h0, h1);
                    Pl[o] = packbf(v0 - h0, v1 - h1);
                }
            } else {
                *(float2*)&C[(size_t)row0 * N + col]       = make_float2(acc[i][j][0] + b0, acc[i][j][1] + b1);
                *(float2*)&C[(size_t)(row0 + 8) * N + col] = make_float2(acc[i][j][2] + b0, acc[i][j][3] + b1);
            }
        }
    }
}

// ---------------------------------------------------------------------------
// fp16 single-plane GEMM body (V/O projections).
// ---------------------------------------------------------------------------
__device__ __forceinline__ void gemm_fp16_body(
    const float* __restrict__ A, const float* __restrict__ W,
    const float* __restrict__ bias, float* __restrict__ C,
    int M, int N, int K, int bxe, int bye, uint32_t* sm)
{
    uint32_t* Ah = sm;
    uint32_t* Bh = Ah + 128 * AS;

    const int tid = threadIdx.x, lane = tid & 31, warp = tid >> 5;
    const int wm = (warp >> 2) * 64, wn = (warp & 3) * 32;
    const int gid = lane >> 2, tig = lane & 3;
    const int bm = bye * 128, bn = bxe * 128;

    const int la_m = tid >> 1, la_k = (tid & 1) * 16;
    const float* Ap = A + (size_t)(bm + la_m) * K + la_k;
    const float* Bp = W + bn + lane * 4;
    const int kr0 = 2 * warp, kr1 = 2 * warp + 1;
    const int kr2 = 2 * warp + 16, kr3 = 2 * warp + 17;

    float4 ar[4], br[4];
    #pragma unroll
    for (int j = 0; j < 4; j++) ar[j] = *(const float4*)(Ap + 4 * j);
    br[0] = *(const float4*)(Bp + (size_t)kr0 * N);
    br[1] = *(const float4*)(Bp + (size_t)kr1 * N);
    br[2] = *(const float4*)(Bp + (size_t)kr2 * N);
    br[3] = *(const float4*)(Bp + (size_t)kr3 * N);

    float acc[4][4][4];
    #pragma unroll
    for (int i = 0; i < 4; i++)
        #pragma unroll
        for (int j = 0; j < 4; j++)
            #pragma unroll
            for (int c = 0; c < 4; c++) acc[i][j][c] = 0.f;

    for (int kt = 0; kt < K; kt += 32) {
        #pragma unroll
        for (int j = 0; j < 4; j++) {
            float4 x = ar[j];
            uint2 hh = make_uint2(packh(x.x, x.y), packh(x.z, x.w));
            *(uint2*)&Ah[la_m * AS + (la_k >> 1) + 2 * j] = hh;
        }
        {
            uint4 h0, h1;
            #pragma unroll
            for (int e = 0; e < 4; e++) {
                ((uint32_t*)&h0)[e] = packh(((const float*)&br[0])[e], ((const float*)&br[1])[e]);
                ((uint32_t*)&h1)[e] = packh(((const float*)&br[2])[e], ((const float*)&br[3])[e]);
            }
            *(uint4*)&Bh[warp * BS + 4 * lane]       = h0;
            *(uint4*)&Bh[(warp + 8) * BS + 4 * lane] = h1;
        }
        __syncthreads();

        if (kt + 32 < K) {
            #pragma unroll
            for (int j = 0; j < 4; j++) ar[j] = *(const float4*)(Ap + kt + 32 + 4 * j);
            br[0] = *(const float4*)(Bp + (size_t)(kt + 32 + kr0) * N);
            br[1] = *(const float4*)(Bp + (size_t)(kt + 32 + kr1) * N);
            br[2] = *(const float4*)(Bp + (size_t)(kt + 32 + kr2) * N);
            br[3] = *(const float4*)(Bp + (size_t)(kt + 32 + kr3) * N);
        }

        #pragma unroll
        for (int s = 0; s < 2; s++) {
            const int s8 = s * 8;
            uint32_t ah[4][4];
            #pragma unroll
            for (int i = 0; i < 4; i++) {
                const int r0 = (wm + i * 16 + gid) * AS + s8;
                const int r1 = r0 + 8 * AS;
                ah[i][0] = Ah[r0 + tig];     ah[i][1] = Ah[r1 + tig];
                ah[i][2] = Ah[r0 + tig + 4]; ah[i][3] = Ah[r1 + tig + 4];
            }
            #pragma unroll
            for (int j = 0; j < 4; j++) {
                const int cb = wn + j * 8 + gid;
                uint32_t bh[2] = {Bh[(s8 + tig) * BS + cb], Bh[(s8 + tig + 4) * BS + cb]};
                #pragma unroll
                for (int i = 0; i < 4; i++) mma_fp16(acc[i][j], ah[i], bh);
            }
        }
        __syncthreads();
    }

    #pragma unroll
    for (int j = 0; j < 4; j++) {
        const int col = bn + wn + j * 8 + tig * 2;
        const float b0 = bias[col], b1 = bias[col + 1];
        #pragma unroll
        for (int i = 0; i < 4; i++) {
            const int row = bm + wm + i * 16 + gid;
            *(float2*)&C[(size_t)row * N + col]       = make_float2(acc[i][j][0] + b0, acc[i][j][1] + b1);
            *(float2*)&C[(size_t)(row + 8) * N + col] = make_float2(acc[i][j][2] + b0, acc[i][j][3] + b1);
        }
    }
}

// ---------------------------------------------------------------------------
// Merged projection kernel: grid.x in [0,24).
//   [0,16)  : Q-proj (bf16 3-term, planes out)
//   [16,20) : K-proj (bf16 3-term, f32 out)
//   [20,24) : V-proj (fp16, f32 out)
// K/V CTAs fill Q-proj's partial waves instead of separate launches.
// ---------------------------------------------------------------------------
__global__ void __launch_bounds__(256, 2)
proj_all(const float* __restrict__ x,
         const float* __restrict__ Wq, const float* __restrict__ bq,
         const float* __restrict__ Wk, const float* __restrict__ bk,
         const float* __restrict__ Wv, const float* __restrict__ bv,
         uint32_t* __restrict__ qh, uint32_t* __restrict__ ql,
         float* __restrict__ kout, float* __restrict__ vout)
{
    __shared__ uint32_t sm[GEMM_SMEM_U32];
    const int bx = blockIdx.x, by = blockIdx.y;
    const int M = B_ * T_;
    if (bx < 16) {
        gemm_bf16_body<true >(x, Wq, bq, nullptr, qh, ql, M, E_,   E_, bx,      by, sm);
    } else if (bx < 20) {
        gemm_bf16_body<false>(x, Wk, bk, kout, nullptr, nullptr, M, KVD_, E_, bx - 16, by, sm);
    } else {
        gemm_fp16_body(x, Wv, bv, vout, M, KVD_, E_, bx - 20, by, sm);
    }
}

// Standalone fp16 GEMM kernel for the O projection.
__global__ void __launch_bounds__(256, 2)
gemm_fp16_k(const float* __restrict__ A, const float* __restrict__ W,
            const float* __restrict__ bias, float* __restrict__ C,
            int M, int N, int K)
{
    __shared__ uint32_t sm[GEMM_SMEM_U32];
    gemm_fp16_body(A, W, bias, C, M, N, K, blockIdx.x, blockIdx.y, sm);
}

// ---------------- RoPE + operand prep ----------------
// Each thread: one token-pair x one d-pair.  K -> bf16 planes (token-major),
// V -> fp16 token-pair-major (flash consumes it with plain uint4 copies).
__global__ void rope_split(const float* __restrict__ k, const float* __restrict__ v,
                           uint32_t* __restrict__ kh, uint32_t* __restrict__ kl,
                           uint32_t* __restrict__ vt)
{
    int p = blockIdx.x * 256 + threadIdx.x;
    int d2 = p & 63, tq = p >> 6;
    int rr0 = 2 * tq, rr1 = rr0 + 1;
    int t0 = rr0 & (T_ - 1);

    double th = exp2((double)d2 * -0.20762050593046014);
    float thf = (float)th;
    float ang0 = (float)t0 * thf;          // fp32 quantization (matches ref)
    float ang1 = (float)(t0 + 1) * thf;
    float s0, c0, s1, c1;
    sincosf(ang0, &s0, &c0);
    sincosf(ang1, &s1, &c1);

    size_t b0 = (size_t)rr0 * HD_ + 2 * d2;
    size_t b1 = (size_t)rr1 * HD_ + 2 * d2;
    float2 k0 = *(const float2*)(k + b0), k1 = *(const float2*)(k + b1);
    float2 v0 = *(const float2*)(v + b0), v1 = *(const float2*)(v + b1);

    float kx0 = k0.x * c0 - k0.y * s0, ky0 = k0.x * s0 + k0.y * c0;
    float kx1 = k1.x * c1 - k1.y * s1, ky1 = k1.x * s1 + k1.y * c1;
    float vx0 = v0.x * c0 - v0.y * s0, vy0 = v0.x * s0 + v0.y * c0;
    float vx1 = v1.x * c1 - v1.y * s1, vy1 = v1.x * s1 + v1.y * c1;

    float hx0 = bfhi(kx0), hy0 = bfhi(ky0), hx1 = bfhi(kx1), hy1 = bfhi(ky1);
    kh[(size_t)rr0 * 64 + d2] = packbf(hx0, hy0);
    kl[(size_t)rr0 * 64 + d2] = packbf(kx0 - hx0, ky0 - hy0);
    kh[(size_t)rr1 * 64 + d2] = packbf(hx1, hy1);
    kl[(size_t)rr1 * 64 + d2] = packbf(kx1 - hx1, ky1 - hy1);

    // token-pair-major: row tq, cols 2*d2 (d even) and 2*d2+1 (d odd)
    *(uint2*)(vt + (size_t)tq * 128 + 2 * d2) =
        make_uint2(packh(vx0, vx1), packh(vy0, vy1));
}

// ---------------- Flash attention: 128q x 64k, warp-local softmax ----------
constexpr int BST = 68;
constexpr int VST = 132;

__global__ void __launch_bounds__(256, 1)
flash_mma(const uint32_t* __restrict__ Qh, const uint32_t* __restrict__ Ql,
          const uint32_t* __restrict__ Kh, const uint32_t* __restrict__ Kl,
          const uint32_t* __restrict__ Vt, const int* __restrict__ mask,
          float* __restrict__ O)
{
    extern __shared__ uint32_t s4[];
    uint32_t* sQh = s4;                // 128*BST
    uint32_t* sQl = sQh + 128 * BST;
    uint32_t* sKh = sQl + 128 * BST;   // 64*BST
    uint32_t* sKl = sKh + 64 * BST;
    uint32_t* sVs = sKl + 64 * BST;    // 32*VST

    const int tid = threadIdx.x, lane = tid & 31, warp = tid >> 5;
    const int gid = lane >> 2, tig = lane & 3;
    const int q0 = blockIdx.x * 128, h = blockIdx.y, b = blockIdx.z;
    const int kh = h & (NKV_ - 1);
    const int lr = warp * 16 + gid;

    const uint32_t* qhb = Qh + ((size_t)b * NH_  + h ) * ((size_t)T_ * 64) + (size_t)q0 * 64;
    const uint32_t* qlb = Ql + ((size_t)b * NH_  + h ) * ((size_t)T_ * 64) + (size_t)q0 * 64;
    const uint32_t* khb = Kh + ((size_t)b * NKV_ + kh) * ((size_t)T_ * 64);
    const uint32_t* klb = Kl + ((size_t)b * NKV_ + kh) * ((size_t)T_ * 64);
    const uint32_t* vtb = Vt + ((size_t)b * NKV_ + kh) * ((size_t)(T_ / 2) * 128);
    const int*      mb  = mask + (size_t)b * T_ * T_;

    #pragma unroll
    for (int i = 0; i < 8; i++) {
        int idx = i * 256 + tid;
        int r = idx >> 4, c = (idx & 15) * 4;
        *(uint4*)&sQh[r * BST + c] = *(const uint4*)(qhb + r * 64 + c);
        *(uint4*)&sQl[r * BST + c] = *(const uint4*)(qlb + r * 64 + c);
    }

    float m0 = -1e30f, m1 = -1e30f, l0 = 0.f, l1 = 0.f;
    float oacc[16][4];
    #pragma unroll
    for (int j = 0; j < 16; j++)
        #pragma unroll
        for (int c = 0; c < 4; c++) oacc[j][c] = 0.f;

    for (int k0 = 0; k0 < T_; k0 += 64) {
        int2 mq0[8], mq1[8];
        #pragma unroll
        for (int j = 0; j < 8; j++) {
            const int col = k0 + j * 8 + 2 * tig;
            mq0[j] = *(const int2*)(mb + (size_t)(q0 + lr)     * T_ + col);
            mq1[j] = *(const int2*)(mb + (size_t)(q0 + lr + 8) * T_ + col);
        }
        uint4 krh[4], krl[4], vr[4];
        #pragma unroll
        for (int i = 0; i < 4; i++) {
            int idx = i * 256 + tid;
            int r = idx >> 4, c = (idx & 15) * 4;
            krh[i] = *(const uint4*)(khb + (size_t)(k0 + r) * 64 + c);
            krl[i] = *(const uint4*)(klb + (size_t)(k0 + r) * 64 + c);
        }
        #pragma unroll
        for (int i = 0; i < 4; i++) {
            int idx = i * 256 + tid;
            int r = idx >> 5, c = (idx & 31) * 4;
            vr[i] = *(const uint4*)(vtb + (size_t)(k0 / 2 + r) * 128 + c);
        }
        __syncthreads();   // all warps done reading prior K/V tiles
        #pragma unroll
        for (int i = 0; i < 4; i++) {
            int idx = i * 256 + tid;
            int r = idx >> 4, c = (idx & 15) * 4;
            *(uint4*)&sKh[r * BST + c] = krh[i];
            *(uint4*)&sKl[r * BST + c] = krl[i];
        }
        #pragma unroll
        for (int i = 0; i < 4; i++) {
            int idx = i * 256 + tid;
            int r = idx >> 5, c = (idx & 31) * 4;
            *(uint4*)&sVs[r * VST + c] = vr[i];
        }
        __syncthreads();

        // S = Q K^T (bf16 3-term, term-outer)
        float sacc[8][4];
        #pragma unroll
        for (int j = 0; j < 8; j++)
            #pragma unroll
            for (int c = 0; c < 4; c++) sacc[j][c] = 0.f;

        #pragma unroll
        for (int s = 0; s < 8; s++) {
            const int qa = lr * BST + 8 * s;
            uint32_t ah[4] = {sQh[qa + tig], sQh[qa + 8 * BST + tig],
                              sQh[qa + tig + 4], sQh[qa + 8 * BST + tig + 4]};
            uint32_t al[4] = {sQl[qa + tig], sQl[qa + 8 * BST + tig],
                              sQl[qa + tig + 4], sQl[qa + 8 * BST + tig + 4]};
            uint32_t bh[8][2], bl[8][2];
            #pragma unroll
            for (int j = 0; j < 8; j++) {
                const int kb2 = (j * 8 + gid) * BST + 8 * s;
                bh[j][0] = sKh[kb2 + tig]; bh[j][1] = sKh[kb2 + tig + 4];
                bl[j][0] = sKl[kb2 + tig]; bl[j][1] = sKl[kb2 + tig + 4];
            }
            #pragma unroll
            for (int j = 0; j < 8; j++) mma_bf16(sacc[j], ah, bh[j]);
            #pragma unroll
            for (int j = 0; j < 8; j++) mma_bf16(sacc[j], ah, bl[j]);
            #pragma unroll
            for (int j = 0; j < 8; j++) mma_bf16(sacc[j], al, bh[j]);
        }

        float mx0 = -1e30f, mx1 = -1e30f;
        #pragma unroll
        for (int j = 0; j < 8; j++) {
            sacc[j][0] = mq0[j].x ? sacc[j][0] * SCL2_ : MSK2_;
            sacc[j][1] = mq0[j].y ? sacc[j][1] * SCL2_ : MSK2_;
            sacc[j][2] = mq1[j].x ? sacc[j][2] * SCL2_ : MSK2_;
            sacc[j][3] = mq1[j].y ? sacc[j][3] * SCL2_ : MSK2_;
            mx0 = fmaxf(mx0, fmaxf(sacc[j][0], sacc[j][1]));
            mx1 = fmaxf(mx1, fmaxf(sacc[j][2], sacc[j][3]));
        }
        mx0 = fmaxf(mx0, __shfl_xor_sync(0xffffffffu, mx0, 1));
        mx0 = fmaxf(mx0, __shfl_xor_sync(0xffffffffu, mx0, 2));
        mx1 = fmaxf(mx1, __shfl_xor_sync(0xffffffffu, mx1, 1));
        mx1 = fmaxf(mx1, __shfl_xor_sync(0xffffffffu, mx1, 2));

        float mn0 = fmaxf(m0, mx0);
        float mn1 = fmaxf(m1, mx1);
        float a0 = ex2f(m0 - mn0), a1 = ex2f(m1 - mn1);
        m0 = mn0; m1 = mn1;

        float sum0 = 0.f, sum1 = 0.f;
        uint32_t pa[4][4];
        #pragma unroll
        for (int s2 = 0; s2 < 4; s2++) {
            const int j0 = 2 * s2, j1 = 2 * s2 + 1;
            float p00 = ex2f(sacc[j0][0] - mn0), p01 = ex2f(sacc[j0][1] - mn0);
            float p02 = ex2f(sacc[j0][2] - mn1), p03 = ex2f(sacc[j0][3] - mn1);
            float p10 = ex2f(sacc[j1][0] - mn0), p11 = ex2f(sacc[j1][1] - mn0);
            float p12 = ex2f(sacc[j1][2] - mn1), p13 = ex2f(sacc[j1][3] - mn1);
            sum0 += p00 + p01 + p10 + p11;
            sum1 += p02 + p03 + p12 + p13;
            pa[s2][0] = packh(p00, p01);
            pa[s2][1] = packh(p02, p03);
            pa[s2][2] = packh(p10, p11);
            pa[s2][3] = packh(p12, p13);
        }
        sum0 += __shfl_xor_sync(0xffffffffu, sum0, 1);
        sum0 += __shfl_xor_sync(0xffffffffu, sum0, 2);
        sum1 += __shfl_xor_sync(0xffffffffu, sum1, 1);
        sum1 += __shfl_xor_sync(0xffffffffu, sum1, 2);
        l0 = l0 * a0 + sum0;
        l1 = l1 * a1 + sum1;
        #pragma unroll
        for (int j = 0; j < 16; j++) {
            oacc[j][0] *= a0; oacc[j][1] *= a0;
            oacc[j][2] *= a1; oacc[j][3] *= a1;
        }

        // O += P V (fp16, register P)
        #pragma unroll
        for (int s2 = 0; s2 < 4; s2++) {
            #pragma unroll
            for (int j = 0; j < 16; j++) {
                const int vn = j * 8 + gid;
                uint32_t vbf[2] = {sVs[(8 * s2 + tig) * VST + vn],
                                   sVs[(8 * s2 + tig + 4) * VST + vn]};
                mma_fp16(oacc[j], pa[s2], vbf);
            }
        }
    }

    const float inv0 = 1.f / l0;
    const float inv1 = 1.f / l1;
    float* ob = O + ((size_t)b * T_ + q0 + lr) * E_ + h * HD_ + 2 * tig;
    #pragma unroll
    for (int j = 0; j < 16; j++) {
        *(float2*)(ob + j * 8)                  = make_float2(oacc[j][0] * inv0, oacc[j][1] * inv0);
        *(float2*)(ob + 8 * (size_t)E_ + j * 8) = make_float2(oacc[j][2] * inv1, oacc[j][3] * inv1);
    }
}

// ---------------- launcher ----------------
extern "C" void kernel_launch(void* const* d_in, const int* in_sizes, int n_in,
                              void* d_out, int out_size)
{
    const float* x  = (const float*)d_in[0];
    const int*   am = (const int*)  d_in[1];
    const float* Wq = (const float*)d_in[2];
    const float* bq = (const float*)d_in[3];
    const float* Wk = (const float*)d_in[4];
    const float* bk = (const float*)d_in[5];
    const float* Wv = (const float*)d_in[6];
    const float* bv = (const float*)d_in[7];
    const float* Wo = (const float*)d_in[8];
    const float* bo = (const float*)d_in[9];
    float* out = (float*)d_out;

    float *k, *v, *att;
    uint32_t *qh, *ql, *kh, *kl, *vt;
    cudaGetSymbolAddress((void**)&k,   g_k);
    cudaGetSymbolAddress((void**)&v,   g_v);
    cudaGetSymbolAddress((void**)&att, g_att);
    cudaGetSymbolAddress((void**)&qh,  g_qh);
    cudaGetSymbolAddress((void**)&ql,  g_ql);
    cudaGetSymbolAddress((void**)&kh,  g_kh);
    cudaGetSymbolAddress((void**)&kl,  g_kl);
    cudaGetSymbolAddress((void**)&vt,  g_vt);

    const int M = B_ * T_;

    // Merged Q/K/V projections (one launch, shared waves)
    proj_all<<<dim3(24, M / 128), 256>>>(x, Wq, bq, Wk, bk, Wv, bv, qh, ql, k, v);

    // RoPE: K -> bf16 planes, V -> fp16 token-pair-major
    rope_split<<<(B_ * NKV_ * (T_ / 2) * 64) / 256, 256>>>(k, v, kh, kl, vt);

    const int fsmem = (2 * 128 * BST + 2 * 64 * BST + 32 * VST) * 4;  // 121344 B
    cudaFuncSetAttribute(flash_mma, cudaFuncAttributeMaxDynamicSharedMemorySize, fsmem);
    flash_mma<<<dim3(T_ / 128, NH_, B_), 256, fsmem>>>(qh, ql, kh, kl, vt, am, att);

    gemm_fp16_k<<<dim3(E_ / 128, M / 128), 256>>>(att, Wo, bo, out, M, E_, E_);
}